// round 5
// baseline (speedup 1.0000x reference)
#include <cuda_runtime.h>
#include <cuda_bf16.h>
#include <math.h>
#include <stdint.h>

#define BB 2
#define SS 2048
#define DD 768
#define HH 12
#define DHH 64
#define TT 64
#define RR 50
#define FF 3072
#define MROWS (BB*SS)   // 4096

typedef __nv_bfloat16 bf16;

// ---------------- scratch ---------------------------------------------------
__device__ float g_v   [MROWS*DD];
__device__ float g_tmp [MROWS*DD];
__device__ float g_x1  [MROWS*DD];
__device__ float g_x2  [MROWS*DD];
__device__ float g_ck  [TT*DD];
__device__ float g_cv  [TT*DD];

__device__ bf16 g_qhi[MROWS*DD],  g_qlo[MROWS*DD];
__device__ bf16 g_khi[MROWS*DD],  g_klo[MROWS*DD];
__device__ bf16 g_vthi[BB*HH*DHH*SS], g_vtlo[BB*HH*DHH*SS];
__device__ bf16 g_ctxhi[MROWS*DD], g_ctxlo[MROWS*DD];
__device__ bf16 g_x1hi[MROWS*DD], g_x1lo[MROWS*DD];
__device__ bf16 g_x2hi[MROWS*DD], g_x2lo[MROWS*DD];
__device__ bf16 g_hhi[MROWS*DD],  g_hlo[MROWS*DD];
__device__ bf16 g_ihi[MROWS*FF],  g_ilo[MROWS*FF];
__device__ bf16 g_ckhi[TT*DD],    g_cklo[TT*DD];
__device__ bf16 g_cvthi[HH*DHH*TT], g_cvtlo[HH*DHH*TT];

#define DxD (768*768)
#define WSPLIT_TOTAL (6*DxD + 2*768*3072)
__device__ bf16 g_whi[WSPLIT_TOTAL];
__device__ bf16 g_wlo[WSPLIT_TOTAL];

// ================= helpers ==================================================
__device__ __forceinline__ uint32_t smem_u32(const void* p) {
    return (uint32_t)__cvta_generic_to_shared(p);
}
__device__ __forceinline__ uint32_t pack_bf16(float a, float b) {
    __nv_bfloat162 t = __floats2bfloat162_rn(a, b);
    return *(uint32_t*)&t;
}
#define CP16(dst, src) \
    asm volatile("cp.async.cg.shared.global [%0], [%1], 16;\n" :: "r"(dst), "l"(src))
#define LDSM4(r0, r1, r2, r3, addr) \
    asm volatile("ldmatrix.sync.aligned.m8n8.x4.shared.b16 {%0,%1,%2,%3}, [%4];" \
                 : "=r"(r0), "=r"(r1), "=r"(r2), "=r"(r3) : "r"(addr))
#define MMA16816(c, a, b) \
    asm volatile("mma.sync.aligned.m16n8k16.row.col.f32.bf16.bf16.f32 " \
                 "{%0,%1,%2,%3}, {%4,%5,%6,%7}, {%8,%9}, {%0,%1,%2,%3};" \
                 : "+f"(c[0]), "+f"(c[1]), "+f"(c[2]), "+f"(c[3]) \
                 : "r"(a[0]), "r"(a[1]), "r"(a[2]), "r"(a[3]), "r"(b[0]), "r"(b[1]))

// ================= split kernels ===========================================
__global__ __launch_bounds__(256) void asplit_kernel(
    const float* __restrict__ X, bf16* __restrict__ hi,
    bf16* __restrict__ lo, int n4)
{
    int i = blockIdx.x * 256 + threadIdx.x;
    if (i >= n4) return;
    float4 v = ((const float4*)X)[i];
    bf16 h0 = __float2bfloat16(v.x), h1 = __float2bfloat16(v.y);
    bf16 h2 = __float2bfloat16(v.z), h3 = __float2bfloat16(v.w);
    __nv_bfloat162 hh0 = {h0, h1}, hh1 = {h2, h3};
    ((__nv_bfloat162*)hi)[2*i]   = hh0;
    ((__nv_bfloat162*)hi)[2*i+1] = hh1;
    __nv_bfloat162 ll0 = {__float2bfloat16(v.x - __bfloat162float(h0)),
                          __float2bfloat16(v.y - __bfloat162float(h1))};
    __nv_bfloat162 ll1 = {__float2bfloat16(v.z - __bfloat162float(h2)),
                          __float2bfloat16(v.w - __bfloat162float(h3))};
    ((__nv_bfloat162*)lo)[2*i]   = ll0;
    ((__nv_bfloat162*)lo)[2*i+1] = ll1;
}

// weight transpose + split: W [K,N] -> WhiT/WloT [N,K]
__global__ __launch_bounds__(256) void wsplit_kernel(
    const float* __restrict__ W, bf16* __restrict__ hiT,
    bf16* __restrict__ loT, int K, int N)
{
    __shared__ float tile[32][33];
    const int tx = threadIdx.x, ty = threadIdx.y;
    const int n0 = blockIdx.x * 32, k0 = blockIdx.y * 32;
    #pragma unroll
    for (int i = 0; i < 4; i++)
        tile[ty + 8*i][tx] = W[(size_t)(k0 + ty + 8*i) * N + n0 + tx];
    __syncthreads();
    #pragma unroll
    for (int i = 0; i < 4; i++) {
        float v = tile[tx][ty + 8*i];
        bf16 h = __float2bfloat16(v);
        size_t o = (size_t)(n0 + ty + 8*i) * K + k0 + tx;
        hiT[o] = h;
        loT[o] = __float2bfloat16(v - __bfloat162float(h));
    }
}

// V transpose+split per head: V fp32 [rows=S_in][768] -> Vt bf16 [b][h][d][Svt]
// grid: (S_in/32, 2, nBH), block (32,8)
__global__ __launch_bounds__(256) void vtsplit_kernel(
    const float* __restrict__ V, bf16* __restrict__ hi, bf16* __restrict__ lo,
    int S_in, int Svt)
{
    __shared__ float tile[32][33];
    const int tx = threadIdx.x, ty = threadIdx.y;
    const int s0 = blockIdx.x * 32, d0 = blockIdx.y * 32;
    const int b = blockIdx.z / HH, h = blockIdx.z % HH;
    #pragma unroll
    for (int i = 0; i < 4; i++)
        tile[ty + 8*i][tx] = V[(size_t)(b * S_in + s0 + ty + 8*i) * DD + h * DHH + d0 + tx];
    __syncthreads();
    const size_t base = ((size_t)(b * HH + h)) * DHH;
    #pragma unroll
    for (int i = 0; i < 4; i++) {
        float v = tile[tx][ty + 8*i];     // = V[s0+tx][d0+ty+8i]
        bf16 hh = __float2bfloat16(v);
        size_t o = (base + d0 + ty + 8*i) * Svt + s0 + tx;
        hi[o] = hh;
        lo[o] = __float2bfloat16(v - __bfloat162float(hh));
    }
}

// ================= bf16-split tensor-core GEMM =============================
#define GBM 64
#define GBN 128
#define GBK 32
#define STAGE_BYTES 24576
#define OFF_AHI 0
#define OFF_ALO 4096
#define OFF_BHI 8192
#define OFF_BLO 16384

__device__ __forceinline__ uint32_t sw_elem(int row, int k) {
    return (uint32_t)(row * 32 + ((((k >> 3) ^ ((row >> 1) & 3))) << 3) + (k & 7));
}

// MODE: 0 bias, 1 bias+res, 2 bias+gelu.  OSPLIT: 0 fp32 C, 1 bf16 hi/lo out.
template<int MODE, int OSPLIT>
__global__ __launch_bounds__(256, 2) void mma_gemm(
    const bf16* __restrict__ Ahi, const bf16* __restrict__ Alo,
    const bf16* __restrict__ BhiT, const bf16* __restrict__ BloT,
    const float* __restrict__ bias, const float* __restrict__ Rz,
    float* __restrict__ C, bf16* __restrict__ Chi, bf16* __restrict__ Clo,
    int M, int N, int K)
{
    extern __shared__ __align__(16) char smem[];
    const uint32_t sb = smem_u32(smem);

    const int tid = threadIdx.x;
    const int wid = tid >> 5, lane = tid & 31;
    const int warp_m = wid & 1, warp_n = wid >> 1;
    const int m0 = blockIdx.y * GBM, n0 = blockIdx.x * GBN;

    const int lrow_a = tid >> 2;
    const int gld = tid & 3;
    const uint32_t gs_a  = (uint32_t)(gld ^ ((lrow_a >> 1) & 3));
    const int browB = lrow_a;
    const uint32_t gs_b0 = (uint32_t)(gld ^ ((browB >> 1) & 3));
    const uint32_t gs_b1 = (uint32_t)(gld ^ (((browB + 64) >> 1) & 3));

    const int KT = K / GBK;

    auto load_stage = [&](int s, int kt) {
        uint32_t base = sb + s * STAGE_BYTES;
        const size_t kofs = (size_t)kt * GBK + gld * 8;
        {
            uint32_t d = base + OFF_AHI + (uint32_t)(lrow_a * 32 + gs_a * 8) * 2;
            CP16(d, Ahi + (size_t)(m0 + lrow_a) * K + kofs);
            d = base + OFF_ALO + (uint32_t)(lrow_a * 32 + gs_a * 8) * 2;
            CP16(d, Alo + (size_t)(m0 + lrow_a) * K + kofs);
        }
        {
            uint32_t d = base + OFF_BHI + (uint32_t)(browB * 32 + gs_b0 * 8) * 2;
            CP16(d, BhiT + (size_t)(n0 + browB) * K + kofs);
            d = base + OFF_BHI + (uint32_t)((browB + 64) * 32 + gs_b1 * 8) * 2;
            CP16(d, BhiT + (size_t)(n0 + browB + 64) * K + kofs);
            d = base + OFF_BLO + (uint32_t)(browB * 32 + gs_b0 * 8) * 2;
            CP16(d, BloT + (size_t)(n0 + browB) * K + kofs);
            d = base + OFF_BLO + (uint32_t)((browB + 64) * 32 + gs_b1 * 8) * 2;
            CP16(d, BloT + (size_t)(n0 + browB + 64) * K + kofs);
        }
    };

    float acc[2][4][4];
    #pragma unroll
    for (int i = 0; i < 2; i++)
        #pragma unroll
        for (int j = 0; j < 4; j++)
            #pragma unroll
            for (int p = 0; p < 4; p++) acc[i][j][p] = 0.f;

    load_stage(0, 0);
    asm volatile("cp.async.commit_group;\n");

    const int lr16 = lane & 15;
    const int lk8  = (lane >> 4) * 8;

    for (int kt = 0; kt < KT; kt++) {
        if (kt + 1 < KT) load_stage((kt + 1) & 1, kt + 1);
        asm volatile("cp.async.commit_group;\n");
        asm volatile("cp.async.wait_group 1;\n");
        __syncthreads();

        const uint32_t base = sb + (kt & 1) * STAGE_BYTES;
        #pragma unroll
        for (int k16 = 0; k16 < GBK; k16 += 16) {
            uint32_t ah[2][4], al[2][4];
            #pragma unroll
            for (int mt = 0; mt < 2; mt++) {
                int row = warp_m * 32 + mt * 16 + lr16;
                int kk = k16 + lk8;
                uint32_t off = sw_elem(row, kk) * 2;
                LDSM4(ah[mt][0], ah[mt][1], ah[mt][2], ah[mt][3], base + OFF_AHI + off);
                LDSM4(al[mt][0], al[mt][1], al[mt][2], al[mt][3], base + OFF_ALO + off);
            }
            uint32_t bh[4][2], bl[4][2];
            #pragma unroll
            for (int p = 0; p < 2; p++) {
                int row = warp_n * 32 + p * 16 + lr16;
                int kk = k16 + lk8;
                uint32_t off = sw_elem(row, kk) * 2;
                uint32_t q0, q1, q2, q3;
                LDSM4(q0, q1, q2, q3, base + OFF_BHI + off);
                bh[2*p][0] = q0; bh[2*p][1] = q2; bh[2*p+1][0] = q1; bh[2*p+1][1] = q3;
                LDSM4(q0, q1, q2, q3, base + OFF_BLO + off);
                bl[2*p][0] = q0; bl[2*p][1] = q2; bl[2*p+1][0] = q1; bl[2*p+1][1] = q3;
            }
            #pragma unroll
            for (int mt = 0; mt < 2; mt++)
                #pragma unroll
                for (int nt = 0; nt < 4; nt++) {
                    MMA16816(acc[mt][nt], ah[mt], bh[nt]);
                    MMA16816(acc[mt][nt], ah[mt], bl[nt]);
                    MMA16816(acc[mt][nt], al[mt], bh[nt]);
                }
        }
        __syncthreads();
    }

    #pragma unroll
    for (int mt = 0; mt < 2; mt++) {
        #pragma unroll
        for (int nt = 0; nt < 4; nt++) {
            int r0 = m0 + warp_m * 32 + mt * 16 + (lane >> 2);
            int cc = n0 + warp_n * 32 + nt * 8 + 2 * (lane & 3);
            float b0 = bias[cc], b1 = bias[cc + 1];
            #pragma unroll
            for (int h = 0; h < 2; h++) {
                int r = r0 + 8 * h;
                float v0 = acc[mt][nt][2*h]     + b0;
                float v1 = acc[mt][nt][2*h + 1] + b1;
                if (MODE == 1) {
                    const float* rp = Rz + (size_t)r * N + cc;
                    v0 += rp[0]; v1 += rp[1];
                }
                if (MODE == 2) {
                    v0 = 0.5f * v0 * (1.0f + erff(v0 * 0.70710678118654752f));
                    v1 = 0.5f * v1 * (1.0f + erff(v1 * 0.70710678118654752f));
                }
                if (OSPLIT) {
                    bf16 h0 = __float2bfloat16(v0), h1 = __float2bfloat16(v1);
                    __nv_bfloat162 hv = {h0, h1};
                    __nv_bfloat162 lv = {__float2bfloat16(v0 - __bfloat162float(h0)),
                                         __float2bfloat16(v1 - __bfloat162float(h1))};
                    *(__nv_bfloat162*)&Chi[(size_t)r * N + cc] = hv;
                    *(__nv_bfloat162*)&Clo[(size_t)r * N + cc] = lv;
                } else {
                    *(float2*)&C[(size_t)r * N + cc] = make_float2(v0, v1);
                }
            }
        }
    }
}

// ---------------- fp32 SIMT GEMM (tag projections) --------------------------
#define BM 64
#define BN 64
#define BK 16
__global__ __launch_bounds__(256) void gemm_kernel(
    const float* __restrict__ A, const float* __restrict__ W,
    const float* __restrict__ bias, float* __restrict__ C, int M, int N, int K)
{
    __shared__ float As[BK][68];
    __shared__ float Bs[BK][BN];
    const int tid = threadIdx.x;
    const int tx = tid & 15, ty = tid >> 4;
    const int m0 = blockIdx.y * BM, n0 = blockIdx.x * BN;
    float acc[4][4] = {};
    for (int k0 = 0; k0 < K; k0 += BK) {
        {
            const int r = tid >> 4, c = tid & 15;
            #pragma unroll
            for (int i = 0; i < 4; i++)
                As[c][r + 16*i] = A[(size_t)(m0 + r + 16*i) * K + k0 + c];
        }
        {
            const int r = tid >> 6, c = tid & 63;
            #pragma unroll
            for (int i = 0; i < 4; i++)
                Bs[r + 4*i][c] = W[(size_t)(k0 + r + 4*i) * N + n0 + c];
        }
        __syncthreads();
        #pragma unroll
        for (int kk = 0; kk < BK; kk++) {
            float4 a4 = *(const float4*)&As[kk][ty*4];
            float4 b4 = *(const float4*)&Bs[kk][tx*4];
            float a[4] = {a4.x, a4.y, a4.z, a4.w};
            float b[4] = {b4.x, b4.y, b4.z, b4.w};
            #pragma unroll
            for (int i = 0; i < 4; i++)
                #pragma unroll
                for (int j = 0; j < 4; j++)
                    acc[i][j] += a[i] * b[j];
        }
        __syncthreads();
    }
    #pragma unroll
    for (int i = 0; i < 4; i++) {
        const int m = m0 + ty*4 + i;
        #pragma unroll
        for (int j = 0; j < 4; j++) {
            const int n = n0 + tx*4 + j;
            C[(size_t)m * N + n] = acc[i][j] + bias[n];
        }
    }
}

// ================= tensor-core flash attention ==============================
// 64 queries x one (b,h) per block; 4 warps; KV tiles of 64; bf16-split MMAs.
// smem: QHI 0, QLO 8K; stage s at 16K + s*32K: KHI+0, KLO+8K, VHI+16K, VLO+24K
#define AQHI 0
#define AQLO 8192
#define ASTG 16384
#define AKHI 0
#define AKLO 8192
#define AVHI 16384
#define AVLO 24576
#define ATT_SMEM (16384 + 2*32768)

__device__ __forceinline__ uint32_t sw64(int row, int k) {
    return (uint32_t)(row * 64 + ((((k >> 3) ^ (row & 7))) << 3) + (k & 7));
}

__global__ __launch_bounds__(128) void mha_kernel(
    const bf16* __restrict__ Qhi, const bf16* __restrict__ Qlo,
    const bf16* __restrict__ Khi, const bf16* __restrict__ Klo,
    const bf16* __restrict__ Vthi, const bf16* __restrict__ Vtlo,
    bf16* __restrict__ Ohi, bf16* __restrict__ Olo,
    int kv_len, int k_bstr, int vt_bstr, int vt_s, int banded)
{
    extern __shared__ __align__(16) char smem[];
    const uint32_t sb = smem_u32(smem);

    const int tid = threadIdx.x;
    const int wid = tid >> 5, lane = tid & 31;
    const int b = blockIdx.z, h = blockIdx.y;
    const int q0 = blockIdx.x * 64;

    const int lr16 = lane & 15;
    const int lk8  = (lane >> 4) * 8;

    // ---- load Q tile (hi+lo) into smem ----
    {
        const int row = tid >> 1;
        const int kg0 = (tid & 1) * 4;
        const size_t qbase = ((size_t)(b * SS + q0 + row)) * DD + h * DHH;
        #pragma unroll
        for (int i = 0; i < 4; i++) {
            int kg = kg0 + i;
            uint32_t sw = (uint32_t)((kg ^ (row & 7)) << 3);
            CP16(sb + AQHI + (row * 64 + sw) * 2, Qhi + qbase + kg * 8);
            CP16(sb + AQLO + (row * 64 + sw) * 2, Qlo + qbase + kg * 8);
        }
    }
    asm volatile("cp.async.commit_group;\n");

    auto load_kv = [&](int s, int kt) {
        const uint32_t base = sb + ASTG + s * 32768;
        const int k0 = kt * 64;
        const int row = tid >> 1;
        const int kg0 = (tid & 1) * 4;
        const size_t kbase = (size_t)b * k_bstr + (size_t)(k0 + row) * DD + h * DHH;
        const size_t vbase = (size_t)b * vt_bstr + (size_t)(h * DHH + row) * vt_s + k0;
        #pragma unroll
        for (int i = 0; i < 4; i++) {
            int kg = kg0 + i;
            uint32_t sw = (uint32_t)((kg ^ (row & 7)) << 3);
            uint32_t so = (uint32_t)(row * 64 + sw) * 2;
            CP16(base + AKHI + so, Khi + kbase + kg * 8);
            CP16(base + AKLO + so, Klo + kbase + kg * 8);
            CP16(base + AVHI + so, Vthi + vbase + kg * 8);
            CP16(base + AVLO + so, Vtlo + vbase + kg * 8);
        }
    };

    load_kv(0, 0);
    asm volatile("cp.async.commit_group;\n");

    // ---- Q fragments (wait for Q only) ----
    asm volatile("cp.async.wait_group 1;\n");
    __syncthreads();
    uint32_t qh[4][4], ql[4][4];
    #pragma unroll
    for (int ks = 0; ks < 4; ks++) {
        int row = wid * 16 + lr16;
        int kk = ks * 16 + lk8;
        uint32_t off = sw64(row, kk) * 2;
        LDSM4(qh[ks][0], qh[ks][1], qh[ks][2], qh[ks][3], sb + AQHI + off);
        LDSM4(ql[ks][0], ql[ks][1], ql[ks][2], ql[ks][3], sb + AQLO + off);
    }

    float m0r = -1e30f, m1r = -1e30f, l0 = 0.f, l1 = 0.f;
    float oa[8][4];
    #pragma unroll
    for (int nt = 0; nt < 8; nt++)
        #pragma unroll
        for (int e = 0; e < 4; e++) oa[nt][e] = 0.f;

    const int gr = lane >> 2;
    const int gc2 = (lane & 3) * 2;
    const int qrow0 = q0 + wid * 16 + gr;
    const int qrow1 = qrow0 + 8;

    const int ntiles = kv_len / 64;
    for (int kt = 0; kt < ntiles; kt++) {
        if (kt + 1 < ntiles) load_kv((kt + 1) & 1, kt + 1);
        asm volatile("cp.async.commit_group;\n");
        asm volatile("cp.async.wait_group 1;\n");
        __syncthreads();

        const uint32_t base = sb + ASTG + (kt & 1) * 32768;

        // ---- S = Q K^T (3-term split) ----
        float sa[8][4];
        #pragma unroll
        for (int nt = 0; nt < 8; nt++)
            #pragma unroll
            for (int e = 0; e < 4; e++) sa[nt][e] = 0.f;

        #pragma unroll
        for (int p = 0; p < 4; p++) {
            #pragma unroll
            for (int ks = 0; ks < 4; ks++) {
                int row = p * 16 + lr16;
                int kk = ks * 16 + lk8;
                uint32_t off = sw64(row, kk) * 2;
                uint32_t h0, h1, h2, h3, l0r, l1r, l2r, l3r;
                LDSM4(h0, h1, h2, h3, base + AKHI + off);
                LDSM4(l0r, l1r, l2r, l3r, base + AKLO + off);
                uint32_t bh0[2] = {h0, h2}, bh1[2] = {h1, h3};
                uint32_t bl0[2] = {l0r, l2r}, bl1[2] = {l1r, l3r};
                MMA16816(sa[2*p],   qh[ks], bh0);
                MMA16816(sa[2*p],   qh[ks], bl0);
                MMA16816(sa[2*p],   ql[ks], bh0);
                MMA16816(sa[2*p+1], qh[ks], bh1);
                MMA16816(sa[2*p+1], qh[ks], bl1);
                MMA16816(sa[2*p+1], ql[ks], bh1);
            }
        }

        // ---- scale + band mask ----
        #pragma unroll
        for (int nt = 0; nt < 8; nt++) {
            int col = kt * 64 + nt * 8 + gc2;
            #pragma unroll
            for (int e = 0; e < 4; e++) {
                float s = sa[nt][e] * 0.125f;
                if (banded) {
                    int r = (e < 2) ? qrow0 : qrow1;
                    int c = col + (e & 1);
                    int d = r - c;
                    if (d <= RR && d >= -RR) s += 1.0f;
                }
                sa[nt][e] = s;
            }
        }

        // ---- online softmax ----
        float mx0 = -1e30f, mx1 = -1e30f;
        #pragma unroll
        for (int nt = 0; nt < 8; nt++) {
            mx0 = fmaxf(mx0, fmaxf(sa[nt][0], sa[nt][1]));
            mx1 = fmaxf(mx1, fmaxf(sa[nt][2], sa[nt][3]));
        }
        mx0 = fmaxf(mx0, __shfl_xor_sync(0xffffffffu, mx0, 1));
        mx0 = fmaxf(mx0, __shfl_xor_sync(0xffffffffu, mx0, 2));
        mx1 = fmaxf(mx1, __shfl_xor_sync(0xffffffffu, mx1, 1));
        mx1 = fmaxf(mx1, __shfl_xor_sync(0xffffffffu, mx1, 2));

        float nm0 = fmaxf(m0r, mx0), nm1 = fmaxf(m1r, mx1);
        float al0 = __expf(m0r - nm0), al1 = __expf(m1r - nm1);
        m0r = nm0; m1r = nm1;
        l0 *= al0; l1 *= al1;
        #pragma unroll
        for (int nt = 0; nt < 8; nt++) {
            oa[nt][0] *= al0; oa[nt][1] *= al0;
            oa[nt][2] *= al1; oa[nt][3] *= al1;
        }

        float ph_f[8][4], pl_f[8][4];
        #pragma unroll
        for (int nt = 0; nt < 8; nt++) {
            #pragma unroll
            for (int e = 0; e < 4; e++) {
                float p = __expf(sa[nt][e] - ((e < 2) ? nm0 : nm1));
                if (e < 2) l0 += p; else l1 += p;
                float hf = __bfloat162float(__float2bfloat16(p));
                ph_f[nt][e] = hf;
                pl_f[nt][e] = p - hf;
            }
        }

        uint32_t ph[4][4], pl[4][4];
        #pragma unroll
        for (int ks = 0; ks < 4; ks++) {
            int t0 = 2*ks, t1 = 2*ks + 1;
            ph[ks][0] = pack_bf16(ph_f[t0][0], ph_f[t0][1]);
            ph[ks][1] = pack_bf16(ph_f[t0][2], ph_f[t0][3]);
            ph[ks][2] = pack_bf16(ph_f[t1][0], ph_f[t1][1]);
            ph[ks][3] = pack_bf16(ph_f[t1][2], ph_f[t1][3]);
            pl[ks][0] = pack_bf16(pl_f[t0][0], pl_f[t0][1]);
            pl[ks][1] = pack_bf16(pl_f[t0][2], pl_f[t0][3]);
            pl[ks][2] = pack_bf16(pl_f[t1][0], pl_f[t1][1]);
            pl[ks][3] = pack_bf16(pl_f[t1][2], pl_f[t1][3]);
        }

        // ---- O += P V^T (3-term split) ----
        #pragma unroll
        for (int p = 0; p < 4; p++) {
            #pragma unroll
            for (int ks = 0; ks < 4; ks++) {
                int row = p * 16 + lr16;
                int kk = ks * 16 + lk8;
                uint32_t off = sw64(row, kk) * 2;
                uint32_t h0, h1, h2, h3, v0, v1, v2, v3;
                LDSM4(h0, h1, h2, h3, base + AVHI + off);
                LDSM4(v0, v1, v2, v3, base + AVLO + off);
                uint32_t bh0[2] = {h0, h2}, bh1[2] = {h1, h3};
                uint32_t bl0[2] = {v0, v2}, bl1[2] = {v1, v3};
                MMA16816(oa[2*p],   ph[ks], bh0);
                MMA16816(oa[2*p],   pl[ks], bh0);
                MMA16816(oa[2*p],   ph[ks], bl0);
                MMA16816(oa[2*p+1], ph[ks], bh1);
                MMA16816(oa[2*p+1], pl[ks], bh1);
                MMA16816(oa[2*p+1], ph[ks], bl1);
            }
        }
        __syncthreads();
    }

    // ---- epilogue ----
    l0 += __shfl_xor_sync(0xffffffffu, l0, 1);
    l0 += __shfl_xor_sync(0xffffffffu, l0, 2);
    l1 += __shfl_xor_sync(0xffffffffu, l1, 1);
    l1 += __shfl_xor_sync(0xffffffffu, l1, 2);
    const float inv0 = 1.0f / l0, inv1 = 1.0f / l1;

    #pragma unroll
    for (int nt = 0; nt < 8; nt++) {
        int d = nt * 8 + gc2;
        size_t base0 = ((size_t)(b * SS + qrow0)) * DD + h * DHH + d;
        size_t base1 = ((size_t)(b * SS + qrow1)) * DD + h * DHH + d;
        float v0 = oa[nt][0] * inv0, v1 = oa[nt][1] * inv0;
        float v2 = oa[nt][2] * inv1, v3 = oa[nt][3] * inv1;
        bf16 h0 = __float2bfloat16(v0), h1 = __float2bfloat16(v1);
        bf16 h2 = __float2bfloat16(v2), h3 = __float2bfloat16(v3);
        __nv_bfloat162 hv0 = {h0, h1}, hv1 = {h2, h3};
        __nv_bfloat162 lv0 = {__float2bfloat16(v0 - __bfloat162float(h0)),
                              __float2bfloat16(v1 - __bfloat162float(h1))};
        __nv_bfloat162 lv1 = {__float2bfloat16(v2 - __bfloat162float(h2)),
                              __float2bfloat16(v3 - __bfloat162float(h3))};
        *(__nv_bfloat162*)&Ohi[base0] = hv0;
        *(__nv_bfloat162*)&Olo[base0] = lv0;
        *(__nv_bfloat162*)&Ohi[base1] = hv1;
        *(__nv_bfloat162*)&Olo[base1] = lv1;
    }
}

// ---------------- layernorm (optional split output) -------------------------
__global__ __launch_bounds__(256) void ln_kernel(
    const float* __restrict__ X, const float* __restrict__ g,
    const float* __restrict__ bta, float* __restrict__ Y,
    bf16* __restrict__ Yhi, bf16* __restrict__ Ylo)
{
    __shared__ float red[8];
    const int row = blockIdx.x, t = threadIdx.x;
    const float* x = X + (size_t)row * DD;

    float v0 = x[t], v1 = x[t + 256], v2 = x[t + 512];
    float s = v0 + v1 + v2;
    #pragma unroll
    for (int o = 16; o; o >>= 1) s += __shfl_xor_sync(0xffffffffu, s, o);
    if ((t & 31) == 0) red[t >> 5] = s;
    __syncthreads();
    float tot = 0.f;
    #pragma unroll
    for (int i = 0; i < 8; i++) tot += red[i];
    const float mean = tot * (1.0f / 768.0f);

    float d0 = v0 - mean, d1 = v1 - mean, d2 = v2 - mean;
    float s2 = d0*d0 + d1*d1 + d2*d2;
    __syncthreads();
    #pragma unroll
    for (int o = 16; o; o >>= 1) s2 += __shfl_xor_sync(0xffffffffu, s2, o);
    if ((t & 31) == 0) red[t >> 5] = s2;
    __syncthreads();
    float tot2 = 0.f;
    #pragma unroll
    for (int i = 0; i < 8; i++) tot2 += red[i];
    const float rstd = rsqrtf(tot2 * (1.0f / 768.0f) + 1e-12f);

    float* y = Y + (size_t)row * DD;
    #pragma unroll
    for (int c = 0; c < 3; c++) {
        int idx = t + 256 * c;
        float dv = (c == 0) ? d0 : (c == 1) ? d1 : d2;
        float r = dv * rstd * g[idx] + bta[idx];
        y[idx] = r;
        if (Yhi) {
            bf16 hh = __float2bfloat16(r);
            Yhi[(size_t)row * DD + idx] = hh;
            Ylo[(size_t)row * DD + idx] = __float2bfloat16(r - __bfloat162float(hh));
        }
    }
}

// ---------------- launch ----------------------------------------------------
extern "C" void kernel_launch(void* const* d_in, const int* in_sizes, int n_in,
                              void* d_out, int out_size)
{
    const float* hidden  = (const float*)d_in[0];
    const float* tag_emb = (const float*)d_in[1];
    const float* sa_wq = (const float*)d_in[2],  *sa_bq = (const float*)d_in[3];
    const float* sa_wk = (const float*)d_in[4],  *sa_bk = (const float*)d_in[5];
    const float* sa_wv = (const float*)d_in[6],  *sa_bv = (const float*)d_in[7];
    const float* sa_wo = (const float*)d_in[8],  *sa_bo = (const float*)d_in[9];
    const float* sa_lg = (const float*)d_in[10], *sa_lb = (const float*)d_in[11];
    const float* ca_wq = (const float*)d_in[12], *ca_bq = (const float*)d_in[13];
    const float* ca_wk = (const float*)d_in[14], *ca_bk = (const float*)d_in[15];
    const float* ca_wv = (const float*)d_in[16], *ca_bv = (const float*)d_in[17];
    const float* ca_wo = (const float*)d_in[18], *ca_bo = (const float*)d_in[19];
    const float* ca_lg = (const float*)d_in[20], *ca_lb = (const float*)d_in[21];
    const float* ff_w1 = (const float*)d_in[22], *ff_b1 = (const float*)d_in[23];
    const float* ff_w2 = (const float*)d_in[24], *ff_b2 = (const float*)d_in[25];
    const float* ff_lg = (const float*)d_in[26], *ff_lb = (const float*)d_in[27];
    float* out = (float*)d_out;

    float *v, *tmp, *x1, *x2, *ck, *cv;
    bf16 *whi, *wlo, *qhi, *qlo, *khi, *klo, *vthi, *vtlo, *ctxhi, *ctxlo;
    bf16 *x1hi, *x1lo, *x2hi, *x2lo, *hhi, *hlo, *ihi, *ilo;
    bf16 *ckhi, *cklo, *cvthi, *cvtlo;
    cudaGetSymbolAddress((void**)&v,    g_v);
    cudaGetSymbolAddress((void**)&tmp,  g_tmp);
    cudaGetSymbolAddress((void**)&x1,   g_x1);
    cudaGetSymbolAddress((void**)&x2,   g_x2);
    cudaGetSymbolAddress((void**)&ck,   g_ck);
    cudaGetSymbolAddress((void**)&cv,   g_cv);
    cudaGetSymbolAddress((void**)&whi,  g_whi);
    cudaGetSymbolAddress((void**)&wlo,  g_wlo);
    cudaGetSymbolAddress((void**)&qhi,  g_qhi);
    cudaGetSymbolAddress((void**)&qlo,  g_qlo);
    cudaGetSymbolAddress((void**)&khi,  g_khi);
    cudaGetSymbolAddress((void**)&klo,  g_klo);
    cudaGetSymbolAddress((void**)&vthi, g_vthi);
    cudaGetSymbolAddress((void**)&vtlo, g_vtlo);
    cudaGetSymbolAddress((void**)&ctxhi, g_ctxhi);
    cudaGetSymbolAddress((void**)&ctxlo, g_ctxlo);
    cudaGetSymbolAddress((void**)&x1hi, g_x1hi);
    cudaGetSymbolAddress((void**)&x1lo, g_x1lo);
    cudaGetSymbolAddress((void**)&x2hi, g_x2hi);
    cudaGetSymbolAddress((void**)&x2lo, g_x2lo);
    cudaGetSymbolAddress((void**)&hhi,  g_hhi);
    cudaGetSymbolAddress((void**)&hlo,  g_hlo);
    cudaGetSymbolAddress((void**)&ihi,  g_ihi);
    cudaGetSymbolAddress((void**)&ilo,  g_ilo);
    cudaGetSymbolAddress((void**)&ckhi, g_ckhi);
    cudaGetSymbolAddress((void**)&cklo, g_cklo);
    cudaGetSymbolAddress((void**)&cvthi, g_cvthi);
    cudaGetSymbolAddress((void**)&cvtlo, g_cvtlo);

    cudaFuncSetAttribute(mma_gemm<0,1>, cudaFuncAttributeMaxDynamicSharedMemorySize, 2*STAGE_BYTES);
    cudaFuncSetAttribute(mma_gemm<0,0>, cudaFuncAttributeMaxDynamicSharedMemorySize, 2*STAGE_BYTES);
    cudaFuncSetAttribute(mma_gemm<1,0>, cudaFuncAttributeMaxDynamicSharedMemorySize, 2*STAGE_BYTES);
    cudaFuncSetAttribute(mma_gemm<2,1>, cudaFuncAttributeMaxDynamicSharedMemorySize, 2*STAGE_BYTES);
    cudaFuncSetAttribute(mha_kernel,    cudaFuncAttributeMaxDynamicSharedMemorySize, ATT_SMEM);

    const size_t o_sawq = 0,        o_sawk = 1*(size_t)DxD, o_sawv = 2*(size_t)DxD;
    const size_t o_sawo = 3*(size_t)DxD, o_cawq = 4*(size_t)DxD, o_cawo = 5*(size_t)DxD;
    const size_t o_ff1  = 6*(size_t)DxD;
    const size_t o_ff2  = 6*(size_t)DxD + (size_t)768*3072;

    const dim3 wsB(32, 8);
    wsplit_kernel<<<dim3(24,24), wsB>>>(sa_wq, whi+o_sawq, wlo+o_sawq, 768, 768);
    wsplit_kernel<<<dim3(24,24), wsB>>>(sa_wk, whi+o_sawk, wlo+o_sawk, 768, 768);
    wsplit_kernel<<<dim3(24,24), wsB>>>(sa_wv, whi+o_sawv, wlo+o_sawv, 768, 768);
    wsplit_kernel<<<dim3(24,24), wsB>>>(sa_wo, whi+o_sawo, wlo+o_sawo, 768, 768);
    wsplit_kernel<<<dim3(24,24), wsB>>>(ca_wq, whi+o_cawq, wlo+o_cawq, 768, 768);
    wsplit_kernel<<<dim3(24,24), wsB>>>(ca_wo, whi+o_cawo, wlo+o_cawo, 768, 768);
    wsplit_kernel<<<dim3(96,24), wsB>>>(ff_w1, whi+o_ff1,  wlo+o_ff1,  768, 3072);
    wsplit_kernel<<<dim3(24,96), wsB>>>(ff_w2, whi+o_ff2,  wlo+o_ff2,  3072, 768);

    const dim3 thr(256);
    const dim3 gMMA_D (DD / GBN, MROWS / GBM);
    const dim3 gMMA_F1(FF / GBN, MROWS / GBM);
    const dim3 gCK(DD / BN, TT / BM);
    const dim3 attn_grid(SS / 64, HH, BB);
    const int nD4 = MROWS * DD / 4;
    const size_t smb = 2 * STAGE_BYTES;

    // ---- self attention ----
    asplit_kernel<<<(nD4 + 255)/256, 256>>>(hidden, hhi, hlo, nD4);
    mma_gemm<0,1><<<gMMA_D, thr, smb>>>(hhi, hlo, whi+o_sawq, wlo+o_sawq, sa_bq, nullptr, nullptr, qhi, qlo, MROWS, DD, DD);
    mma_gemm<0,1><<<gMMA_D, thr, smb>>>(hhi, hlo, whi+o_sawk, wlo+o_sawk, sa_bk, nullptr, nullptr, khi, klo, MROWS, DD, DD);
    mma_gemm<0,0><<<gMMA_D, thr, smb>>>(hhi, hlo, whi+o_sawv, wlo+o_sawv, sa_bv, nullptr, v, nullptr, nullptr, MROWS, DD, DD);
    vtsplit_kernel<<<dim3(SS/32, 2, BB*HH), wsB>>>(v, vthi, vtlo, SS, SS);
    mha_kernel<<<attn_grid, 128, ATT_SMEM>>>(qhi, qlo, khi, klo, vthi, vtlo, ctxhi, ctxlo,
                                             SS, SS*DD, HH*DHH*SS, SS, 1);
    mma_gemm<1,0><<<gMMA_D, thr, smb>>>(ctxhi, ctxlo, whi+o_sawo, wlo+o_sawo, sa_bo, hidden, tmp, nullptr, nullptr, MROWS, DD, DD);
    ln_kernel<<<MROWS, thr>>>(tmp, sa_lg, sa_lb, x1, x1hi, x1lo);

    // ---- cross attention ----
    mma_gemm<0,1><<<gMMA_D, thr, smb>>>(x1hi, x1lo, whi+o_cawq, wlo+o_cawq, ca_bq, nullptr, nullptr, qhi, qlo, MROWS, DD, DD);
    gemm_kernel<<<gCK, thr>>>(tag_emb, ca_wk, ca_bk, ck, TT, DD, DD);
    gemm_kernel<<<gCK, thr>>>(tag_emb, ca_wv, ca_bv, cv, TT, DD, DD);
    asplit_kernel<<<(TT*DD/4 + 255)/256, 256>>>(ck, ckhi, cklo, TT*DD/4);
    vtsplit_kernel<<<dim3(TT/32, 2, HH), wsB>>>(cv, cvthi, cvtlo, TT, TT);
    mha_kernel<<<attn_grid, 128, ATT_SMEM>>>(qhi, qlo, ckhi, cklo, cvthi, cvtlo, ctxhi, ctxlo,
                                             TT, 0, 0, TT, 0);
    mma_gemm<1,0><<<gMMA_D, thr, smb>>>(ctxhi, ctxlo, whi+o_cawo, wlo+o_cawo, ca_bo, x1, tmp, nullptr, nullptr, MROWS, DD, DD);
    ln_kernel<<<MROWS, thr>>>(tmp, ca_lg, ca_lb, x2, x2hi, x2lo);

    // ---- FFN ----
    mma_gemm<2,1><<<gMMA_F1, thr, smb>>>(x2hi, x2lo, whi+o_ff1, wlo+o_ff1, ff_b1, nullptr, nullptr, ihi, ilo, MROWS, FF, DD);
    mma_gemm<1,0><<<gMMA_D, thr, smb>>>(ihi, ilo, whi+o_ff2, wlo+o_ff2, ff_b2, x2, tmp, nullptr, nullptr, MROWS, DD, FF);
    ln_kernel<<<MROWS, thr>>>(tmp, ff_lg, ff_lb, out, nullptr, nullptr);
}

// round 6
// speedup vs baseline: 1.1498x; 1.1498x over previous
#include <cuda_runtime.h>
#include <cuda_bf16.h>
#include <math.h>
#include <stdint.h>

#define BB 2
#define SS 2048
#define DD 768
#define HH 12
#define DHH 64
#define TT 64
#define RR 50
#define FF 3072
#define MROWS (BB*SS)   // 4096

typedef __nv_bfloat16 bf16;

// ---------------- scratch ---------------------------------------------------
__device__ float g_v   [MROWS*DD];
__device__ float g_tmp [MROWS*DD];
__device__ float g_x1  [MROWS*DD];
__device__ float g_x2  [MROWS*DD];
__device__ float g_ck  [TT*DD];
__device__ float g_cv  [TT*DD];

// packed bf16 operand buffers (tile-swizzled; see pack_* helpers)
__device__ __align__(128) bf16 g_qhi[MROWS*DD];
__device__ __align__(128) bf16 g_qlo[MROWS*DD];
__device__ __align__(128) bf16 g_khi[MROWS*DD];
__device__ __align__(128) bf16 g_klo[MROWS*DD];
__device__ __align__(128) bf16 g_vthi[BB*HH*DHH*SS];
__device__ __align__(128) bf16 g_vtlo[BB*HH*DHH*SS];
__device__ __align__(128) bf16 g_ctxhi[MROWS*DD];
__device__ __align__(128) bf16 g_ctxlo[MROWS*DD];
__device__ __align__(128) bf16 g_x1hi[MROWS*DD];
__device__ __align__(128) bf16 g_x1lo[MROWS*DD];
__device__ __align__(128) bf16 g_x2hi[MROWS*DD];
__device__ __align__(128) bf16 g_x2lo[MROWS*DD];
__device__ __align__(128) bf16 g_hhi[MROWS*DD];
__device__ __align__(128) bf16 g_hlo[MROWS*DD];
__device__ __align__(128) bf16 g_ihi[MROWS*FF];
__device__ __align__(128) bf16 g_ilo[MROWS*FF];
__device__ __align__(128) bf16 g_ckhi[HH*TT*DHH];
__device__ __align__(128) bf16 g_cklo[HH*TT*DHH];
__device__ __align__(128) bf16 g_cvthi[HH*DHH*TT];
__device__ __align__(128) bf16 g_cvtlo[HH*DHH*TT];

#define DxD (768*768)
#define WSPLIT_TOTAL (6*DxD + 2*768*3072)
__device__ __align__(128) bf16 g_whi[WSPLIT_TOTAL];
__device__ __align__(128) bf16 g_wlo[WSPLIT_TOTAL];

// ================= helpers ==================================================
__device__ __forceinline__ uint32_t smem_u32(const void* p) {
    return (uint32_t)__cvta_generic_to_shared(p);
}
__device__ __forceinline__ uint32_t pack_bf16(float a, float b) {
    __nv_bfloat162 t = __floats2bfloat162_rn(a, b);
    return *(uint32_t*)&t;
}
// swizzled element offset inside a [rows][32] bf16 tile (GEMM A/B blocks)
__device__ __forceinline__ uint32_t sw_elem(int row, int k) {
    return (uint32_t)(row * 32 + ((((k >> 3) ^ ((row >> 1) & 3))) << 3) + (k & 7));
}
// swizzled element offset inside a [64][64] bf16 tile (attention blocks)
__device__ __forceinline__ uint32_t sw64(int row, int k) {
    return (uint32_t)(row * 64 + ((((k >> 3) ^ (row & 7))) << 3) + (k & 7));
}

#define LDSM4(r0, r1, r2, r3, addr) \
    asm volatile("ldmatrix.sync.aligned.m8n8.x4.shared.b16 {%0,%1,%2,%3}, [%4];" \
                 : "=r"(r0), "=r"(r1), "=r"(r2), "=r"(r3) : "r"(addr))
#define MMA16816(c, a, b) \
    asm volatile("mma.sync.aligned.m16n8k16.row.col.f32.bf16.bf16.f32 " \
                 "{%0,%1,%2,%3}, {%4,%5,%6,%7}, {%8,%9}, {%0,%1,%2,%3};" \
                 : "+f"(c[0]), "+f"(c[1]), "+f"(c[2]), "+f"(c[3]) \
                 : "r"(a[0]), "r"(a[1]), "r"(a[2]), "r"(a[3]), "r"(b[0]), "r"(b[1]))

__device__ __forceinline__ void mbar_init(uint32_t a, uint32_t cnt) {
    asm volatile("mbarrier.init.shared.b64 [%0], %1;" :: "r"(a), "r"(cnt) : "memory");
}
__device__ __forceinline__ void mbar_expect(uint32_t a, uint32_t bytes) {
    asm volatile("mbarrier.arrive.expect_tx.shared.b64 _, [%0], %1;"
                 :: "r"(a), "r"(bytes) : "memory");
}
__device__ __forceinline__ void mbar_wait(uint32_t a, uint32_t parity) {
    asm volatile(
        "{\n\t.reg .pred P;\n\t"
        "W%=:\n\t"
        "mbarrier.try_wait.parity.acquire.cta.shared::cta.b64 P, [%0], %1, 0x989680;\n\t"
        "@!P bra W%=;\n\t}"
        :: "r"(a), "r"(parity) : "memory");
}
__device__ __forceinline__ void bulk_g2s(uint32_t dst, const void* src,
                                         uint32_t bytes, uint32_t mbar) {
    asm volatile(
        "cp.async.bulk.shared::cta.global.mbarrier::complete_tx::bytes [%0], [%1], %2, [%3];"
        :: "r"(dst), "l"(src), "r"(bytes), "r"(mbar) : "memory");
}

// ================= pack/split kernels ======================================
// hidden -> GEMM-A packed (64x32 blocks, K=768)
__global__ __launch_bounds__(256) void asplit_kernel(
    const float* __restrict__ X, bf16* __restrict__ hi,
    bf16* __restrict__ lo, int n4)
{
    int i = blockIdx.x * 256 + threadIdx.x;
    if (i >= n4) return;
    float4 v = ((const float4*)X)[i];
    int r = (i * 4) / 768, c = (i * 4) % 768;
    size_t off = ((size_t)(r >> 6) * 24 + (c >> 5)) * 2048 + sw_elem(r & 63, c & 31);
    bf16 h0 = __float2bfloat16(v.x), h1 = __float2bfloat16(v.y);
    bf16 h2 = __float2bfloat16(v.z), h3 = __float2bfloat16(v.w);
    *(__nv_bfloat162*)&hi[off]     = {h0, h1};
    *(__nv_bfloat162*)&hi[off + 2] = {h2, h3};
    *(__nv_bfloat162*)&lo[off]     = {__float2bfloat16(v.x - __bfloat162float(h0)),
                                      __float2bfloat16(v.y - __bfloat162float(h1))};
    *(__nv_bfloat162*)&lo[off + 2] = {__float2bfloat16(v.z - __bfloat162float(h2)),
                                      __float2bfloat16(v.w - __bfloat162float(h3))};
}

// weights W [K,N] -> GEMM-B packed (128x32 blocks over [N][K])
__global__ __launch_bounds__(256) void wsplit_kernel(
    const float* __restrict__ W, bf16* __restrict__ hiT,
    bf16* __restrict__ loT, int K, int N)
{
    __shared__ float tile[32][33];
    const int tx = threadIdx.x, ty = threadIdx.y;
    const int n0 = blockIdx.x * 32, k0 = blockIdx.y * 32;
    #pragma unroll
    for (int i = 0; i < 4; i++)
        tile[ty + 8*i][tx] = W[(size_t)(k0 + ty + 8*i) * N + n0 + tx];
    __syncthreads();
    #pragma unroll
    for (int i = 0; i < 4; i++) {
        float v = tile[tx][ty + 8*i];
        int n = n0 + ty + 8*i, k = k0 + tx;
        bf16 h = __float2bfloat16(v);
        size_t o = ((size_t)(n >> 7) * (K >> 5) + (k >> 5)) * 4096 + sw_elem(n & 127, k & 31);
        hiT[o] = h;
        loT[o] = __float2bfloat16(v - __bfloat162float(h));
    }
}

// self-V fp32 [b*S][768] -> attention V packed (64x64 blocks, rows=d, cols=s)
__global__ __launch_bounds__(256) void vtsplit_kernel(
    const float* __restrict__ V, bf16* __restrict__ hi, bf16* __restrict__ lo)
{
    __shared__ float tile[32][33];
    const int tx = threadIdx.x, ty = threadIdx.y;
    const int s0 = blockIdx.x * 32, d0 = blockIdx.y * 32;
    const int b = blockIdx.z / HH, h = blockIdx.z % HH;
    #pragma unroll
    for (int i = 0; i < 4; i++)
        tile[ty + 8*i][tx] = V[(size_t)(b * SS + s0 + ty + 8*i) * DD + h * DHH + d0 + tx];
    __syncthreads();
    #pragma unroll
    for (int i = 0; i < 4; i++) {
        float v = tile[tx][ty + 8*i];          // = V[s0+tx][d0+ty+8i]
        int s = s0 + tx, d = d0 + ty + 8*i;
        bf16 hh = __float2bfloat16(v);
        size_t o = ((size_t)(b * HH + h) * 32 + (s >> 6)) * 4096 + sw64(d, s & 63);
        hi[o] = hh;
        lo[o] = __float2bfloat16(v - __bfloat162float(hh));
    }
}

// cross K/V fp32 [64][768] -> attention packed per head (1 block each)
__global__ __launch_bounds__(256) void cpack_kernel(
    const float* __restrict__ ck, const float* __restrict__ cv,
    bf16* __restrict__ khi, bf16* __restrict__ klo,
    bf16* __restrict__ vhi, bf16* __restrict__ vlo)
{
    const int h = blockIdx.x;
    for (int idx = threadIdx.x; idx < 4096; idx += 256) {
        int s = idx >> 6, d = idx & 63;
        float kv = ck[(size_t)s * DD + h * DHH + d];
        bf16 kh = __float2bfloat16(kv);
        size_t ko = (size_t)h * 4096 + sw64(s, d);
        khi[ko] = kh;
        klo[ko] = __float2bfloat16(kv - __bfloat162float(kh));
        float vv = cv[(size_t)s * DD + h * DHH + d];
        bf16 vh = __float2bfloat16(vv);
        size_t vo = (size_t)h * 4096 + sw64(d, s);
        vhi[vo] = vh;
        vlo[vo] = __float2bfloat16(vv - __bfloat162float(vh));
    }
}

// ================= bf16-split tensor-core GEMM (bulk-copy loads) ===========
#define GBM 64
#define GBN 128
#define STAGE_BYTES 24576
#define OFF_AHI 0
#define OFF_ALO 4096
#define OFF_BHI 8192
#define OFF_BLO 16384
#define GEMM_SMEM (1024 + 2*STAGE_BYTES)

// MODE: 0 bias, 1 bias+res, 2 bias+gelu
// OSPLIT: 0 fp32 C | 1 attention-QK packed | 2 GEMM-A packed
template<int MODE, int OSPLIT>
__global__ __launch_bounds__(256, 2) void mma_gemm(
    const bf16* __restrict__ Apk_hi, const bf16* __restrict__ Apk_lo,
    const bf16* __restrict__ Bpk_hi, const bf16* __restrict__ Bpk_lo,
    const float* __restrict__ bias, const float* __restrict__ Rz,
    float* __restrict__ C, bf16* __restrict__ Chi, bf16* __restrict__ Clo,
    int N, int K)
{
    extern __shared__ __align__(16) char smem[];
    const uint32_t sb = smem_u32(smem);
    const uint32_t mb0 = sb, mb1 = sb + 8;
    const uint32_t data = sb + 1024;

    const int tid = threadIdx.x;
    const int wid = tid >> 5, lane = tid & 31;
    const int warp_m = wid & 1, warp_n = wid >> 1;
    const int m0 = blockIdx.y * GBM, n0 = blockIdx.x * GBN;
    const int KT = K >> 5;

    const bf16* Ahi_t = Apk_hi + (size_t)(m0 >> 6) * KT * 2048;
    const bf16* Alo_t = Apk_lo + (size_t)(m0 >> 6) * KT * 2048;
    const bf16* Bhi_t = Bpk_hi + (size_t)(n0 >> 7) * KT * 4096;
    const bf16* Blo_t = Bpk_lo + (size_t)(n0 >> 7) * KT * 4096;

    if (tid == 0) { mbar_init(mb0, 1); mbar_init(mb1, 1); }
    __syncthreads();

    auto issue = [&](int s, int kt) {
        const uint32_t mb = s ? mb1 : mb0;
        mbar_expect(mb, (uint32_t)STAGE_BYTES);
        const uint32_t b = data + s * STAGE_BYTES;
        bulk_g2s(b + OFF_AHI, Ahi_t + (size_t)kt * 2048, 4096, mb);
        bulk_g2s(b + OFF_ALO, Alo_t + (size_t)kt * 2048, 4096, mb);
        bulk_g2s(b + OFF_BHI, Bhi_t + (size_t)kt * 4096, 8192, mb);
        bulk_g2s(b + OFF_BLO, Blo_t + (size_t)kt * 4096, 8192, mb);
    };
    if (tid == 0) issue(0, 0);

    float acc[2][4][4];
    #pragma unroll
    for (int i = 0; i < 2; i++)
        #pragma unroll
        for (int j = 0; j < 4; j++)
            #pragma unroll
            for (int p = 0; p < 4; p++) acc[i][j][p] = 0.f;

    const int lr16 = lane & 15;
    const int lk8  = (lane >> 4) * 8;
    int ph0 = 0, ph1 = 0;

    for (int kt = 0; kt < KT; kt++) {
        const int s = kt & 1;
        if (kt + 1 < KT && tid == 0) issue(s ^ 1, kt + 1);
        if (s == 0) { mbar_wait(mb0, ph0); ph0 ^= 1; }
        else        { mbar_wait(mb1, ph1); ph1 ^= 1; }

        const uint32_t base = data + s * STAGE_BYTES;
        #pragma unroll
        for (int k16 = 0; k16 < 32; k16 += 16) {
            uint32_t ah[2][4], al[2][4];
            #pragma unroll
            for (int mt = 0; mt < 2; mt++) {
                int row = warp_m * 32 + mt * 16 + lr16;
                uint32_t off = sw_elem(row, k16 + lk8) * 2;
                LDSM4(ah[mt][0], ah[mt][1], ah[mt][2], ah[mt][3], base + OFF_AHI + off);
                LDSM4(al[mt][0], al[mt][1], al[mt][2], al[mt][3], base + OFF_ALO + off);
            }
            uint32_t bh[4][2], bl[4][2];
            #pragma unroll
            for (int p = 0; p < 2; p++) {
                int row = warp_n * 32 + p * 16 + lr16;
                uint32_t off = sw_elem(row, k16 + lk8) * 2;
                uint32_t q0, q1, q2, q3;
                LDSM4(q0, q1, q2, q3, base + OFF_BHI + off);
                bh[2*p][0] = q0; bh[2*p][1] = q2; bh[2*p+1][0] = q1; bh[2*p+1][1] = q3;
                LDSM4(q0, q1, q2, q3, base + OFF_BLO + off);
                bl[2*p][0] = q0; bl[2*p][1] = q2; bl[2*p+1][0] = q1; bl[2*p+1][1] = q3;
            }
            #pragma unroll
            for (int mt = 0; mt < 2; mt++)
                #pragma unroll
                for (int nt = 0; nt < 4; nt++) {
                    MMA16816(acc[mt][nt], ah[mt], bh[nt]);
                    MMA16816(acc[mt][nt], ah[mt], bl[nt]);
                    MMA16816(acc[mt][nt], al[mt], bh[nt]);
                }
        }
        __syncthreads();
    }

    #pragma unroll
    for (int mt = 0; mt < 2; mt++) {
        #pragma unroll
        for (int nt = 0; nt < 4; nt++) {
            int r0 = m0 + warp_m * 32 + mt * 16 + (lane >> 2);
            int cc = n0 + warp_n * 32 + nt * 8 + 2 * (lane & 3);
            float b0 = bias[cc], b1 = bias[cc + 1];
            #pragma unroll
            for (int hh = 0; hh < 2; hh++) {
                int r = r0 + 8 * hh;
                float v0 = acc[mt][nt][2*hh]     + b0;
                float v1 = acc[mt][nt][2*hh + 1] + b1;
                if (MODE == 1) {
                    const float* rp = Rz + (size_t)r * N + cc;
                    v0 += rp[0]; v1 += rp[1];
                }
                if (MODE == 2) {
                    v0 = 0.5f * v0 * (1.0f + erff(v0 * 0.70710678118654752f));
                    v1 = 0.5f * v1 * (1.0f + erff(v1 * 0.70710678118654752f));
                }
                if (OSPLIT == 0) {
                    *(float2*)&C[(size_t)r * N + cc] = make_float2(v0, v1);
                } else {
                    bf16 h0 = __float2bfloat16(v0), h1 = __float2bfloat16(v1);
                    __nv_bfloat162 hv = {h0, h1};
                    __nv_bfloat162 lv = {__float2bfloat16(v0 - __bfloat162float(h0)),
                                         __float2bfloat16(v1 - __bfloat162float(h1))};
                    size_t off;
                    if (OSPLIT == 1) {
                        int bb = r >> 11, s2 = r & 2047;
                        int h2 = cc >> 6, d = cc & 63;
                        off = ((size_t)(bb * HH + h2) * 32 + (s2 >> 6)) * 4096
                              + sw64(s2 & 63, d);
                    } else {
                        off = ((size_t)(r >> 6) * (N >> 5) + (cc >> 5)) * 2048
                              + sw_elem(r & 63, cc & 31);
                    }
                    *(__nv_bfloat162*)&Chi[off] = hv;
                    *(__nv_bfloat162*)&Clo[off] = lv;
                }
            }
        }
    }
}

// ---------------- fp32 SIMT GEMM (tag projections) --------------------------
#define BM 64
#define BN 64
#define BK 16
__global__ __launch_bounds__(256) void gemm_kernel(
    const float* __restrict__ A, const float* __restrict__ W,
    const float* __restrict__ bias, float* __restrict__ C, int M, int N, int K)
{
    __shared__ float As[BK][68];
    __shared__ float Bs[BK][BN];
    const int tid = threadIdx.x;
    const int tx = tid & 15, ty = tid >> 4;
    const int m0 = blockIdx.y * BM, n0 = blockIdx.x * BN;
    float acc[4][4] = {};
    for (int k0 = 0; k0 < K; k0 += BK) {
        {
            const int r = tid >> 4, c = tid & 15;
            #pragma unroll
            for (int i = 0; i < 4; i++)
                As[c][r + 16*i] = A[(size_t)(m0 + r + 16*i) * K + k0 + c];
        }
        {
            const int r = tid >> 6, c = tid & 63;
            #pragma unroll
            for (int i = 0; i < 4; i++)
                Bs[r + 4*i][c] = W[(size_t)(k0 + r + 4*i) * N + n0 + c];
        }
        __syncthreads();
        #pragma unroll
        for (int kk = 0; kk < BK; kk++) {
            float4 a4 = *(const float4*)&As[kk][ty*4];
            float4 b4 = *(const float4*)&Bs[kk][tx*4];
            float a[4] = {a4.x, a4.y, a4.z, a4.w};
            float b[4] = {b4.x, b4.y, b4.z, b4.w};
            #pragma unroll
            for (int i = 0; i < 4; i++)
                #pragma unroll
                for (int j = 0; j < 4; j++)
                    acc[i][j] += a[i] * b[j];
        }
        __syncthreads();
    }
    #pragma unroll
    for (int i = 0; i < 4; i++) {
        const int m = m0 + ty*4 + i;
        #pragma unroll
        for (int j = 0; j < 4; j++) {
            const int n = n0 + tx*4 + j;
            C[(size_t)m * N + n] = acc[i][j] + bias[n];
        }
    }
}

// ================= tensor-core flash attention (bulk-copy loads) ============
#define AQHI 0
#define AQLO 8192
#define ASTG 16384
#define AKHI 0
#define AKLO 8192
#define AVHI 16384
#define AVLO 24576
#define ATT_SMEM (1024 + 16384 + 2*32768)

__global__ __launch_bounds__(128) void mha_kernel(
    const bf16* __restrict__ Qhi, const bf16* __restrict__ Qlo,
    const bf16* __restrict__ Khi, const bf16* __restrict__ Klo,
    const bf16* __restrict__ Vhi, const bf16* __restrict__ Vlo,
    bf16* __restrict__ Ohi, bf16* __restrict__ Olo,
    int ntiles, int kb, int kh, int banded)
{
    extern __shared__ __align__(16) char smem[];
    const uint32_t sb = smem_u32(smem);
    const uint32_t mbq = sb, mb0 = sb + 8, mb1 = sb + 16;
    const uint32_t data = sb + 1024;

    const int tid = threadIdx.x;
    const int wid = tid >> 5, lane = tid & 31;
    const int b = blockIdx.z, h = blockIdx.y;
    const int q0 = blockIdx.x * 64;

    const int lr16 = lane & 15;
    const int lk8  = (lane >> 4) * 8;

    if (tid == 0) { mbar_init(mbq, 1); mbar_init(mb0, 1); mbar_init(mb1, 1); }
    __syncthreads();

    const size_t qblk  = (size_t)(b * HH + h) * 32 + (q0 >> 6);
    const size_t kvbase = (size_t)b * kb + (size_t)h * kh;

    auto issue_kv = [&](int s, int kt) {
        const uint32_t mb = s ? mb1 : mb0;
        mbar_expect(mb, 32768u);
        const uint32_t st = data + ASTG + s * 32768;
        bulk_g2s(st + AKHI, Khi + (kvbase + kt) * 4096, 8192, mb);
        bulk_g2s(st + AKLO, Klo + (kvbase + kt) * 4096, 8192, mb);
        bulk_g2s(st + AVHI, Vhi + (kvbase + kt) * 4096, 8192, mb);
        bulk_g2s(st + AVLO, Vlo + (kvbase + kt) * 4096, 8192, mb);
    };

    if (tid == 0) {
        mbar_expect(mbq, 16384u);
        bulk_g2s(data + AQHI, Qhi + qblk * 4096, 8192, mbq);
        bulk_g2s(data + AQLO, Qlo + qblk * 4096, 8192, mbq);
        issue_kv(0, 0);
    }

    mbar_wait(mbq, 0);
    uint32_t qh[4][4], ql[4][4];
    #pragma unroll
    for (int ks = 0; ks < 4; ks++) {
        int row = wid * 16 + lr16;
        uint32_t off = sw64(row, ks * 16 + lk8) * 2;
        LDSM4(qh[ks][0], qh[ks][1], qh[ks][2], qh[ks][3], data + AQHI + off);
        LDSM4(ql[ks][0], ql[ks][1], ql[ks][2], ql[ks][3], data + AQLO + off);
    }

    float m0r = -1e30f, m1r = -1e30f, l0 = 0.f, l1 = 0.f;
    float oa[8][4];
    #pragma unroll
    for (int nt = 0; nt < 8; nt++)
        #pragma unroll
        for (int e = 0; e < 4; e++) oa[nt][e] = 0.f;

    const int gr = lane >> 2;
    const int gc2 = (lane & 3) * 2;
    const int qrow0 = q0 + wid * 16 + gr;
    const int qrow1 = qrow0 + 8;

    int ph0 = 0, ph1 = 0;
    for (int kt = 0; kt < ntiles; kt++) {
        const int s = kt & 1;
        if (kt + 1 < ntiles && tid == 0) issue_kv(s ^ 1, kt + 1);
        if (s == 0) { mbar_wait(mb0, ph0); ph0 ^= 1; }
        else        { mbar_wait(mb1, ph1); ph1 ^= 1; }

        const uint32_t base = data + ASTG + s * 32768;

        float sa[8][4];
        #pragma unroll
        for (int nt = 0; nt < 8; nt++)
            #pragma unroll
            for (int e = 0; e < 4; e++) sa[nt][e] = 0.f;

        #pragma unroll
        for (int p = 0; p < 4; p++) {
            #pragma unroll
            for (int ks = 0; ks < 4; ks++) {
                int row = p * 16 + lr16;
                uint32_t off = sw64(row, ks * 16 + lk8) * 2;
                uint32_t h0, h1, h2, h3, l0r, l1r, l2r, l3r;
                LDSM4(h0, h1, h2, h3, base + AKHI + off);
                LDSM4(l0r, l1r, l2r, l3r, base + AKLO + off);
                uint32_t bh0[2] = {h0, h2}, bh1[2] = {h1, h3};
                uint32_t bl0[2] = {l0r, l2r}, bl1[2] = {l1r, l3r};
                MMA16816(sa[2*p],   qh[ks], bh0);
                MMA16816(sa[2*p],   qh[ks], bl0);
                MMA16816(sa[2*p],   ql[ks], bh0);
                MMA16816(sa[2*p+1], qh[ks], bh1);
                MMA16816(sa[2*p+1], qh[ks], bl1);
                MMA16816(sa[2*p+1], ql[ks], bh1);
            }
        }

        #pragma unroll
        for (int nt = 0; nt < 8; nt++) {
            int col = kt * 64 + nt * 8 + gc2;
            #pragma unroll
            for (int e = 0; e < 4; e++) {
                float s2 = sa[nt][e] * 0.125f;
                if (banded) {
                    int r = (e < 2) ? qrow0 : qrow1;
                    int c = col + (e & 1);
                    int d = r - c;
                    if (d <= RR && d >= -RR) s2 += 1.0f;
                }
                sa[nt][e] = s2;
            }
        }

        float mx0 = -1e30f, mx1 = -1e30f;
        #pragma unroll
        for (int nt = 0; nt < 8; nt++) {
            mx0 = fmaxf(mx0, fmaxf(sa[nt][0], sa[nt][1]));
            mx1 = fmaxf(mx1, fmaxf(sa[nt][2], sa[nt][3]));
        }
        mx0 = fmaxf(mx0, __shfl_xor_sync(0xffffffffu, mx0, 1));
        mx0 = fmaxf(mx0, __shfl_xor_sync(0xffffffffu, mx0, 2));
        mx1 = fmaxf(mx1, __shfl_xor_sync(0xffffffffu, mx1, 1));
        mx1 = fmaxf(mx1, __shfl_xor_sync(0xffffffffu, mx1, 2));

        float nm0 = fmaxf(m0r, mx0), nm1 = fmaxf(m1r, mx1);
        float al0 = __expf(m0r - nm0), al1 = __expf(m1r - nm1);
        m0r = nm0; m1r = nm1;
        l0 *= al0; l1 *= al1;
        #pragma unroll
        for (int nt = 0; nt < 8; nt++) {
            oa[nt][0] *= al0; oa[nt][1] *= al0;
            oa[nt][2] *= al1; oa[nt][3] *= al1;
        }

        float ph_f[8][4], pl_f[8][4];
        #pragma unroll
        for (int nt = 0; nt < 8; nt++) {
            #pragma unroll
            for (int e = 0; e < 4; e++) {
                float p = __expf(sa[nt][e] - ((e < 2) ? nm0 : nm1));
                if (e < 2) l0 += p; else l1 += p;
                float hf = __bfloat162float(__float2bfloat16(p));
                ph_f[nt][e] = hf;
                pl_f[nt][e] = p - hf;
            }
        }

        uint32_t ph[4][4], pl[4][4];
        #pragma unroll
        for (int ks = 0; ks < 4; ks++) {
            int t0 = 2*ks, t1 = 2*ks + 1;
            ph[ks][0] = pack_bf16(ph_f[t0][0], ph_f[t0][1]);
            ph[ks][1] = pack_bf16(ph_f[t0][2], ph_f[t0][3]);
            ph[ks][2] = pack_bf16(ph_f[t1][0], ph_f[t1][1]);
            ph[ks][3] = pack_bf16(ph_f[t1][2], ph_f[t1][3]);
            pl[ks][0] = pack_bf16(pl_f[t0][0], pl_f[t0][1]);
            pl[ks][1] = pack_bf16(pl_f[t0][2], pl_f[t0][3]);
            pl[ks][2] = pack_bf16(pl_f[t1][0], pl_f[t1][1]);
            pl[ks][3] = pack_bf16(pl_f[t1][2], pl_f[t1][3]);
        }

        #pragma unroll
        for (int p = 0; p < 4; p++) {
            #pragma unroll
            for (int ks = 0; ks < 4; ks++) {
                int row = p * 16 + lr16;
                uint32_t off = sw64(row, ks * 16 + lk8) * 2;
                uint32_t h0, h1, h2, h3, v0, v1, v2, v3;
                LDSM4(h0, h1, h2, h3, base + AVHI + off);
                LDSM4(v0, v1, v2, v3, base + AVLO + off);
                uint32_t bh0[2] = {h0, h2}, bh1[2] = {h1, h3};
                uint32_t bl0[2] = {v0, v2}, bl1[2] = {v1, v3};
                MMA16816(oa[2*p],   ph[ks], bh0);
                MMA16816(oa[2*p],   pl[ks], bh0);
                MMA16816(oa[2*p],   ph[ks], bl0);
                MMA16816(oa[2*p+1], ph[ks], bh1);
                MMA16816(oa[2*p+1], pl[ks], bh1);
                MMA16816(oa[2*p+1], ph[ks], bl1);
            }
        }
        __syncthreads();
    }

    l0 += __shfl_xor_sync(0xffffffffu, l0, 1);
    l0 += __shfl_xor_sync(0xffffffffu, l0, 2);
    l1 += __shfl_xor_sync(0xffffffffu, l1, 1);
    l1 += __shfl_xor_sync(0xffffffffu, l1, 2);
    const float inv0 = 1.0f / l0, inv1 = 1.0f / l1;

    // write ctx in GEMM-A packed layout (N=768 -> 24 col-blocks)
    #pragma unroll
    for (int nt = 0; nt < 8; nt++) {
        int d = nt * 8 + gc2;
        int col = h * DHH + d;
        int R0 = b * SS + qrow0, R1 = b * SS + qrow1;
        size_t off0 = ((size_t)(R0 >> 6) * 24 + (col >> 5)) * 2048 + sw_elem(R0 & 63, col & 31);
        size_t off1 = ((size_t)(R1 >> 6) * 24 + (col >> 5)) * 2048 + sw_elem(R1 & 63, col & 31);
        float v0 = oa[nt][0] * inv0, v1 = oa[nt][1] * inv0;
        float v2 = oa[nt][2] * inv1, v3 = oa[nt][3] * inv1;
        bf16 h0 = __float2bfloat16(v0), h1 = __float2bfloat16(v1);
        bf16 h2 = __float2bfloat16(v2), h3 = __float2bfloat16(v3);
        *(__nv_bfloat162*)&Ohi[off0] = {h0, h1};
        *(__nv_bfloat162*)&Olo[off0] = {__float2bfloat16(v0 - __bfloat162float(h0)),
                                        __float2bfloat16(v1 - __bfloat162float(h1))};
        *(__nv_bfloat162*)&Ohi[off1] = {h2, h3};
        *(__nv_bfloat162*)&Olo[off1] = {__float2bfloat16(v2 - __bfloat162float(h2)),
                                        __float2bfloat16(v3 - __bfloat162float(h3))};
    }
}

// ---------------- layernorm (fp32 + optional packed split out) --------------
__global__ __launch_bounds__(256) void ln_kernel(
    const float* __restrict__ X, const float* __restrict__ g,
    const float* __restrict__ bta, float* __restrict__ Y,
    bf16* __restrict__ Yhi, bf16* __restrict__ Ylo)
{
    __shared__ float red[8];
    const int row = blockIdx.x, t = threadIdx.x;
    const float* x = X + (size_t)row * DD;

    float v0 = x[t], v1 = x[t + 256], v2 = x[t + 512];
    float s = v0 + v1 + v2;
    #pragma unroll
    for (int o = 16; o; o >>= 1) s += __shfl_xor_sync(0xffffffffu, s, o);
    if ((t & 31) == 0) red[t >> 5] = s;
    __syncthreads();
    float tot = 0.f;
    #pragma unroll
    for (int i = 0; i < 8; i++) tot += red[i];
    const float mean = tot * (1.0f / 768.0f);

    float d0 = v0 - mean, d1 = v1 - mean, d2 = v2 - mean;
    float s2 = d0*d0 + d1*d1 + d2*d2;
    __syncthreads();
    #pragma unroll
    for (int o = 16; o; o >>= 1) s2 += __shfl_xor_sync(0xffffffffu, s2, o);
    if ((t & 31) == 0) red[t >> 5] = s2;
    __syncthreads();
    float tot2 = 0.f;
    #pragma unroll
    for (int i = 0; i < 8; i++) tot2 += red[i];
    const float rstd = rsqrtf(tot2 * (1.0f / 768.0f) + 1e-12f);

    float* y = Y + (size_t)row * DD;
    #pragma unroll
    for (int c = 0; c < 3; c++) {
        int idx = t + 256 * c;
        float dv = (c == 0) ? d0 : (c == 1) ? d1 : d2;
        float r = dv * rstd * g[idx] + bta[idx];
        y[idx] = r;
        if (Yhi) {
            size_t off = ((size_t)(row >> 6) * 24 + (idx >> 5)) * 2048
                         + sw_elem(row & 63, idx & 31);
            bf16 hh = __float2bfloat16(r);
            Yhi[off] = hh;
            Ylo[off] = __float2bfloat16(r - __bfloat162float(hh));
        }
    }
}

// ---------------- launch ----------------------------------------------------
extern "C" void kernel_launch(void* const* d_in, const int* in_sizes, int n_in,
                              void* d_out, int out_size)
{
    const float* hidden  = (const float*)d_in[0];
    const float* tag_emb = (const float*)d_in[1];
    const float* sa_wq = (const float*)d_in[2],  *sa_bq = (const float*)d_in[3];
    const float* sa_wk = (const float*)d_in[4],  *sa_bk = (const float*)d_in[5];
    const float* sa_wv = (const float*)d_in[6],  *sa_bv = (const float*)d_in[7];
    const float* sa_wo = (const float*)d_in[8],  *sa_bo = (const float*)d_in[9];
    const float* sa_lg = (const float*)d_in[10], *sa_lb = (const float*)d_in[11];
    const float* ca_wq = (const float*)d_in[12], *ca_bq = (const float*)d_in[13];
    const float* ca_wk = (const float*)d_in[14], *ca_bk = (const float*)d_in[15];
    const float* ca_wv = (const float*)d_in[16], *ca_bv = (const float*)d_in[17];
    const float* ca_wo = (const float*)d_in[18], *ca_bo = (const float*)d_in[19];
    const float* ca_lg = (const float*)d_in[20], *ca_lb = (const float*)d_in[21];
    const float* ff_w1 = (const float*)d_in[22], *ff_b1 = (const float*)d_in[23];
    const float* ff_w2 = (const float*)d_in[24], *ff_b2 = (const float*)d_in[25];
    const float* ff_lg = (const float*)d_in[26], *ff_lb = (const float*)d_in[27];
    float* out = (float*)d_out;

    float *v, *tmp, *x1, *x2, *ck, *cv;
    bf16 *whi, *wlo, *qhi, *qlo, *khi, *klo, *vthi, *vtlo, *ctxhi, *ctxlo;
    bf16 *x1hi, *x1lo, *x2hi, *x2lo, *hhi, *hlo, *ihi, *ilo;
    bf16 *ckhi, *cklo, *cvthi, *cvtlo;
    cudaGetSymbolAddress((void**)&v,    g_v);
    cudaGetSymbolAddress((void**)&tmp,  g_tmp);
    cudaGetSymbolAddress((void**)&x1,   g_x1);
    cudaGetSymbolAddress((void**)&x2,   g_x2);
    cudaGetSymbolAddress((void**)&ck,   g_ck);
    cudaGetSymbolAddress((void**)&cv,   g_cv);
    cudaGetSymbolAddress((void**)&whi,  g_whi);
    cudaGetSymbolAddress((void**)&wlo,  g_wlo);
    cudaGetSymbolAddress((void**)&qhi,  g_qhi);
    cudaGetSymbolAddress((void**)&qlo,  g_qlo);
    cudaGetSymbolAddress((void**)&khi,  g_khi);
    cudaGetSymbolAddress((void**)&klo,  g_klo);
    cudaGetSymbolAddress((void**)&vthi, g_vthi);
    cudaGetSymbolAddress((void**)&vtlo, g_vtlo);
    cudaGetSymbolAddress((void**)&ctxhi, g_ctxhi);
    cudaGetSymbolAddress((void**)&ctxlo, g_ctxlo);
    cudaGetSymbolAddress((void**)&x1hi, g_x1hi);
    cudaGetSymbolAddress((void**)&x1lo, g_x1lo);
    cudaGetSymbolAddress((void**)&x2hi, g_x2hi);
    cudaGetSymbolAddress((void**)&x2lo, g_x2lo);
    cudaGetSymbolAddress((void**)&hhi,  g_hhi);
    cudaGetSymbolAddress((void**)&hlo,  g_hlo);
    cudaGetSymbolAddress((void**)&ihi,  g_ihi);
    cudaGetSymbolAddress((void**)&ilo,  g_ilo);
    cudaGetSymbolAddress((void**)&ckhi, g_ckhi);
    cudaGetSymbolAddress((void**)&cklo, g_cklo);
    cudaGetSymbolAddress((void**)&cvthi, g_cvthi);
    cudaGetSymbolAddress((void**)&cvtlo, g_cvtlo);

    cudaFuncSetAttribute(mma_gemm<0,1>, cudaFuncAttributeMaxDynamicSharedMemorySize, GEMM_SMEM);
    cudaFuncSetAttribute(mma_gemm<0,0>, cudaFuncAttributeMaxDynamicSharedMemorySize, GEMM_SMEM);
    cudaFuncSetAttribute(mma_gemm<1,0>, cudaFuncAttributeMaxDynamicSharedMemorySize, GEMM_SMEM);
    cudaFuncSetAttribute(mma_gemm<2,2>, cudaFuncAttributeMaxDynamicSharedMemorySize, GEMM_SMEM);
    cudaFuncSetAttribute(mma_gemm<0,2>, cudaFuncAttributeMaxDynamicSharedMemorySize, GEMM_SMEM);
    cudaFuncSetAttribute(mha_kernel,    cudaFuncAttributeMaxDynamicSharedMemorySize, ATT_SMEM);

    const size_t o_sawq = 0,             o_sawk = 1*(size_t)DxD, o_sawv = 2*(size_t)DxD;
    const size_t o_sawo = 3*(size_t)DxD, o_cawq = 4*(size_t)DxD, o_cawo = 5*(size_t)DxD;
    const size_t o_ff1  = 6*(size_t)DxD;
    const size_t o_ff2  = 6*(size_t)DxD + (size_t)768*3072;

    const dim3 wsB(32, 8);
    wsplit_kernel<<<dim3(24,24), wsB>>>(sa_wq, whi+o_sawq, wlo+o_sawq, 768, 768);
    wsplit_kernel<<<dim3(24,24), wsB>>>(sa_wk, whi+o_sawk, wlo+o_sawk, 768, 768);
    wsplit_kernel<<<dim3(24,24), wsB>>>(sa_wv, whi+o_sawv, wlo+o_sawv, 768, 768);
    wsplit_kernel<<<dim3(24,24), wsB>>>(sa_wo, whi+o_sawo, wlo+o_sawo, 768, 768);
    wsplit_kernel<<<dim3(24,24), wsB>>>(ca_wq, whi+o_cawq, wlo+o_cawq, 768, 768);
    wsplit_kernel<<<dim3(24,24), wsB>>>(ca_wo, whi+o_cawo, wlo+o_cawo, 768, 768);
    wsplit_kernel<<<dim3(96,24), wsB>>>(ff_w1, whi+o_ff1,  wlo+o_ff1,  768, 3072);
    wsplit_kernel<<<dim3(24,96), wsB>>>(ff_w2, whi+o_ff2,  wlo+o_ff2,  3072, 768);

    const dim3 thr(256);
    const dim3 gMMA_D (DD / GBN, MROWS / GBM);
    const dim3 gMMA_F1(FF / GBN, MROWS / GBM);
    const dim3 gCK(DD / BN, TT / BM);
    const dim3 attn_grid(SS / 64, HH, BB);
    const int nD4 = MROWS * DD / 4;
    const size_t smb = GEMM_SMEM;

    // ---- self attention ----
    asplit_kernel<<<(nD4 + 255)/256, 256>>>(hidden, hhi, hlo, nD4);
    mma_gemm<0,1><<<gMMA_D, thr, smb>>>(hhi, hlo, whi+o_sawq, wlo+o_sawq, sa_bq, nullptr, nullptr, qhi, qlo, DD, DD);
    mma_gemm<0,1><<<gMMA_D, thr, smb>>>(hhi, hlo, whi+o_sawk, wlo+o_sawk, sa_bk, nullptr, nullptr, khi, klo, DD, DD);
    mma_gemm<0,0><<<gMMA_D, thr, smb>>>(hhi, hlo, whi+o_sawv, wlo+o_sawv, sa_bv, nullptr, v, nullptr, nullptr, DD, DD);
    vtsplit_kernel<<<dim3(SS/32, 2, BB*HH), wsB>>>(v, vthi, vtlo);
    mha_kernel<<<attn_grid, 128, ATT_SMEM>>>(qhi, qlo, khi, klo, vthi, vtlo, ctxhi, ctxlo,
                                             SS/64, HH*32, 32, 1);
    mma_gemm<1,0><<<gMMA_D, thr, smb>>>(ctxhi, ctxlo, whi+o_sawo, wlo+o_sawo, sa_bo, hidden, tmp, nullptr, nullptr, DD, DD);
    ln_kernel<<<MROWS, thr>>>(tmp, sa_lg, sa_lb, x1, x1hi, x1lo);

    // ---- cross attention ----
    mma_gemm<0,1><<<gMMA_D, thr, smb>>>(x1hi, x1lo, whi+o_cawq, wlo+o_cawq, ca_bq, nullptr, nullptr, qhi, qlo, DD, DD);
    gemm_kernel<<<gCK, thr>>>(tag_emb, ca_wk, ca_bk, ck, TT, DD, DD);
    gemm_kernel<<<gCK, thr>>>(tag_emb, ca_wv, ca_bv, cv, TT, DD, DD);
    cpack_kernel<<<HH, 256>>>(ck, cv, ckhi, cklo, cvthi, cvtlo);
    mha_kernel<<<attn_grid, 128, ATT_SMEM>>>(qhi, qlo, ckhi, cklo, cvthi, cvtlo, ctxhi, ctxlo,
                                             1, 0, 1, 0);
    mma_gemm<1,0><<<gMMA_D, thr, smb>>>(ctxhi, ctxlo, whi+o_cawo, wlo+o_cawo, ca_bo, x1, tmp, nullptr, nullptr, DD, DD);
    ln_kernel<<<MROWS, thr>>>(tmp, ca_lg, ca_lb, x2, x2hi, x2lo);

    // ---- FFN ----
    mma_gemm<2,2><<<gMMA_F1, thr, smb>>>(x2hi, x2lo, whi+o_ff1, wlo+o_ff1, ff_b1, nullptr, nullptr, ihi, ilo, FF, DD);
    mma_gemm<1,0><<<gMMA_D, thr, smb>>>(ihi, ilo, whi+o_ff2, wlo+o_ff2, ff_b2, x2, tmp, nullptr, nullptr, DD, FF);
    ln_kernel<<<MROWS, thr>>>(tmp, ff_lg, ff_lb, out, nullptr, nullptr);
}

// round 8
// speedup vs baseline: 1.1722x; 1.0195x over previous
#include <cuda_runtime.h>
#include <cuda_bf16.h>
#include <math.h>
#include <stdint.h>

#define BB 2
#define SS 2048
#define DD 768
#define HH 12
#define DHH 64
#define TT 64
#define RR 50
#define FF 3072
#define MROWS (BB*SS)   // 4096

typedef __nv_bfloat16 bf16;

// ---------------- scratch ---------------------------------------------------
__device__ float g_tmp [MROWS*DD];
__device__ float g_x1  [MROWS*DD];
__device__ float g_x2  [MROWS*DD];
__device__ float g_ck  [TT*DD];
__device__ float g_cv  [TT*DD];
__device__ float g_bqkv[3*DD];

// attention-packed buffers (64x64 sw64 blocks)
__device__ __align__(128) bf16 g_qhi[MROWS*DD];
__device__ __align__(128) bf16 g_qlo[MROWS*DD];
__device__ __align__(128) bf16 g_khi[MROWS*DD];
__device__ __align__(128) bf16 g_klo[MROWS*DD];
__device__ __align__(128) bf16 g_vthi[BB*HH*DHH*SS];
__device__ __align__(128) bf16 g_vtlo[BB*HH*DHH*SS];
__device__ __align__(128) bf16 g_ckhi[HH*TT*DHH];
__device__ __align__(128) bf16 g_cklo[HH*TT*DHH];
__device__ __align__(128) bf16 g_cvthi[HH*DHH*TT];
__device__ __align__(128) bf16 g_cvtlo[HH*DHH*TT];

// GEMM operand buffers (tile-packed; sw_elem blocks)
__device__ __align__(128) bf16 g_ctxhi[MROWS*DD];
__device__ __align__(128) bf16 g_ctxlo[MROWS*DD];
__device__ __align__(128) bf16 g_x1hi[MROWS*DD];
__device__ __align__(128) bf16 g_x1lo[MROWS*DD];
__device__ __align__(128) bf16 g_x2hi[MROWS*DD];
__device__ __align__(128) bf16 g_x2lo[MROWS*DD];
__device__ __align__(128) bf16 g_hhi[MROWS*DD];
__device__ __align__(128) bf16 g_hlo[MROWS*DD];
__device__ __align__(128) bf16 g_ihi[MROWS*FF];
__device__ __align__(128) bf16 g_ilo[MROWS*FF];

#define DxD (768*768)
#define WSPLIT_TOTAL (6*DxD + 2*768*3072)
__device__ __align__(128) bf16 g_whi[WSPLIT_TOTAL];
__device__ __align__(128) bf16 g_wlo[WSPLIT_TOTAL];

// ================= helpers ==================================================
__device__ __forceinline__ uint32_t smem_u32(const void* p) {
    return (uint32_t)__cvta_generic_to_shared(p);
}
__device__ __forceinline__ uint32_t pack_bf16(float a, float b) {
    __nv_bfloat162 t = __floats2bfloat162_rn(a, b);
    return *(uint32_t*)&t;
}
// swizzled element offset inside a [rows][32] bf16 tile (GEMM A/B blocks)
__device__ __forceinline__ uint32_t sw_elem(int row, int k) {
    return (uint32_t)(row * 32 + ((((k >> 3) ^ ((row >> 1) & 3))) << 3) + (k & 7));
}
// attention 64x64 tile swizzled element offset
__device__ __forceinline__ uint32_t sw64(int row, int k) {
    return (uint32_t)(row * 64 + ((((k >> 3) ^ (row & 7))) << 3) + (k & 7));
}

#define LDSM4(r0, r1, r2, r3, addr) \
    asm volatile("ldmatrix.sync.aligned.m8n8.x4.shared.b16 {%0,%1,%2,%3}, [%4];" \
                 : "=r"(r0), "=r"(r1), "=r"(r2), "=r"(r3) : "r"(addr))
#define MMA16816(c, a, b) \
    asm volatile("mma.sync.aligned.m16n8k16.row.col.f32.bf16.bf16.f32 " \
                 "{%0,%1,%2,%3}, {%4,%5,%6,%7}, {%8,%9}, {%0,%1,%2,%3};" \
                 : "+f"(c[0]), "+f"(c[1]), "+f"(c[2]), "+f"(c[3]) \
                 : "r"(a[0]), "r"(a[1]), "r"(a[2]), "r"(a[3]), "r"(b[0]), "r"(b[1]))

__device__ __forceinline__ void mbar_init(uint32_t a, uint32_t cnt) {
    asm volatile("mbarrier.init.shared.b64 [%0], %1;" :: "r"(a), "r"(cnt) : "memory");
}
__device__ __forceinline__ void mbar_expect(uint32_t a, uint32_t bytes) {
    asm volatile("mbarrier.arrive.expect_tx.shared.b64 _, [%0], %1;"
                 :: "r"(a), "r"(bytes) : "memory");
}
__device__ __forceinline__ void mbar_wait(uint32_t a, uint32_t parity) {
    asm volatile(
        "{\n\t.reg .pred P;\n\t"
        "W%=:\n\t"
        "mbarrier.try_wait.parity.acquire.cta.shared::cta.b64 P, [%0], %1, 0x989680;\n\t"
        "@!P bra W%=;\n\t}"
        :: "r"(a), "r"(parity) : "memory");
}
__device__ __forceinline__ void bulk_g2s(uint32_t dst, const void* src,
                                         uint32_t bytes, uint32_t mbar) {
    asm volatile(
        "cp.async.bulk.shared::cta.global.mbarrier::complete_tx::bytes [%0], [%1], %2, [%3];"
        :: "r"(dst), "l"(src), "r"(bytes), "r"(mbar) : "memory");
}

// ================= pack/split kernels ======================================
// hidden -> GEMM-A packed (64x32 blocks, K=768)
__global__ __launch_bounds__(256) void asplit_kernel(
    const float* __restrict__ X, bf16* __restrict__ hi,
    bf16* __restrict__ lo, int n4)
{
    int i = blockIdx.x * 256 + threadIdx.x;
    if (i >= n4) return;
    float4 v = ((const float4*)X)[i];
    int r = (i * 4) / 768, c = (i * 4) % 768;
    size_t off = ((size_t)(r >> 6) * 24 + (c >> 5)) * 2048 + sw_elem(r & 63, c & 31);
    bf16 h0 = __float2bfloat16(v.x), h1 = __float2bfloat16(v.y);
    bf16 h2 = __float2bfloat16(v.z), h3 = __float2bfloat16(v.w);
    *(__nv_bfloat162*)&hi[off]     = {h0, h1};
    *(__nv_bfloat162*)&hi[off + 2] = {h2, h3};
    *(__nv_bfloat162*)&lo[off]     = {__float2bfloat16(v.x - __bfloat162float(h0)),
                                      __float2bfloat16(v.y - __bfloat162float(h1))};
    *(__nv_bfloat162*)&lo[off + 2] = {__float2bfloat16(v.z - __bfloat162float(h2)),
                                      __float2bfloat16(v.w - __bfloat162float(h3))};
}

// all 8 weight splits in one launch. grid (96, 24, 8), block (32, 8).
__global__ __launch_bounds__(256) void wsplit8_kernel(
    const float* __restrict__ w0, const float* __restrict__ w1,
    const float* __restrict__ w2, const float* __restrict__ w3,
    const float* __restrict__ w4, const float* __restrict__ w5,
    const float* __restrict__ w6, const float* __restrict__ w7,
    bf16* __restrict__ hiB, bf16* __restrict__ loB)
{
    __shared__ float tile[32][33];
    const int z = blockIdx.z;
    const float* W;
    int K, N, n0, k0;
    size_t ofs;
    if (z < 6) {
        if (blockIdx.x >= 24) return;
        K = 768; N = 768;
        k0 = blockIdx.x * 32; n0 = blockIdx.y * 32;
        const float* ws[6] = {w0, w1, w2, w3, w4, w5};
        W = ws[z];
        ofs = (size_t)z * DxD;
    } else if (z == 6) {           // ff_w1: K=768, N=3072
        K = 768; N = 3072;
        n0 = blockIdx.x * 32; k0 = blockIdx.y * 32;
        W = w6;
        ofs = 6 * (size_t)DxD;
    } else {                       // ff_w2: K=3072, N=768
        K = 3072; N = 768;
        k0 = blockIdx.x * 32; n0 = blockIdx.y * 32;
        W = w7;
        ofs = 6 * (size_t)DxD + (size_t)768 * 3072;
    }
    bf16* hiT = hiB + ofs;
    bf16* loT = loB + ofs;

    const int tx = threadIdx.x, ty = threadIdx.y;
    #pragma unroll
    for (int i = 0; i < 4; i++)
        tile[ty + 8*i][tx] = W[(size_t)(k0 + ty + 8*i) * N + n0 + tx];
    __syncthreads();
    #pragma unroll
    for (int i = 0; i < 4; i++) {
        float v = tile[tx][ty + 8*i];
        int n = n0 + ty + 8*i, k = k0 + tx;
        bf16 h = __float2bfloat16(v);
        size_t o = ((size_t)(n >> 7) * (K >> 5) + (k >> 5)) * 4096 + sw_elem(n & 127, k & 31);
        hiT[o] = h;
        loT[o] = __float2bfloat16(v - __bfloat162float(h));
    }
}

// concat q/k/v biases into one 2304 vector
__global__ __launch_bounds__(256) void bcat_kernel(
    const float* __restrict__ a, const float* __restrict__ b,
    const float* __restrict__ c, float* __restrict__ o)
{
    int i = blockIdx.x * 256 + threadIdx.x;
    if (i < 768) o[i] = a[i];
    else if (i < 1536) o[i] = b[i - 768];
    else if (i < 2304) o[i] = c[i - 1536];
}

// cross K/V fp32 [64][768] -> attention packed per head
__global__ __launch_bounds__(256) void cpack_kernel(
    const float* __restrict__ ck, const float* __restrict__ cv,
    bf16* __restrict__ khi, bf16* __restrict__ klo,
    bf16* __restrict__ vhi, bf16* __restrict__ vlo)
{
    const int h = blockIdx.x;
    for (int idx = threadIdx.x; idx < 4096; idx += 256) {
        int s = idx >> 6, d = idx & 63;
        float kv = ck[(size_t)s * DD + h * DHH + d];
        bf16 kh = __float2bfloat16(kv);
        size_t ko = (size_t)h * 4096 + sw64(s, d);
        khi[ko] = kh;
        klo[ko] = __float2bfloat16(kv - __bfloat162float(kh));
        float vv = cv[(size_t)s * DD + h * DHH + d];
        bf16 vh = __float2bfloat16(vv);
        size_t vo = (size_t)h * 4096 + sw64(d, s);
        vhi[vo] = vh;
        vlo[vo] = __float2bfloat16(vv - __bfloat162float(vh));
    }
}

// ================= bf16-split tensor-core GEMM (bulk-copy loads) ===========
#define GBM 64
#define GBN 128
#define STAGE_BYTES 24576
#define OFF_AHI 0
#define OFF_ALO 4096
#define OFF_BHI 8192
#define OFF_BLO 16384
#define GEMM_SMEM (1024 + 2*STAGE_BYTES)

// MODE: 0 bias, 1 bias+res, 2 bias+gelu
// OSPLIT: 0 fp32 C | 1 attention-QK packed | 2 GEMM-A packed | 3 fused QKV route
template<int MODE, int OSPLIT>
__global__ __launch_bounds__(256, 2) void mma_gemm(
    const bf16* __restrict__ Apk_hi, const bf16* __restrict__ Apk_lo,
    const bf16* __restrict__ Bpk_hi, const bf16* __restrict__ Bpk_lo,
    const float* __restrict__ bias, const float* __restrict__ Rz,
    float* __restrict__ C, bf16* __restrict__ Chi, bf16* __restrict__ Clo,
    bf16* __restrict__ C2hi, bf16* __restrict__ C2lo,
    bf16* __restrict__ C3hi, bf16* __restrict__ C3lo,
    int N, int K)
{
    extern __shared__ __align__(16) char smem[];
    const uint32_t sb = smem_u32(smem);
    const uint32_t mb0 = sb, mb1 = sb + 8;
    const uint32_t data = sb + 1024;

    const int tid = threadIdx.x;
    const int wid = tid >> 5, lane = tid & 31;
    const int warp_m = wid & 1, warp_n = wid >> 1;
    const int m0 = blockIdx.y * GBM, n0 = blockIdx.x * GBN;
    const int KT = K >> 5;

    const bf16* Ahi_t = Apk_hi + (size_t)(m0 >> 6) * KT * 2048;
    const bf16* Alo_t = Apk_lo + (size_t)(m0 >> 6) * KT * 2048;
    const bf16* Bhi_t = Bpk_hi + (size_t)(n0 >> 7) * KT * 4096;
    const bf16* Blo_t = Bpk_lo + (size_t)(n0 >> 7) * KT * 4096;

    if (tid == 0) { mbar_init(mb0, 1); mbar_init(mb1, 1); }
    __syncthreads();

    auto issue = [&](int s, int kt) {
        const uint32_t mb = s ? mb1 : mb0;
        mbar_expect(mb, (uint32_t)STAGE_BYTES);
        const uint32_t b = data + s * STAGE_BYTES;
        bulk_g2s(b + OFF_AHI, Ahi_t + (size_t)kt * 2048, 4096, mb);
        bulk_g2s(b + OFF_ALO, Alo_t + (size_t)kt * 2048, 4096, mb);
        bulk_g2s(b + OFF_BHI, Bhi_t + (size_t)kt * 4096, 8192, mb);
        bulk_g2s(b + OFF_BLO, Blo_t + (size_t)kt * 4096, 8192, mb);
    };
    if (tid == 0) issue(0, 0);

    float acc[2][4][4];
    #pragma unroll
    for (int i = 0; i < 2; i++)
        #pragma unroll
        for (int j = 0; j < 4; j++)
            #pragma unroll
            for (int p = 0; p < 4; p++) acc[i][j][p] = 0.f;

    const int lr16 = lane & 15;
    const int lk8  = (lane >> 4) * 8;
    int ph0 = 0, ph1 = 0;

    for (int kt = 0; kt < KT; kt++) {
        const int s = kt & 1;
        if (kt + 1 < KT && tid == 0) issue(s ^ 1, kt + 1);
        if (s == 0) { mbar_wait(mb0, ph0); ph0 ^= 1; }
        else        { mbar_wait(mb1, ph1); ph1 ^= 1; }

        const uint32_t base = data + s * STAGE_BYTES;
        #pragma unroll
        for (int k16 = 0; k16 < 32; k16 += 16) {
            uint32_t ah[2][4], al[2][4];
            #pragma unroll
            for (int mt = 0; mt < 2; mt++) {
                int row = warp_m * 32 + mt * 16 + lr16;
                uint32_t off = sw_elem(row, k16 + lk8) * 2;
                LDSM4(ah[mt][0], ah[mt][1], ah[mt][2], ah[mt][3], base + OFF_AHI + off);
                LDSM4(al[mt][0], al[mt][1], al[mt][2], al[mt][3], base + OFF_ALO + off);
            }
            uint32_t bh[4][2], bl[4][2];
            #pragma unroll
            for (int p = 0; p < 2; p++) {
                int row = warp_n * 32 + p * 16 + lr16;
                uint32_t off = sw_elem(row, k16 + lk8) * 2;
                uint32_t q0, q1, q2, q3;
                LDSM4(q0, q1, q2, q3, base + OFF_BHI + off);
                bh[2*p][0] = q0; bh[2*p][1] = q2; bh[2*p+1][0] = q1; bh[2*p+1][1] = q3;
                LDSM4(q0, q1, q2, q3, base + OFF_BLO + off);
                bl[2*p][0] = q0; bl[2*p][1] = q2; bl[2*p+1][0] = q1; bl[2*p+1][1] = q3;
            }
            #pragma unroll
            for (int mt = 0; mt < 2; mt++)
                #pragma unroll
                for (int nt = 0; nt < 4; nt++) {
                    MMA16816(acc[mt][nt], ah[mt], bh[nt]);
                    MMA16816(acc[mt][nt], ah[mt], bl[nt]);
                    MMA16816(acc[mt][nt], al[mt], bh[nt]);
                }
        }
        __syncthreads();
    }

    #pragma unroll
    for (int mt = 0; mt < 2; mt++) {
        #pragma unroll
        for (int nt = 0; nt < 4; nt++) {
            int r0 = m0 + warp_m * 32 + mt * 16 + (lane >> 2);
            int cc = n0 + warp_n * 32 + nt * 8 + 2 * (lane & 3);
            float b0 = bias[cc], b1 = bias[cc + 1];
            #pragma unroll
            for (int hh = 0; hh < 2; hh++) {
                int r = r0 + 8 * hh;
                float v0 = acc[mt][nt][2*hh]     + b0;
                float v1 = acc[mt][nt][2*hh + 1] + b1;
                if (MODE == 1) {
                    const float* rp = Rz + (size_t)r * N + cc;
                    v0 += rp[0]; v1 += rp[1];
                }
                if (MODE == 2) {
                    v0 = 0.5f * v0 * (1.0f + erff(v0 * 0.70710678118654752f));
                    v1 = 0.5f * v1 * (1.0f + erff(v1 * 0.70710678118654752f));
                }
                if (OSPLIT == 0) {
                    *(float2*)&C[(size_t)r * N + cc] = make_float2(v0, v1);
                } else {
                    bf16 h0 = __float2bfloat16(v0), h1 = __float2bfloat16(v1);
                    __nv_bfloat162 hv = {h0, h1};
                    bf16 l0b = __float2bfloat16(v0 - __bfloat162float(h0));
                    bf16 l1b = __float2bfloat16(v1 - __bfloat162float(h1));
                    __nv_bfloat162 lv = {l0b, l1b};
                    if (OSPLIT == 1) {
                        int bb = r >> 11, s2 = r & 2047;
                        int h2 = cc >> 6, d = cc & 63;
                        size_t off = ((size_t)(bb * HH + h2) * 32 + (s2 >> 6)) * 4096
                                     + sw64(s2 & 63, d);
                        *(__nv_bfloat162*)&Chi[off] = hv;
                        *(__nv_bfloat162*)&Clo[off] = lv;
                    } else if (OSPLIT == 2) {
                        size_t off = ((size_t)(r >> 6) * (N >> 5) + (cc >> 5)) * 2048
                                     + sw_elem(r & 63, cc & 31);
                        *(__nv_bfloat162*)&Chi[off] = hv;
                        *(__nv_bfloat162*)&Clo[off] = lv;
                    } else {
                        // fused QKV routing: cc in [0,2304)
                        int j = (cc >= 1536) ? 2 : ((cc >= 768) ? 1 : 0);
                        int local = cc - j * 768;
                        int bb = r >> 11, s2 = r & 2047;
                        int h2 = local >> 6, d = local & 63;
                        size_t blk = ((size_t)(bb * HH + h2) * 32 + (s2 >> 6)) * 4096;
                        if (j == 0) {
                            size_t off = blk + sw64(s2 & 63, d);
                            *(__nv_bfloat162*)&Chi[off] = hv;
                            *(__nv_bfloat162*)&Clo[off] = lv;
                        } else if (j == 1) {
                            size_t off = blk + sw64(s2 & 63, d);
                            *(__nv_bfloat162*)&C2hi[off] = hv;
                            *(__nv_bfloat162*)&C2lo[off] = lv;
                        } else {
                            // V: transpose into (d, s) layout — scalar stores
                            size_t off0 = blk + sw64(d,     s2 & 63);
                            size_t off1 = blk + sw64(d + 1, s2 & 63);
                            C3hi[off0] = h0; C3lo[off0] = l0b;
                            C3hi[off1] = h1; C3lo[off1] = l1b;
                        }
                    }
                }
            }
        }
    }
}

// ---------------- fp32 SIMT GEMM (tag projections) --------------------------
#define BM 64
#define BN 64
#define BK 16
__global__ __launch_bounds__(256) void gemm_kernel(
    const float* __restrict__ A, const float* __restrict__ W,
    const float* __restrict__ bias, float* __restrict__ C, int M, int N, int K)
{
    __shared__ float As[BK][68];
    __shared__ float Bs[BK][BN];
    const int tid = threadIdx.x;
    const int tx = tid & 15, ty = tid >> 4;
    const int m0 = blockIdx.y * BM, n0 = blockIdx.x * BN;
    float acc[4][4] = {};
    for (int k0 = 0; k0 < K; k0 += BK) {
        {
            const int r = tid >> 4, c = tid & 15;
            #pragma unroll
            for (int i = 0; i < 4; i++)
                As[c][r + 16*i] = A[(size_t)(m0 + r + 16*i) * K + k0 + c];
        }
        {
            const int r = tid >> 6, c = tid & 63;
            #pragma unroll
            for (int i = 0; i < 4; i++)
                Bs[r + 4*i][c] = W[(size_t)(k0 + r + 4*i) * N + n0 + c];
        }
        __syncthreads();
        #pragma unroll
        for (int kk = 0; kk < BK; kk++) {
            float4 a4 = *(const float4*)&As[kk][ty*4];
            float4 b4 = *(const float4*)&Bs[kk][tx*4];
            float a[4] = {a4.x, a4.y, a4.z, a4.w};
            float b[4] = {b4.x, b4.y, b4.z, b4.w};
            #pragma unroll
            for (int i = 0; i < 4; i++)
                #pragma unroll
                for (int j = 0; j < 4; j++)
                    acc[i][j] += a[i] * b[j];
        }
        __syncthreads();
    }
    #pragma unroll
    for (int i = 0; i < 4; i++) {
        const int m = m0 + ty*4 + i;
        #pragma unroll
        for (int j = 0; j < 4; j++) {
            const int n = n0 + tx*4 + j;
            C[(size_t)m * N + n] = acc[i][j] + bias[n];
        }
    }
}

// ================= tensor-core flash attention (bulk-copy loads) ============
#define AQHI 0
#define AQLO 8192
#define ASTG 16384
#define AKHI 0
#define AKLO 8192
#define AVHI 16384
#define AVLO 24576
#define ATT_SMEM (1024 + 16384 + 2*32768)

__global__ __launch_bounds__(128) void mha_kernel(
    const bf16* __restrict__ Qhi, const bf16* __restrict__ Qlo,
    const bf16* __restrict__ Khi, const bf16* __restrict__ Klo,
    const bf16* __restrict__ Vhi, const bf16* __restrict__ Vlo,
    bf16* __restrict__ Ohi, bf16* __restrict__ Olo,
    int ntiles, int kb, int kh, int banded)
{
    extern __shared__ __align__(16) char smem[];
    const uint32_t sb = smem_u32(smem);
    const uint32_t mbq = sb, mb0 = sb + 8, mb1 = sb + 16;
    const uint32_t data = sb + 1024;

    const int tid = threadIdx.x;
    const int wid = tid >> 5, lane = tid & 31;
    const int b = blockIdx.z, h = blockIdx.y;
    const int q0 = blockIdx.x * 64;

    const int lr16 = lane & 15;
    const int lk8  = (lane >> 4) * 8;

    if (tid == 0) { mbar_init(mbq, 1); mbar_init(mb0, 1); mbar_init(mb1, 1); }
    __syncthreads();

    const size_t qblk  = (size_t)(b * HH + h) * 32 + (q0 >> 6);
    const size_t kvbase = (size_t)b * kb + (size_t)h * kh;

    auto issue_kv = [&](int s, int kt) {
        const uint32_t mb = s ? mb1 : mb0;
        mbar_expect(mb, 32768u);
        const uint32_t st = data + ASTG + s * 32768;
        bulk_g2s(st + AKHI, Khi + (kvbase + kt) * 4096, 8192, mb);
        bulk_g2s(st + AKLO, Klo + (kvbase + kt) * 4096, 8192, mb);
        bulk_g2s(st + AVHI, Vhi + (kvbase + kt) * 4096, 8192, mb);
        bulk_g2s(st + AVLO, Vlo + (kvbase + kt) * 4096, 8192, mb);
    };

    if (tid == 0) {
        mbar_expect(mbq, 16384u);
        bulk_g2s(data + AQHI, Qhi + qblk * 4096, 8192, mbq);
        bulk_g2s(data + AQLO, Qlo + qblk * 4096, 8192, mbq);
        issue_kv(0, 0);
    }

    mbar_wait(mbq, 0);
    uint32_t qh[4][4], ql[4][4];
    #pragma unroll
    for (int ks = 0; ks < 4; ks++) {
        int row = wid * 16 + lr16;
        uint32_t off = sw64(row, ks * 16 + lk8) * 2;
        LDSM4(qh[ks][0], qh[ks][1], qh[ks][2], qh[ks][3], data + AQHI + off);
        LDSM4(ql[ks][0], ql[ks][1], ql[ks][2], ql[ks][3], data + AQLO + off);
    }

    float m0r = -1e30f, m1r = -1e30f, l0 = 0.f, l1 = 0.f;
    float oa[8][4];
    #pragma unroll
    for (int nt = 0; nt < 8; nt++)
        #pragma unroll
        for (int e = 0; e < 4; e++) oa[nt][e] = 0.f;

    const int gr = lane >> 2;
    const int gc2 = (lane & 3) * 2;
    const int qrow0 = q0 + wid * 16 + gr;
    const int qrow1 = qrow0 + 8;

    int ph0 = 0, ph1 = 0;
    for (int kt = 0; kt < ntiles; kt++) {
        const int s = kt & 1;
        if (kt + 1 < ntiles && tid == 0) issue_kv(s ^ 1, kt + 1);
        if (s == 0) { mbar_wait(mb0, ph0); ph0 ^= 1; }
        else        { mbar_wait(mb1, ph1); ph1 ^= 1; }

        const uint32_t base = data + ASTG + s * 32768;

        float sa[8][4];
        #pragma unroll
        for (int nt = 0; nt < 8; nt++)
            #pragma unroll
            for (int e = 0; e < 4; e++) sa[nt][e] = 0.f;

        #pragma unroll
        for (int p = 0; p < 4; p++) {
            #pragma unroll
            for (int ks = 0; ks < 4; ks++) {
                int row = p * 16 + lr16;
                uint32_t off = sw64(row, ks * 16 + lk8) * 2;
                uint32_t h0, h1, h2, h3, l0r, l1r, l2r, l3r;
                LDSM4(h0, h1, h2, h3, base + AKHI + off);
                LDSM4(l0r, l1r, l2r, l3r, base + AKLO + off);
                uint32_t bh0[2] = {h0, h2}, bh1[2] = {h1, h3};
                uint32_t bl0[2] = {l0r, l2r}, bl1[2] = {l1r, l3r};
                MMA16816(sa[2*p],   qh[ks], bh0);
                MMA16816(sa[2*p],   qh[ks], bl0);
                MMA16816(sa[2*p],   ql[ks], bh0);
                MMA16816(sa[2*p+1], qh[ks], bh1);
                MMA16816(sa[2*p+1], qh[ks], bl1);
                MMA16816(sa[2*p+1], ql[ks], bh1);
            }
        }

        #pragma unroll
        for (int nt = 0; nt < 8; nt++) {
            int col = kt * 64 + nt * 8 + gc2;
            #pragma unroll
            for (int e = 0; e < 4; e++) {
                float s2 = sa[nt][e] * 0.125f;
                if (banded) {
                    int r = (e < 2) ? qrow0 : qrow1;
                    int c = col + (e & 1);
                    int d = r - c;
                    if (d <= RR && d >= -RR) s2 += 1.0f;
                }
                sa[nt][e] = s2;
            }
        }

        float mx0 = -1e30f, mx1 = -1e30f;
        #pragma unroll
        for (int nt = 0; nt < 8; nt++) {
            mx0 = fmaxf(mx0, fmaxf(sa[nt][0], sa[nt][1]));
            mx1 = fmaxf(mx1, fmaxf(sa[nt][2], sa[nt][3]));
        }
        mx0 = fmaxf(mx0, __shfl_xor_sync(0xffffffffu, mx0, 1));
        mx0 = fmaxf(mx0, __shfl_xor_sync(0xffffffffu, mx0, 2));
        mx1 = fmaxf(mx1, __shfl_xor_sync(0xffffffffu, mx1, 1));
        mx1 = fmaxf(mx1, __shfl_xor_sync(0xffffffffu, mx1, 2));

        float nm0 = fmaxf(m0r, mx0), nm1 = fmaxf(m1r, mx1);
        float al0 = __expf(m0r - nm0), al1 = __expf(m1r - nm1);
        m0r = nm0; m1r = nm1;
        l0 *= al0; l1 *= al1;
        #pragma unroll
        for (int nt = 0; nt < 8; nt++) {
            oa[nt][0] *= al0; oa[nt][1] *= al0;
            oa[nt][2] *= al1; oa[nt][3] *= al1;
        }

        float ph_f[8][4], pl_f[8][4];
        #pragma unroll
        for (int nt = 0; nt < 8; nt++) {
            #pragma unroll
            for (int e = 0; e < 4; e++) {
                float p = __expf(sa[nt][e] - ((e < 2) ? nm0 : nm1));
                if (e < 2) l0 += p; else l1 += p;
                float hf = __bfloat162float(__float2bfloat16(p));
                ph_f[nt][e] = hf;
                pl_f[nt][e] = p - hf;
            }
        }

        uint32_t ph[4][4], pl[4][4];
        #pragma unroll
        for (int ks = 0; ks < 4; ks++) {
            int t0 = 2*ks, t1 = 2*ks + 1;
            ph[ks][0] = pack_bf16(ph_f[t0][0], ph_f[t0][1]);
            ph[ks][1] = pack_bf16(ph_f[t0][2], ph_f[t0][3]);
            ph[ks][2] = pack_bf16(ph_f[t1][0], ph_f[t1][1]);
            ph[ks][3] = pack_bf16(ph_f[t1][2], ph_f[t1][3]);
            pl[ks][0] = pack_bf16(pl_f[t0][0], pl_f[t0][1]);
            pl[ks][1] = pack_bf16(pl_f[t0][2], pl_f[t0][3]);
            pl[ks][2] = pack_bf16(pl_f[t1][0], pl_f[t1][1]);
            pl[ks][3] = pack_bf16(pl_f[t1][2], pl_f[t1][3]);
        }

        #pragma unroll
        for (int p = 0; p < 4; p++) {
            #pragma unroll
            for (int ks = 0; ks < 4; ks++) {
                int row = p * 16 + lr16;
                uint32_t off = sw64(row, ks * 16 + lk8) * 2;
                uint32_t h0, h1, h2, h3, v0, v1, v2, v3;
                LDSM4(h0, h1, h2, h3, base + AVHI + off);
                LDSM4(v0, v1, v2, v3, base + AVLO + off);
                uint32_t bh0[2] = {h0, h2}, bh1[2] = {h1, h3};
                uint32_t bl0[2] = {v0, v2}, bl1[2] = {v1, v3};
                MMA16816(oa[2*p],   ph[ks], bh0);
                MMA16816(oa[2*p],   pl[ks], bh0);
                MMA16816(oa[2*p],   ph[ks], bl0);
                MMA16816(oa[2*p+1], ph[ks], bh1);
                MMA16816(oa[2*p+1], pl[ks], bh1);
                MMA16816(oa[2*p+1], ph[ks], bl1);
            }
        }
        __syncthreads();
    }

    l0 += __shfl_xor_sync(0xffffffffu, l0, 1);
    l0 += __shfl_xor_sync(0xffffffffu, l0, 2);
    l1 += __shfl_xor_sync(0xffffffffu, l1, 1);
    l1 += __shfl_xor_sync(0xffffffffu, l1, 2);
    const float inv0 = 1.0f / l0, inv1 = 1.0f / l1;

    // write ctx in GEMM-A packed layout (N=768 -> 24 col-blocks)
    #pragma unroll
    for (int nt = 0; nt < 8; nt++) {
        int d = nt * 8 + gc2;
        int col = h * DHH + d;
        int R0 = b * SS + qrow0, R1 = b * SS + qrow1;
        size_t off0 = ((size_t)(R0 >> 6) * 24 + (col >> 5)) * 2048 + sw_elem(R0 & 63, col & 31);
        size_t off1 = ((size_t)(R1 >> 6) * 24 + (col >> 5)) * 2048 + sw_elem(R1 & 63, col & 31);
        float v0 = oa[nt][0] * inv0, v1 = oa[nt][1] * inv0;
        float v2 = oa[nt][2] * inv1, v3 = oa[nt][3] * inv1;
        bf16 h0 = __float2bfloat16(v0), h1 = __float2bfloat16(v1);
        bf16 h2 = __float2bfloat16(v2), h3 = __float2bfloat16(v3);
        *(__nv_bfloat162*)&Ohi[off0] = {h0, h1};
        *(__nv_bfloat162*)&Olo[off0] = {__float2bfloat16(v0 - __bfloat162float(h0)),
                                        __float2bfloat16(v1 - __bfloat162float(h1))};
        *(__nv_bfloat162*)&Ohi[off1] = {h2, h3};
        *(__nv_bfloat162*)&Olo[off1] = {__float2bfloat16(v2 - __bfloat162float(h2)),
                                        __float2bfloat16(v3 - __bfloat162float(h3))};
    }
}

// ---------------- layernorm (fp32 + optional packed split out) --------------
__global__ __launch_bounds__(256) void ln_kernel(
    const float* __restrict__ X, const float* __restrict__ g,
    const float* __restrict__ bta, float* __restrict__ Y,
    bf16* __restrict__ Yhi, bf16* __restrict__ Ylo)
{
    __shared__ float red[8];
    const int row = blockIdx.x, t = threadIdx.x;
    const float* x = X + (size_t)row * DD;

    float v0 = x[t], v1 = x[t + 256], v2 = x[t + 512];
    float s = v0 + v1 + v2;
    #pragma unroll
    for (int o = 16; o; o >>= 1) s += __shfl_xor_sync(0xffffffffu, s, o);
    if ((t & 31) == 0) red[t >> 5] = s;
    __syncthreads();
    float tot = 0.f;
    #pragma unroll
    for (int i = 0; i < 8; i++) tot += red[i];
    const float mean = tot * (1.0f / 768.0f);

    float d0 = v0 - mean, d1 = v1 - mean, d2 = v2 - mean;
    float s2 = d0*d0 + d1*d1 + d2*d2;
    __syncthreads();
    #pragma unroll
    for (int o = 16; o; o >>= 1) s2 += __shfl_xor_sync(0xffffffffu, s2, o);
    if ((t & 31) == 0) red[t >> 5] = s2;
    __syncthreads();
    float tot2 = 0.f;
    #pragma unroll
    for (int i = 0; i < 8; i++) tot2 += red[i];
    const float rstd = rsqrtf(tot2 * (1.0f / 768.0f) + 1e-12f);

    float* y = Y + (size_t)row * DD;
    #pragma unroll
    for (int c = 0; c < 3; c++) {
        int idx = t + 256 * c;
        float dv = (c == 0) ? d0 : (c == 1) ? d1 : d2;
        float r = dv * rstd * g[idx] + bta[idx];
        y[idx] = r;
        if (Yhi) {
            size_t off = ((size_t)(row >> 6) * 24 + (idx >> 5)) * 2048
                         + sw_elem(row & 63, idx & 31);
            bf16 hh = __float2bfloat16(r);
            Yhi[off] = hh;
            Ylo[off] = __float2bfloat16(r - __bfloat162float(hh));
        }
    }
}

// ---------------- launch ----------------------------------------------------
extern "C" void kernel_launch(void* const* d_in, const int* in_sizes, int n_in,
                              void* d_out, int out_size)
{
    const float* hidden  = (const float*)d_in[0];
    const float* tag_emb = (const float*)d_in[1];
    const float* sa_wq = (const float*)d_in[2],  *sa_bq = (const float*)d_in[3];
    const float* sa_wk = (const float*)d_in[4],  *sa_bk = (const float*)d_in[5];
    const float* sa_wv = (const float*)d_in[6],  *sa_bv = (const float*)d_in[7];
    const float* sa_wo = (const float*)d_in[8],  *sa_bo = (const float*)d_in[9];
    const float* sa_lg = (const float*)d_in[10], *sa_lb = (const float*)d_in[11];
    const float* ca_wq = (const float*)d_in[12], *ca_bq = (const float*)d_in[13];
    const float* ca_wk = (const float*)d_in[14], *ca_bk = (const float*)d_in[15];
    const float* ca_wv = (const float*)d_in[16], *ca_bv = (const float*)d_in[17];
    const float* ca_wo = (const float*)d_in[18], *ca_bo = (const float*)d_in[19];
    const float* ca_lg = (const float*)d_in[20], *ca_lb = (const float*)d_in[21];
    const float* ff_w1 = (const float*)d_in[22], *ff_b1 = (const float*)d_in[23];
    const float* ff_w2 = (const float*)d_in[24], *ff_b2 = (const float*)d_in[25];
    const float* ff_lg = (const float*)d_in[26], *ff_lb = (const float*)d_in[27];
    float* out = (float*)d_out;

    float *tmp, *x1, *x2, *ck, *cv, *bqkv;
    bf16 *whi, *wlo, *qhi, *qlo, *khi, *klo, *vthi, *vtlo, *ctxhi, *ctxlo;
    bf16 *x1hi, *x1lo, *x2hi, *x2lo, *hhi, *hlo, *ihi, *ilo;
    bf16 *ckhi, *cklo, *cvthi, *cvtlo;
    cudaGetSymbolAddress((void**)&tmp,  g_tmp);
    cudaGetSymbolAddress((void**)&x1,   g_x1);
    cudaGetSymbolAddress((void**)&x2,   g_x2);
    cudaGetSymbolAddress((void**)&ck,   g_ck);
    cudaGetSymbolAddress((void**)&cv,   g_cv);
    cudaGetSymbolAddress((void**)&bqkv, g_bqkv);
    cudaGetSymbolAddress((void**)&whi,  g_whi);
    cudaGetSymbolAddress((void**)&wlo,  g_wlo);
    cudaGetSymbolAddress((void**)&qhi,  g_qhi);
    cudaGetSymbolAddress((void**)&qlo,  g_qlo);
    cudaGetSymbolAddress((void**)&khi,  g_khi);
    cudaGetSymbolAddress((void**)&klo,  g_klo);
    cudaGetSymbolAddress((void**)&vthi, g_vthi);
    cudaGetSymbolAddress((void**)&vtlo, g_vtlo);
    cudaGetSymbolAddress((void**)&ctxhi, g_ctxhi);
    cudaGetSymbolAddress((void**)&ctxlo, g_ctxlo);
    cudaGetSymbolAddress((void**)&x1hi, g_x1hi);
    cudaGetSymbolAddress((void**)&x1lo, g_x1lo);
    cudaGetSymbolAddress((void**)&x2hi, g_x2hi);
    cudaGetSymbolAddress((void**)&x2lo, g_x2lo);
    cudaGetSymbolAddress((void**)&hhi,  g_hhi);
    cudaGetSymbolAddress((void**)&hlo,  g_hlo);
    cudaGetSymbolAddress((void**)&ihi,  g_ihi);
    cudaGetSymbolAddress((void**)&ilo,  g_ilo);
    cudaGetSymbolAddress((void**)&ckhi, g_ckhi);
    cudaGetSymbolAddress((void**)&cklo, g_cklo);
    cudaGetSymbolAddress((void**)&cvthi, g_cvthi);
    cudaGetSymbolAddress((void**)&cvtlo, g_cvtlo);

    cudaFuncSetAttribute(mma_gemm<0,3>, cudaFuncAttributeMaxDynamicSharedMemorySize, GEMM_SMEM);
    cudaFuncSetAttribute(mma_gemm<0,1>, cudaFuncAttributeMaxDynamicSharedMemorySize, GEMM_SMEM);
    cudaFuncSetAttribute(mma_gemm<1,0>, cudaFuncAttributeMaxDynamicSharedMemorySize, GEMM_SMEM);
    cudaFuncSetAttribute(mma_gemm<2,2>, cudaFuncAttributeMaxDynamicSharedMemorySize, GEMM_SMEM);
    cudaFuncSetAttribute(mha_kernel,    cudaFuncAttributeMaxDynamicSharedMemorySize, ATT_SMEM);

    const size_t o_sawo = 3*(size_t)DxD, o_cawq = 4*(size_t)DxD, o_cawo = 5*(size_t)DxD;
    const size_t o_ff1  = 6*(size_t)DxD;
    const size_t o_ff2  = 6*(size_t)DxD + (size_t)768*3072;

    const dim3 wsB(32, 8);
    // all weight splits in one launch (qkv at offsets 0,DxD,2DxD -> fused N=2304 layout)
    wsplit8_kernel<<<dim3(96, 24, 8), wsB>>>(sa_wq, sa_wk, sa_wv, sa_wo, ca_wq, ca_wo,
                                             ff_w1, ff_w2, whi, wlo);
    bcat_kernel<<<9, 256>>>(sa_bq, sa_bk, sa_bv, bqkv);

    const dim3 thr(256);
    const dim3 gQKV(2304 / GBN, MROWS / GBM);   // (18, 64)
    const dim3 gMMA_D (DD / GBN, MROWS / GBM);  // (6, 64)
    const dim3 gMMA_F1(FF / GBN, MROWS / GBM);  // (24, 64)
    const dim3 gCK(DD / BN, TT / BM);
    const dim3 attn_grid(SS / 64, HH, BB);
    const int nD4 = MROWS * DD / 4;
    const size_t smb = GEMM_SMEM;

    // ---- self attention ----
    asplit_kernel<<<(nD4 + 255)/256, 256>>>(hidden, hhi, hlo, nD4);
    mma_gemm<0,3><<<gQKV, thr, smb>>>(hhi, hlo, whi, wlo, bqkv, nullptr,
                                      nullptr, qhi, qlo, khi, klo, vthi, vtlo, 2304, DD);
    mha_kernel<<<attn_grid, 128, ATT_SMEM>>>(qhi, qlo, khi, klo, vthi, vtlo, ctxhi, ctxlo,
                                             SS/64, HH*32, 32, 1);
    mma_gemm<1,0><<<gMMA_D, thr, smb>>>(ctxhi, ctxlo, whi+o_sawo, wlo+o_sawo, sa_bo, hidden,
                                        tmp, nullptr, nullptr, nullptr, nullptr, nullptr, nullptr, DD, DD);
    ln_kernel<<<MROWS, thr>>>(tmp, sa_lg, sa_lb, x1, x1hi, x1lo);

    // ---- cross attention ----
    mma_gemm<0,1><<<gMMA_D, thr, smb>>>(x1hi, x1lo, whi+o_cawq, wlo+o_cawq, ca_bq, nullptr,
                                        nullptr, qhi, qlo, nullptr, nullptr, nullptr, nullptr, DD, DD);
    gemm_kernel<<<gCK, thr>>>(tag_emb, ca_wk, ca_bk, ck, TT, DD, DD);
    gemm_kernel<<<gCK, thr>>>(tag_emb, ca_wv, ca_bv, cv, TT, DD, DD);
    cpack_kernel<<<HH, 256>>>(ck, cv, ckhi, cklo, cvthi, cvtlo);
    mha_kernel<<<attn_grid, 128, ATT_SMEM>>>(qhi, qlo, ckhi, cklo, cvthi, cvtlo, ctxhi, ctxlo,
                                             1, 0, 1, 0);
    mma_gemm<1,0><<<gMMA_D, thr, smb>>>(ctxhi, ctxlo, whi+o_cawo, wlo+o_cawo, ca_bo, x1,
                                        tmp, nullptr, nullptr, nullptr, nullptr, nullptr, nullptr, DD, DD);
    ln_kernel<<<MROWS, thr>>>(tmp, ca_lg, ca_lb, x2, x2hi, x2lo);

    // ---- FFN ----
    mma_gemm<2,2><<<gMMA_F1, thr, smb>>>(x2hi, x2lo, whi+o_ff1, wlo+o_ff1, ff_b1, nullptr,
                                         nullptr, ihi, ilo, nullptr, nullptr, nullptr, nullptr, FF, DD);
    mma_gemm<1,0><<<gMMA_D, thr, smb>>>(ihi, ilo, whi+o_ff2, wlo+o_ff2, ff_b2, x2,
                                        tmp, nullptr, nullptr, nullptr, nullptr, nullptr, nullptr, DD, FF);
    ln_kernel<<<MROWS, thr>>>(tmp, ff_lg, ff_lb, out, nullptr, nullptr);
}

// round 10
// speedup vs baseline: 1.1795x; 1.0063x over previous
#include <cuda_runtime.h>
#include <cuda_bf16.h>
#include <math.h>
#include <stdint.h>

#define BB 2
#define SS 2048
#define DD 768
#define HH 12
#define DHH 64
#define TT 64
#define RR 50
#define FF 3072
#define MROWS (BB*SS)   // 4096

typedef __nv_bfloat16 bf16;

// ---------------- scratch ---------------------------------------------------
__device__ float g_tmp [MROWS*DD];
__device__ float g_x1  [MROWS*DD];
__device__ float g_x2  [MROWS*DD];
__device__ float g_ck  [TT*DD];
__device__ float g_cv  [TT*DD];
__device__ float g_bqkv[3*DD];

// attention-packed buffers (64x64 sw64 blocks)
__device__ __align__(128) bf16 g_qhi[MROWS*DD];
__device__ __align__(128) bf16 g_qlo[MROWS*DD];
__device__ __align__(128) bf16 g_khi[MROWS*DD];
__device__ __align__(128) bf16 g_klo[MROWS*DD];
__device__ __align__(128) bf16 g_vthi[BB*HH*DHH*SS];
__device__ __align__(128) bf16 g_vtlo[BB*HH*DHH*SS];
__device__ __align__(128) bf16 g_ckhi[HH*TT*DHH];
__device__ __align__(128) bf16 g_cklo[HH*TT*DHH];
__device__ __align__(128) bf16 g_cvthi[HH*DHH*TT];
__device__ __align__(128) bf16 g_cvtlo[HH*DHH*TT];

// GEMM operand buffers (tile-packed; sw_elem blocks)
__device__ __align__(128) bf16 g_ctxhi[MROWS*DD];
__device__ __align__(128) bf16 g_ctxlo[MROWS*DD];
__device__ __align__(128) bf16 g_x1hi[MROWS*DD];
__device__ __align__(128) bf16 g_x1lo[MROWS*DD];
__device__ __align__(128) bf16 g_x2hi[MROWS*DD];
__device__ __align__(128) bf16 g_x2lo[MROWS*DD];
__device__ __align__(128) bf16 g_hhi[MROWS*DD];
__device__ __align__(128) bf16 g_hlo[MROWS*DD];
__device__ __align__(128) bf16 g_ihi[MROWS*FF];
__device__ __align__(128) bf16 g_ilo[MROWS*FF];

#define DxD (768*768)
#define WSPLIT_TOTAL (6*DxD + 2*768*3072)
__device__ __align__(128) bf16 g_whi[WSPLIT_TOTAL];
__device__ __align__(128) bf16 g_wlo[WSPLIT_TOTAL];

// ================= helpers ==================================================
__device__ __forceinline__ uint32_t smem_u32(const void* p) {
    return (uint32_t)__cvta_generic_to_shared(p);
}
__device__ __forceinline__ uint32_t pack_bf16(float a, float b) {
    __nv_bfloat162 t = __floats2bfloat162_rn(a, b);
    return *(uint32_t*)&t;
}
// swizzled element offset inside a [rows][32] bf16 tile (GEMM A/B blocks)
__device__ __forceinline__ uint32_t sw_elem(int row, int k) {
    return (uint32_t)(row * 32 + ((((k >> 3) ^ ((row >> 1) & 3))) << 3) + (k & 7));
}
// attention 64x64 tile swizzled element offset
__device__ __forceinline__ uint32_t sw64(int row, int k) {
    return (uint32_t)(row * 64 + ((((k >> 3) ^ (row & 7))) << 3) + (k & 7));
}

#define LDSM4(r0, r1, r2, r3, addr) \
    asm volatile("ldmatrix.sync.aligned.m8n8.x4.shared.b16 {%0,%1,%2,%3}, [%4];" \
                 : "=r"(r0), "=r"(r1), "=r"(r2), "=r"(r3) : "r"(addr))
#define MMA16816(c, a, b) \
    asm volatile("mma.sync.aligned.m16n8k16.row.col.f32.bf16.bf16.f32 " \
                 "{%0,%1,%2,%3}, {%4,%5,%6,%7}, {%8,%9}, {%0,%1,%2,%3};" \
                 : "+f"(c[0]), "+f"(c[1]), "+f"(c[2]), "+f"(c[3]) \
                 : "r"(a[0]), "r"(a[1]), "r"(a[2]), "r"(a[3]), "r"(b[0]), "r"(b[1]))

__device__ __forceinline__ void mbar_init(uint32_t a, uint32_t cnt) {
    asm volatile("mbarrier.init.shared.b64 [%0], %1;" :: "r"(a), "r"(cnt) : "memory");
}
__device__ __forceinline__ void mbar_expect(uint32_t a, uint32_t bytes) {
    asm volatile("mbarrier.arrive.expect_tx.shared.b64 _, [%0], %1;"
                 :: "r"(a), "r"(bytes) : "memory");
}
__device__ __forceinline__ void mbar_wait(uint32_t a, uint32_t parity) {
    asm volatile(
        "{\n\t.reg .pred P;\n\t"
        "W%=:\n\t"
        "mbarrier.try_wait.parity.acquire.cta.shared::cta.b64 P, [%0], %1, 0x989680;\n\t"
        "@!P bra W%=;\n\t}"
        :: "r"(a), "r"(parity) : "memory");
}
__device__ __forceinline__ void bulk_g2s(uint32_t dst, const void* src,
                                         uint32_t bytes, uint32_t mbar) {
    asm volatile(
        "cp.async.bulk.shared::cta.global.mbarrier::complete_tx::bytes [%0], [%1], %2, [%3];"
        :: "r"(dst), "l"(src), "r"(bytes), "r"(mbar) : "memory");
}

// ================= pack/split kernels ======================================
__global__ __launch_bounds__(256) void asplit_kernel(
    const float* __restrict__ X, bf16* __restrict__ hi,
    bf16* __restrict__ lo, int n4)
{
    int i = blockIdx.x * 256 + threadIdx.x;
    if (i >= n4) return;
    float4 v = ((const float4*)X)[i];
    int r = (i * 4) / 768, c = (i * 4) % 768;
    size_t off = ((size_t)(r >> 6) * 24 + (c >> 5)) * 2048 + sw_elem(r & 63, c & 31);
    bf16 h0 = __float2bfloat16(v.x), h1 = __float2bfloat16(v.y);
    bf16 h2 = __float2bfloat16(v.z), h3 = __float2bfloat16(v.w);
    *(__nv_bfloat162*)&hi[off]     = {h0, h1};
    *(__nv_bfloat162*)&hi[off + 2] = {h2, h3};
    *(__nv_bfloat162*)&lo[off]     = {__float2bfloat16(v.x - __bfloat162float(h0)),
                                      __float2bfloat16(v.y - __bfloat162float(h1))};
    *(__nv_bfloat162*)&lo[off + 2] = {__float2bfloat16(v.z - __bfloat162float(h2)),
                                      __float2bfloat16(v.w - __bfloat162float(h3))};
}

// all 8 weight splits in one launch. grid (96, 24, 8), block (32, 8).
__global__ __launch_bounds__(256) void wsplit8_kernel(
    const float* __restrict__ w0, const float* __restrict__ w1,
    const float* __restrict__ w2, const float* __restrict__ w3,
    const float* __restrict__ w4, const float* __restrict__ w5,
    const float* __restrict__ w6, const float* __restrict__ w7,
    bf16* __restrict__ hiB, bf16* __restrict__ loB)
{
    __shared__ float tile[32][33];
    const int z = blockIdx.z;
    const float* W;
    int K, N, n0, k0;
    size_t ofs;
    if (z < 6) {
        if (blockIdx.x >= 24) return;
        K = 768; N = 768;
        k0 = blockIdx.x * 32; n0 = blockIdx.y * 32;
        const float* ws[6] = {w0, w1, w2, w3, w4, w5};
        W = ws[z];
        ofs = (size_t)z * DxD;
    } else if (z == 6) {
        K = 768; N = 3072;
        n0 = blockIdx.x * 32; k0 = blockIdx.y * 32;
        W = w6;
        ofs = 6 * (size_t)DxD;
    } else {
        K = 3072; N = 768;
        k0 = blockIdx.x * 32; n0 = blockIdx.y * 32;
        W = w7;
        ofs = 6 * (size_t)DxD + (size_t)768 * 3072;
    }
    bf16* hiT = hiB + ofs;
    bf16* loT = loB + ofs;

    const int tx = threadIdx.x, ty = threadIdx.y;
    #pragma unroll
    for (int i = 0; i < 4; i++)
        tile[ty + 8*i][tx] = W[(size_t)(k0 + ty + 8*i) * N + n0 + tx];
    __syncthreads();
    #pragma unroll
    for (int i = 0; i < 4; i++) {
        float v = tile[tx][ty + 8*i];
        int n = n0 + ty + 8*i, k = k0 + tx;
        bf16 h = __float2bfloat16(v);
        size_t o = ((size_t)(n >> 7) * (K >> 5) + (k >> 5)) * 4096 + sw_elem(n & 127, k & 31);
        hiT[o] = h;
        loT[o] = __float2bfloat16(v - __bfloat162float(h));
    }
}

__global__ __launch_bounds__(256) void bcat_kernel(
    const float* __restrict__ a, const float* __restrict__ b,
    const float* __restrict__ c, float* __restrict__ o)
{
    int i = blockIdx.x * 256 + threadIdx.x;
    if (i < 768) o[i] = a[i];
    else if (i < 1536) o[i] = b[i - 768];
    else if (i < 2304) o[i] = c[i - 1536];
}

__global__ __launch_bounds__(256) void cpack_kernel(
    const float* __restrict__ ck, const float* __restrict__ cv,
    bf16* __restrict__ khi, bf16* __restrict__ klo,
    bf16* __restrict__ vhi, bf16* __restrict__ vlo)
{
    const int h = blockIdx.x;
    for (int idx = threadIdx.x; idx < 4096; idx += 256) {
        int s = idx >> 6, d = idx & 63;
        float kv = ck[(size_t)s * DD + h * DHH + d];
        bf16 kh = __float2bfloat16(kv);
        size_t ko = (size_t)h * 4096 + sw64(s, d);
        khi[ko] = kh;
        klo[ko] = __float2bfloat16(kv - __bfloat162float(kh));
        float vv = cv[(size_t)s * DD + h * DHH + d];
        bf16 vh = __float2bfloat16(vv);
        size_t vo = (size_t)h * 4096 + sw64(d, s);
        vhi[vo] = vh;
        vlo[vo] = __float2bfloat16(vv - __bfloat162float(vh));
    }
}

// ================= bf16-split tensor-core GEMM (3-stage pipeline) ==========
#define GBM 64
#define GBN 128
#define STAGE_BYTES 24576
#define OFF_AHI 0
#define OFF_ALO 4096
#define OFF_BHI 8192
#define OFF_BLO 16384
#define GEMM_SMEM (1024 + 3*STAGE_BYTES)

// MODE: 0 bias, 1 bias+res, 2 bias+gelu
// OSPLIT: 0 fp32 C | 1 attention-QK packed | 2 GEMM-A packed | 3 fused QKV route
template<int MODE, int OSPLIT>
__global__ __launch_bounds__(256, 2) void mma_gemm(
    const bf16* __restrict__ Apk_hi, const bf16* __restrict__ Apk_lo,
    const bf16* __restrict__ Bpk_hi, const bf16* __restrict__ Bpk_lo,
    const float* __restrict__ bias, const float* __restrict__ Rz,
    float* __restrict__ C, bf16* __restrict__ Chi, bf16* __restrict__ Clo,
    bf16* __restrict__ C2hi, bf16* __restrict__ C2lo,
    bf16* __restrict__ C3hi, bf16* __restrict__ C3lo,
    int N, int K)
{
    extern __shared__ __align__(16) char smem[];
    const uint32_t sb = smem_u32(smem);
    const uint32_t mb0 = sb, mb1 = sb + 8, mb2 = sb + 16;
    const uint32_t data = sb + 1024;

    const int tid = threadIdx.x;
    const int wid = tid >> 5, lane = tid & 31;
    const int warp_m = wid & 1, warp_n = wid >> 1;
    const int m0 = blockIdx.y * GBM, n0 = blockIdx.x * GBN;
    const int KT = K >> 5;

    const bf16* Ahi_t = Apk_hi + (size_t)(m0 >> 6) * KT * 2048;
    const bf16* Alo_t = Apk_lo + (size_t)(m0 >> 6) * KT * 2048;
    const bf16* Bhi_t = Bpk_hi + (size_t)(n0 >> 7) * KT * 4096;
    const bf16* Blo_t = Bpk_lo + (size_t)(n0 >> 7) * KT * 4096;

    if (tid == 0) { mbar_init(mb0, 1); mbar_init(mb1, 1); mbar_init(mb2, 1); }
    __syncthreads();

    auto issue = [&](int s, int kt) {
        const uint32_t mb = sb + s * 8;
        mbar_expect(mb, (uint32_t)STAGE_BYTES);
        const uint32_t b = data + s * STAGE_BYTES;
        bulk_g2s(b + OFF_AHI, Ahi_t + (size_t)kt * 2048, 4096, mb);
        bulk_g2s(b + OFF_ALO, Alo_t + (size_t)kt * 2048, 4096, mb);
        bulk_g2s(b + OFF_BHI, Bhi_t + (size_t)kt * 4096, 8192, mb);
        bulk_g2s(b + OFF_BLO, Blo_t + (size_t)kt * 4096, 8192, mb);
    };
    if (tid == 0) {
        issue(0, 0);
        if (KT > 1) issue(1, 1);
    }

    float acc[2][4][4];
    #pragma unroll
    for (int i = 0; i < 2; i++)
        #pragma unroll
        for (int j = 0; j < 4; j++)
            #pragma unroll
            for (int p = 0; p < 4; p++) acc[i][j][p] = 0.f;

    const int lr16 = lane & 15;
    const int lk8  = (lane >> 4) * 8;
    int p0 = 0, p1 = 0, p2 = 0;
    int s = 0;

    for (int kt = 0; kt < KT; kt++) {
        if (s == 0) { mbar_wait(mb0, p0); p0 ^= 1; }
        else if (s == 1) { mbar_wait(mb1, p1); p1 ^= 1; }
        else { mbar_wait(mb2, p2); p2 ^= 1; }

        const uint32_t base = data + s * STAGE_BYTES;
        #pragma unroll
        for (int k16 = 0; k16 < 32; k16 += 16) {
            uint32_t ah[2][4], al[2][4];
            #pragma unroll
            for (int mt = 0; mt < 2; mt++) {
                int row = warp_m * 32 + mt * 16 + lr16;
                uint32_t off = sw_elem(row, k16 + lk8) * 2;
                LDSM4(ah[mt][0], ah[mt][1], ah[mt][2], ah[mt][3], base + OFF_AHI + off);
                LDSM4(al[mt][0], al[mt][1], al[mt][2], al[mt][3], base + OFF_ALO + off);
            }
            uint32_t bh[4][2], bl[4][2];
            #pragma unroll
            for (int p = 0; p < 2; p++) {
                int row = warp_n * 32 + p * 16 + lr16;
                uint32_t off = sw_elem(row, k16 + lk8) * 2;
                uint32_t q0, q1, q2, q3;
                LDSM4(q0, q1, q2, q3, base + OFF_BHI + off);
                bh[2*p][0] = q0; bh[2*p][1] = q2; bh[2*p+1][0] = q1; bh[2*p+1][1] = q3;
                LDSM4(q0, q1, q2, q3, base + OFF_BLO + off);
                bl[2*p][0] = q0; bl[2*p][1] = q2; bl[2*p+1][0] = q1; bl[2*p+1][1] = q3;
            }
            #pragma unroll
            for (int mt = 0; mt < 2; mt++)
                #pragma unroll
                for (int nt = 0; nt < 4; nt++) {
                    MMA16816(acc[mt][nt], ah[mt], bh[nt]);
                    MMA16816(acc[mt][nt], ah[mt], bl[nt]);
                    MMA16816(acc[mt][nt], al[mt], bh[nt]);
                }
        }
        __syncthreads();
        if (tid == 0 && kt + 2 < KT) issue((kt + 2) % 3, kt + 2);
        s = (s + 1 == 3) ? 0 : s + 1;
    }

    #pragma unroll
    for (int mt = 0; mt < 2; mt++) {
        #pragma unroll
        for (int nt = 0; nt < 4; nt++) {
            int r0 = m0 + warp_m * 32 + mt * 16 + (lane >> 2);
            int cc = n0 + warp_n * 32 + nt * 8 + 2 * (lane & 3);
            float b0 = bias[cc], b1 = bias[cc + 1];
            #pragma unroll
            for (int hh = 0; hh < 2; hh++) {
                int r = r0 + 8 * hh;
                float v0 = acc[mt][nt][2*hh]     + b0;
                float v1 = acc[mt][nt][2*hh + 1] + b1;
                if (MODE == 1) {
                    const float* rp = Rz + (size_t)r * N + cc;
                    v0 += rp[0]; v1 += rp[1];
                }
                if (MODE == 2) {
                    v0 = 0.5f * v0 * (1.0f + erff(v0 * 0.70710678118654752f));
                    v1 = 0.5f * v1 * (1.0f + erff(v1 * 0.70710678118654752f));
                }
                if (OSPLIT == 0) {
                    *(float2*)&C[(size_t)r * N + cc] = make_float2(v0, v1);
                } else {
                    bf16 h0 = __float2bfloat16(v0), h1 = __float2bfloat16(v1);
                    __nv_bfloat162 hv = {h0, h1};
                    bf16 l0b = __float2bfloat16(v0 - __bfloat162float(h0));
                    bf16 l1b = __float2bfloat16(v1 - __bfloat162float(h1));
                    __nv_bfloat162 lv = {l0b, l1b};
                    if (OSPLIT == 1) {
                        int bb = r >> 11, s2 = r & 2047;
                        int h2 = cc >> 6, d = cc & 63;
                        size_t off = ((size_t)(bb * HH + h2) * 32 + (s2 >> 6)) * 4096
                                     + sw64(s2 & 63, d);
                        *(__nv_bfloat162*)&Chi[off] = hv;
                        *(__nv_bfloat162*)&Clo[off] = lv;
                    } else if (OSPLIT == 2) {
                        size_t off = ((size_t)(r >> 6) * (N >> 5) + (cc >> 5)) * 2048
                                     + sw_elem(r & 63, cc & 31);
                        *(__nv_bfloat162*)&Chi[off] = hv;
                        *(__nv_bfloat162*)&Clo[off] = lv;
                    } else {
                        int j = (cc >= 1536) ? 2 : ((cc >= 768) ? 1 : 0);
                        int local = cc - j * 768;
                        int bb = r >> 11, s2 = r & 2047;
                        int h2 = local >> 6, d = local & 63;
                        size_t blk = ((size_t)(bb * HH + h2) * 32 + (s2 >> 6)) * 4096;
                        if (j == 0) {
                            size_t off = blk + sw64(s2 & 63, d);
                            *(__nv_bfloat162*)&Chi[off] = hv;
                            *(__nv_bfloat162*)&Clo[off] = lv;
                        } else if (j == 1) {
                            size_t off = blk + sw64(s2 & 63, d);
                            *(__nv_bfloat162*)&C2hi[off] = hv;
                            *(__nv_bfloat162*)&C2lo[off] = lv;
                        } else {
                            size_t off0 = blk + sw64(d,     s2 & 63);
                            size_t off1 = blk + sw64(d + 1, s2 & 63);
                            C3hi[off0] = h0; C3lo[off0] = l0b;
                            C3hi[off1] = h1; C3lo[off1] = l1b;
                        }
                    }
                }
            }
        }
    }
}

// ---------------- fp32 SIMT GEMM (tag projections) --------------------------
#define BM 64
#define BN 64
#define BK 16
__global__ __launch_bounds__(256) void gemm_kernel(
    const float* __restrict__ A, const float* __restrict__ W,
    const float* __restrict__ bias, float* __restrict__ C, int M, int N, int K)
{
    __shared__ float As[BK][68];
    __shared__ float Bs[BK][BN];
    const int tid = threadIdx.x;
    const int tx = tid & 15, ty = tid >> 4;
    const int m0 = blockIdx.y * BM, n0 = blockIdx.x * BN;
    float acc[4][4] = {};
    for (int k0 = 0; k0 < K; k0 += BK) {
        {
            const int r = tid >> 4, c = tid & 15;
            #pragma unroll
            for (int i = 0; i < 4; i++)
                As[c][r + 16*i] = A[(size_t)(m0 + r + 16*i) * K + k0 + c];
        }
        {
            const int r = tid >> 6, c = tid & 63;
            #pragma unroll
            for (int i = 0; i < 4; i++)
                Bs[r + 4*i][c] = W[(size_t)(k0 + r + 4*i) * N + n0 + c];
        }
        __syncthreads();
        #pragma unroll
        for (int kk = 0; kk < BK; kk++) {
            float4 a4 = *(const float4*)&As[kk][ty*4];
            float4 b4 = *(const float4*)&Bs[kk][tx*4];
            float a[4] = {a4.x, a4.y, a4.z, a4.w};
            float b[4] = {b4.x, b4.y, b4.z, b4.w};
            #pragma unroll
            for (int i = 0; i < 4; i++)
                #pragma unroll
                for (int j = 0; j < 4; j++)
                    acc[i][j] += a[i] * b[j];
        }
        __syncthreads();
    }
    #pragma unroll
    for (int i = 0; i < 4; i++) {
        const int m = m0 + ty*4 + i;
        #pragma unroll
        for (int j = 0; j < 4; j++) {
            const int n = n0 + tx*4 + j;
            C[(size_t)m * N + n] = acc[i][j] + bias[n];
        }
    }
}

// ================= tensor-core flash attention (128 queries / block) ========
#define AQHI 0
#define AQLO 16384
#define ASTG 32768
#define AKHI 0
#define AKLO 8192
#define AVHI 16384
#define AVLO 24576
#define ATT_SMEM (1024 + 32768 + 2*32768)

__global__ __launch_bounds__(256) void mha_kernel(
    const bf16* __restrict__ Qhi, const bf16* __restrict__ Qlo,
    const bf16* __restrict__ Khi, const bf16* __restrict__ Klo,
    const bf16* __restrict__ Vhi, const bf16* __restrict__ Vlo,
    bf16* __restrict__ Ohi, bf16* __restrict__ Olo,
    int ntiles, int kb, int kh, int banded)
{
    extern __shared__ __align__(16) char smem[];
    const uint32_t sb = smem_u32(smem);
    const uint32_t mbq = sb, mb0 = sb + 8, mb1 = sb + 16;
    const uint32_t data = sb + 1024;

    const int tid = threadIdx.x;
    const int wid = tid >> 5, lane = tid & 31;
    const int b = blockIdx.z, h = blockIdx.y;
    const int q0 = blockIdx.x * 128;

    const int lr16 = lane & 15;
    const int lk8  = (lane >> 4) * 8;

    if (tid == 0) { mbar_init(mbq, 1); mbar_init(mb0, 1); mbar_init(mb1, 1); }
    __syncthreads();

    const size_t qblk  = (size_t)(b * HH + h) * 32 + (q0 >> 6);   // first of 2 blocks
    const size_t kvbase = (size_t)b * kb + (size_t)h * kh;

    auto issue_kv = [&](int s, int kt) {
        const uint32_t mb = s ? mb1 : mb0;
        mbar_expect(mb, 32768u);
        const uint32_t st = data + ASTG + s * 32768;
        bulk_g2s(st + AKHI, Khi + (kvbase + kt) * 4096, 8192, mb);
        bulk_g2s(st + AKLO, Klo + (kvbase + kt) * 4096, 8192, mb);
        bulk_g2s(st + AVHI, Vhi + (kvbase + kt) * 4096, 8192, mb);
        bulk_g2s(st + AVLO, Vlo + (kvbase + kt) * 4096, 8192, mb);
    };

    if (tid == 0) {
        mbar_expect(mbq, 32768u);
        bulk_g2s(data + AQHI, Qhi + qblk * 4096, 16384, mbq);   // 2 contiguous 64-row blocks
        bulk_g2s(data + AQLO, Qlo + qblk * 4096, 16384, mbq);
        issue_kv(0, 0);
    }

    mbar_wait(mbq, 0);
    // warp w owns q rows [w*16, w*16+16): tile = wid>>2, local row = (wid*16+lr16)&63
    const uint32_t qtile = (uint32_t)(wid >> 2) * 8192;
    uint32_t qh[4][4], ql[4][4];
    #pragma unroll
    for (int ks = 0; ks < 4; ks++) {
        int lrow = (wid * 16 + lr16) & 63;
        uint32_t off = qtile + sw64(lrow, ks * 16 + lk8) * 2;
        LDSM4(qh[ks][0], qh[ks][1], qh[ks][2], qh[ks][3], data + AQHI + off);
        LDSM4(ql[ks][0], ql[ks][1], ql[ks][2], ql[ks][3], data + AQLO + off);
    }

    float m0r = -1e30f, m1r = -1e30f, l0 = 0.f, l1 = 0.f;
    float oa[8][4];
    #pragma unroll
    for (int nt = 0; nt < 8; nt++)
        #pragma unroll
        for (int e = 0; e < 4; e++) oa[nt][e] = 0.f;

    const int gr = lane >> 2;
    const int gc2 = (lane & 3) * 2;
    const int qrow0 = q0 + wid * 16 + gr;
    const int qrow1 = qrow0 + 8;

    int ph0 = 0, ph1 = 0;
    for (int kt = 0; kt < ntiles; kt++) {
        const int s = kt & 1;
        if (kt + 1 < ntiles && tid == 0) issue_kv(s ^ 1, kt + 1);
        if (s == 0) { mbar_wait(mb0, ph0); ph0 ^= 1; }
        else        { mbar_wait(mb1, ph1); ph1 ^= 1; }

        const uint32_t base = data + ASTG + s * 32768;

        float sa[8][4];
        #pragma unroll
        for (int nt = 0; nt < 8; nt++)
            #pragma unroll
            for (int e = 0; e < 4; e++) sa[nt][e] = 0.f;

        #pragma unroll
        for (int p = 0; p < 4; p++) {
            #pragma unroll
            for (int ks = 0; ks < 4; ks++) {
                int row = p * 16 + lr16;
                uint32_t off = sw64(row, ks * 16 + lk8) * 2;
                uint32_t h0, h1, h2, h3, l0r, l1r, l2r, l3r;
                LDSM4(h0, h1, h2, h3, base + AKHI + off);
                LDSM4(l0r, l1r, l2r, l3r, base + AKLO + off);
                uint32_t bh0[2] = {h0, h2}, bh1[2] = {h1, h3};
                uint32_t bl0[2] = {l0r, l2r}, bl1[2] = {l1r, l3r};
                MMA16816(sa[2*p],   qh[ks], bh0);
                MMA16816(sa[2*p],   qh[ks], bl0);
                MMA16816(sa[2*p],   ql[ks], bh0);
                MMA16816(sa[2*p+1], qh[ks], bh1);
                MMA16816(sa[2*p+1], qh[ks], bl1);
                MMA16816(sa[2*p+1], ql[ks], bh1);
            }
        }

        #pragma unroll
        for (int nt = 0; nt < 8; nt++) {
            int col = kt * 64 + nt * 8 + gc2;
            #pragma unroll
            for (int e = 0; e < 4; e++) {
                float s2 = sa[nt][e] * 0.125f;
                if (banded) {
                    int r = (e < 2) ? qrow0 : qrow1;
                    int c = col + (e & 1);
                    int d = r - c;
                    if (d <= RR && d >= -RR) s2 += 1.0f;
                }
                sa[nt][e] = s2;
            }
        }

        float mx0 = -1e30f, mx1 = -1e30f;
        #pragma unroll
        for (int nt = 0; nt < 8; nt++) {
            mx0 = fmaxf(mx0, fmaxf(sa[nt][0], sa[nt][1]));
            mx1 = fmaxf(mx1, fmaxf(sa[nt][2], sa[nt][3]));
        }
        mx0 = fmaxf(mx0, __shfl_xor_sync(0xffffffffu, mx0, 1));
        mx0 = fmaxf(mx0, __shfl_xor_sync(0xffffffffu, mx0, 2));
        mx1 = fmaxf(mx1, __shfl_xor_sync(0xffffffffu, mx1, 1));
        mx1 = fmaxf(mx1, __shfl_xor_sync(0xffffffffu, mx1, 2));

        float nm0 = fmaxf(m0r, mx0), nm1 = fmaxf(m1r, mx1);
        float al0 = __expf(m0r - nm0), al1 = __expf(m1r - nm1);
        m0r = nm0; m1r = nm1;
        l0 *= al0; l1 *= al1;
        #pragma unroll
        for (int nt = 0; nt < 8; nt++) {
            oa[nt][0] *= al0; oa[nt][1] *= al0;
            oa[nt][2] *= al1; oa[nt][3] *= al1;
        }

        float ph_f[8][4], pl_f[8][4];
        #pragma unroll
        for (int nt = 0; nt < 8; nt++) {
            #pragma unroll
            for (int e = 0; e < 4; e++) {
                float p = __expf(sa[nt][e] - ((e < 2) ? nm0 : nm1));
                if (e < 2) l0 += p; else l1 += p;
                float hf = __bfloat162float(__float2bfloat16(p));
                ph_f[nt][e] = hf;
                pl_f[nt][e] = p - hf;
            }
        }

        uint32_t ph[4][4], pl[4][4];
        #pragma unroll
        for (int ks = 0; ks < 4; ks++) {
            int t0 = 2*ks, t1 = 2*ks + 1;
            ph[ks][0] = pack_bf16(ph_f[t0][0], ph_f[t0][1]);
            ph[ks][1] = pack_bf16(ph_f[t0][2], ph_f[t0][3]);
            ph[ks][2] = pack_bf16(ph_f[t1][0], ph_f[t1][1]);
            ph[ks][3] = pack_bf16(ph_f[t1][2], ph_f[t1][3]);
            pl[ks][0] = pack_bf16(pl_f[t0][0], pl_f[t0][1]);
            pl[ks][1] = pack_bf16(pl_f[t0][2], pl_f[t0][3]);
            pl[ks][2] = pack_bf16(pl_f[t1][0], pl_f[t1][1]);
            pl[ks][3] = pack_bf16(pl_f[t1][2], pl_f[t1][3]);
        }

        #pragma unroll
        for (int p = 0; p < 4; p++) {
            #pragma unroll
            for (int ks = 0; ks < 4; ks++) {
                int row = p * 16 + lr16;
                uint32_t off = sw64(row, ks * 16 + lk8) * 2;
                uint32_t h0, h1, h2, h3, v0, v1, v2, v3;
                LDSM4(h0, h1, h2, h3, base + AVHI + off);
                LDSM4(v0, v1, v2, v3, base + AVLO + off);
                uint32_t bh0[2] = {h0, h2}, bh1[2] = {h1, h3};
                uint32_t bl0[2] = {v0, v2}, bl1[2] = {v1, v3};
                MMA16816(oa[2*p],   ph[ks], bh0);
                MMA16816(oa[2*p],   pl[ks], bh0);
                MMA16816(oa[2*p],   ph[ks], bl0);
                MMA16816(oa[2*p+1], ph[ks], bh1);
                MMA16816(oa[2*p+1], pl[ks], bh1);
                MMA16816(oa[2*p+1], ph[ks], bl1);
            }
        }
        __syncthreads();
    }

    l0 += __shfl_xor_sync(0xffffffffu, l0, 1);
    l0 += __shfl_xor_sync(0xffffffffu, l0, 2);
    l1 += __shfl_xor_sync(0xffffffffu, l1, 1);
    l1 += __shfl_xor_sync(0xffffffffu, l1, 2);
    const float inv0 = 1.0f / l0, inv1 = 1.0f / l1;

    // write ctx in GEMM-A packed layout (N=768 -> 24 col-blocks)
    #pragma unroll
    for (int nt = 0; nt < 8; nt++) {
        int d = nt * 8 + gc2;
        int col = h * DHH + d;
        int R0 = b * SS + qrow0, R1 = b * SS + qrow1;
        size_t off0 = ((size_t)(R0 >> 6) * 24 + (col >> 5)) * 2048 + sw_elem(R0 & 63, col & 31);
        size_t off1 = ((size_t)(R1 >> 6) * 24 + (col >> 5)) * 2048 + sw_elem(R1 & 63, col & 31);
        float v0 = oa[nt][0] * inv0, v1 = oa[nt][1] * inv0;
        float v2 = oa[nt][2] * inv1, v3 = oa[nt][3] * inv1;
        bf16 h0 = __float2bfloat16(v0), h1 = __float2bfloat16(v1);
        bf16 h2 = __float2bfloat16(v2), h3 = __float2bfloat16(v3);
        *(__nv_bfloat162*)&Ohi[off0] = {h0, h1};
        *(__nv_bfloat162*)&Olo[off0] = {__float2bfloat16(v0 - __bfloat162float(h0)),
                                        __float2bfloat16(v1 - __bfloat162float(h1))};
        *(__nv_bfloat162*)&Ohi[off1] = {h2, h3};
        *(__nv_bfloat162*)&Olo[off1] = {__float2bfloat16(v2 - __bfloat162float(h2)),
                                        __float2bfloat16(v3 - __bfloat162float(h3))};
    }
}

// ---------------- layernorm (fp32 + optional packed split out) --------------
__global__ __launch_bounds__(256) void ln_kernel(
    const float* __restrict__ X, const float* __restrict__ g,
    const float* __restrict__ bta, float* __restrict__ Y,
    bf16* __restrict__ Yhi, bf16* __restrict__ Ylo)
{
    __shared__ float red[8];
    const int row = blockIdx.x, t = threadIdx.x;
    const float* x = X + (size_t)row * DD;

    float v0 = x[t], v1 = x[t + 256], v2 = x[t + 512];
    float s = v0 + v1 + v2;
    #pragma unroll
    for (int o = 16; o; o >>= 1) s += __shfl_xor_sync(0xffffffffu, s, o);
    if ((t & 31) == 0) red[t >> 5] = s;
    __syncthreads();
    float tot = 0.f;
    #pragma unroll
    for (int i = 0; i < 8; i++) tot += red[i];
    const float mean = tot * (1.0f / 768.0f);

    float d0 = v0 - mean, d1 = v1 - mean, d2 = v2 - mean;
    float s2 = d0*d0 + d1*d1 + d2*d2;
    __syncthreads();
    #pragma unroll
    for (int o = 16; o; o >>= 1) s2 += __shfl_xor_sync(0xffffffffu, s2, o);
    if ((t & 31) == 0) red[t >> 5] = s2;
    __syncthreads();
    float tot2 = 0.f;
    #pragma unroll
    for (int i = 0; i < 8; i++) tot2 += red[i];
    const float rstd = rsqrtf(tot2 * (1.0f / 768.0f) + 1e-12f);

    float* y = Y + (size_t)row * DD;
    #pragma unroll
    for (int c = 0; c < 3; c++) {
        int idx = t + 256 * c;
        float dv = (c == 0) ? d0 : (c == 1) ? d1 : d2;
        float r = dv * rstd * g[idx] + bta[idx];
        y[idx] = r;
        if (Yhi) {
            size_t off = ((size_t)(row >> 6) * 24 + (idx >> 5)) * 2048
                         + sw_elem(row & 63, idx & 31);
            bf16 hh = __float2bfloat16(r);
            Yhi[off] = hh;
            Ylo[off] = __float2bfloat16(r - __bfloat162float(hh));
        }
    }
}

// ---------------- launch ----------------------------------------------------
extern "C" void kernel_launch(void* const* d_in, const int* in_sizes, int n_in,
                              void* d_out, int out_size)
{
    const float* hidden  = (const float*)d_in[0];
    const float* tag_emb = (const float*)d_in[1];
    const float* sa_wq = (const float*)d_in[2],  *sa_bq = (const float*)d_in[3];
    const float* sa_wk = (const float*)d_in[4],  *sa_bk = (const float*)d_in[5];
    const float* sa_wv = (const float*)d_in[6],  *sa_bv = (const float*)d_in[7];
    const float* sa_wo = (const float*)d_in[8],  *sa_bo = (const float*)d_in[9];
    const float* sa_lg = (const float*)d_in[10], *sa_lb = (const float*)d_in[11];
    const float* ca_wq = (const float*)d_in[12], *ca_bq = (const float*)d_in[13];
    const float* ca_wk = (const float*)d_in[14], *ca_bk = (const float*)d_in[15];
    const float* ca_wv = (const float*)d_in[16], *ca_bv = (const float*)d_in[17];
    const float* ca_wo = (const float*)d_in[18], *ca_bo = (const float*)d_in[19];
    const float* ca_lg = (const float*)d_in[20], *ca_lb = (const float*)d_in[21];
    const float* ff_w1 = (const float*)d_in[22], *ff_b1 = (const float*)d_in[23];
    const float* ff_w2 = (const float*)d_in[24], *ff_b2 = (const float*)d_in[25];
    const float* ff_lg = (const float*)d_in[26], *ff_lb = (const float*)d_in[27];
    float* out = (float*)d_out;

    float *tmp, *x1, *x2, *ck, *cv, *bqkv;
    bf16 *whi, *wlo, *qhi, *qlo, *khi, *klo, *vthi, *vtlo, *ctxhi, *ctxlo;
    bf16 *x1hi, *x1lo, *x2hi, *x2lo, *hhi, *hlo, *ihi, *ilo;
    bf16 *ckhi, *cklo, *cvthi, *cvtlo;
    cudaGetSymbolAddress((void**)&tmp,  g_tmp);
    cudaGetSymbolAddress((void**)&x1,   g_x1);
    cudaGetSymbolAddress((void**)&x2,   g_x2);
    cudaGetSymbolAddress((void**)&ck,   g_ck);
    cudaGetSymbolAddress((void**)&cv,   g_cv);
    cudaGetSymbolAddress((void**)&bqkv, g_bqkv);
    cudaGetSymbolAddress((void**)&whi,  g_whi);
    cudaGetSymbolAddress((void**)&wlo,  g_wlo);
    cudaGetSymbolAddress((void**)&qhi,  g_qhi);
    cudaGetSymbolAddress((void**)&qlo,  g_qlo);
    cudaGetSymbolAddress((void**)&khi,  g_khi);
    cudaGetSymbolAddress((void**)&klo,  g_klo);
    cudaGetSymbolAddress((void**)&vthi, g_vthi);
    cudaGetSymbolAddress((void**)&vtlo, g_vtlo);
    cudaGetSymbolAddress((void**)&ctxhi, g_ctxhi);
    cudaGetSymbolAddress((void**)&ctxlo, g_ctxlo);
    cudaGetSymbolAddress((void**)&x1hi, g_x1hi);
    cudaGetSymbolAddress((void**)&x1lo, g_x1lo);
    cudaGetSymbolAddress((void**)&x2hi, g_x2hi);
    cudaGetSymbolAddress((void**)&x2lo, g_x2lo);
    cudaGetSymbolAddress((void**)&hhi,  g_hhi);
    cudaGetSymbolAddress((void**)&hlo,  g_hlo);
    cudaGetSymbolAddress((void**)&ihi,  g_ihi);
    cudaGetSymbolAddress((void**)&ilo,  g_ilo);
    cudaGetSymbolAddress((void**)&ckhi, g_ckhi);
    cudaGetSymbolAddress((void**)&cklo, g_cklo);
    cudaGetSymbolAddress((void**)&cvthi, g_cvthi);
    cudaGetSymbolAddress((void**)&cvtlo, g_cvtlo);

    cudaFuncSetAttribute(mma_gemm<0,3>, cudaFuncAttributeMaxDynamicSharedMemorySize, GEMM_SMEM);
    cudaFuncSetAttribute(mma_gemm<0,1>, cudaFuncAttributeMaxDynamicSharedMemorySize, GEMM_SMEM);
    cudaFuncSetAttribute(mma_gemm<1,0>, cudaFuncAttributeMaxDynamicSharedMemorySize, GEMM_SMEM);
    cudaFuncSetAttribute(mma_gemm<2,2>, cudaFuncAttributeMaxDynamicSharedMemorySize, GEMM_SMEM);
    cudaFuncSetAttribute(mha_kernel,    cudaFuncAttributeMaxDynamicSharedMemorySize, ATT_SMEM);

    const size_t o_sawo = 3*(size_t)DxD, o_cawq = 4*(size_t)DxD, o_cawo = 5*(size_t)DxD;
    const size_t o_ff1  = 6*(size_t)DxD;
    const size_t o_ff2  = 6*(size_t)DxD + (size_t)768*3072;

    const dim3 wsB(32, 8);
    wsplit8_kernel<<<dim3(96, 24, 8), wsB>>>(sa_wq, sa_wk, sa_wv, sa_wo, ca_wq, ca_wo,
                                             ff_w1, ff_w2, whi, wlo);
    bcat_kernel<<<9, 256>>>(sa_bq, sa_bk, sa_bv, bqkv);

    const dim3 thr(256);
    const dim3 gQKV(2304 / GBN, MROWS / GBM);   // (18, 64)
    const dim3 gMMA_D (DD / GBN, MROWS / GBM);  // (6, 64)
    const dim3 gMMA_F1(FF / GBN, MROWS / GBM);  // (24, 64)
    const dim3 gCK(DD / BN, TT / BM);
    const dim3 attn_grid(SS / 128, HH, BB);     // 128 queries per block
    const int nD4 = MROWS * DD / 4;
    const size_t smb = GEMM_SMEM;

    // ---- self attention ----
    asplit_kernel<<<(nD4 + 255)/256, 256>>>(hidden, hhi, hlo, nD4);
    mma_gemm<0,3><<<gQKV, thr, smb>>>(hhi, hlo, whi, wlo, bqkv, nullptr,
                                      nullptr, qhi, qlo, khi, klo, vthi, vtlo, 2304, DD);
    mha_kernel<<<attn_grid, 256, ATT_SMEM>>>(qhi, qlo, khi, klo, vthi, vtlo, ctxhi, ctxlo,
                                             SS/64, HH*32, 32, 1);
    mma_gemm<1,0><<<gMMA_D, thr, smb>>>(ctxhi, ctxlo, whi+o_sawo, wlo+o_sawo, sa_bo, hidden,
                                        tmp, nullptr, nullptr, nullptr, nullptr, nullptr, nullptr, DD, DD);
    ln_kernel<<<MROWS, thr>>>(tmp, sa_lg, sa_lb, x1, x1hi, x1lo);

    // ---- cross attention ----
    mma_gemm<0,1><<<gMMA_D, thr, smb>>>(x1hi, x1lo, whi+o_cawq, wlo+o_cawq, ca_bq, nullptr,
                                        nullptr, qhi, qlo, nullptr, nullptr, nullptr, nullptr, DD, DD);
    gemm_kernel<<<gCK, thr>>>(tag_emb, ca_wk, ca_bk, ck, TT, DD, DD);
    gemm_kernel<<<gCK, thr>>>(tag_emb, ca_wv, ca_bv, cv, TT, DD, DD);
    cpack_kernel<<<HH, 256>>>(ck, cv, ckhi, cklo, cvthi, cvtlo);
    mha_kernel<<<attn_grid, 256, ATT_SMEM>>>(qhi, qlo, ckhi, cklo, cvthi, cvtlo, ctxhi, ctxlo,
                                             1, 0, 1, 0);
    mma_gemm<1,0><<<gMMA_D, thr, smb>>>(ctxhi, ctxlo, whi+o_cawo, wlo+o_cawo, ca_bo, x1,
                                        tmp, nullptr, nullptr, nullptr, nullptr, nullptr, nullptr, DD, DD);
    ln_kernel<<<MROWS, thr>>>(tmp, ca_lg, ca_lb, x2, x2hi, x2lo);

    // ---- FFN ----
    mma_gemm<2,2><<<gMMA_F1, thr, smb>>>(x2hi, x2lo, whi+o_ff1, wlo+o_ff1, ff_b1, nullptr,
                                         nullptr, ihi, ilo, nullptr, nullptr, nullptr, nullptr, FF, DD);
    mma_gemm<1,0><<<gMMA_D, thr, smb>>>(ihi, ilo, whi+o_ff2, wlo+o_ff2, ff_b2, x2,
                                        tmp, nullptr, nullptr, nullptr, nullptr, nullptr, nullptr, DD, FF);
    ln_kernel<<<MROWS, thr>>>(tmp, ff_lg, ff_lb, out, nullptr, nullptr);
}

// round 12
// speedup vs baseline: 1.1872x; 1.0065x over previous
#include <cuda_runtime.h>
#include <cuda_bf16.h>
#include <math.h>
#include <stdint.h>

#define BB 2
#define SS 2048
#define DD 768
#define HH 12
#define DHH 64
#define TT 64
#define RR 50
#define FF 3072
#define MROWS (BB*SS)   // 4096

typedef __nv_bfloat16 bf16;

// ---------------- scratch ---------------------------------------------------
__device__ float g_tmp [MROWS*DD];
__device__ float g_x1  [MROWS*DD];
__device__ float g_x2  [MROWS*DD];
__device__ float g_bqkv[3*DD];

// attention-packed buffers (64x64 sw64 blocks)
__device__ __align__(128) bf16 g_qhi[MROWS*DD];
__device__ __align__(128) bf16 g_qlo[MROWS*DD];
__device__ __align__(128) bf16 g_khi[MROWS*DD];
__device__ __align__(128) bf16 g_klo[MROWS*DD];
__device__ __align__(128) bf16 g_vthi[BB*HH*DHH*SS];
__device__ __align__(128) bf16 g_vtlo[BB*HH*DHH*SS];
__device__ __align__(128) bf16 g_ckhi[HH*TT*DHH];
__device__ __align__(128) bf16 g_cklo[HH*TT*DHH];
__device__ __align__(128) bf16 g_cvthi[HH*DHH*TT];
__device__ __align__(128) bf16 g_cvtlo[HH*DHH*TT];

// GEMM operand buffers (tile-packed; sw_elem blocks)
__device__ __align__(128) bf16 g_ctxhi[MROWS*DD];
__device__ __align__(128) bf16 g_ctxlo[MROWS*DD];
__device__ __align__(128) bf16 g_x1hi[MROWS*DD];
__device__ __align__(128) bf16 g_x1lo[MROWS*DD];
__device__ __align__(128) bf16 g_x2hi[MROWS*DD];
__device__ __align__(128) bf16 g_x2lo[MROWS*DD];
__device__ __align__(128) bf16 g_hhi[MROWS*DD];
__device__ __align__(128) bf16 g_hlo[MROWS*DD];
__device__ __align__(128) bf16 g_ihi[MROWS*FF];
__device__ __align__(128) bf16 g_ilo[MROWS*FF];

#define DxD (768*768)
#define WSPLIT_TOTAL (6*DxD + 2*768*3072)
__device__ __align__(128) bf16 g_whi[WSPLIT_TOTAL];
__device__ __align__(128) bf16 g_wlo[WSPLIT_TOTAL];

// ================= helpers ==================================================
__device__ __forceinline__ uint32_t smem_u32(const void* p) {
    return (uint32_t)__cvta_generic_to_shared(p);
}
__device__ __forceinline__ uint32_t pack_bf16(float a, float b) {
    __nv_bfloat162 t = __floats2bfloat162_rn(a, b);
    return *(uint32_t*)&t;
}
// swizzled element offset inside a [rows][32] bf16 tile (GEMM A/B blocks)
__device__ __forceinline__ uint32_t sw_elem(int row, int k) {
    return (uint32_t)(row * 32 + ((((k >> 3) ^ ((row >> 1) & 3))) << 3) + (k & 7));
}
// attention 64x64 tile swizzled element offset
__device__ __forceinline__ uint32_t sw64(int row, int k) {
    return (uint32_t)(row * 64 + ((((k >> 3) ^ (row & 7))) << 3) + (k & 7));
}

#define LDSM4(r0, r1, r2, r3, addr) \
    asm volatile("ldmatrix.sync.aligned.m8n8.x4.shared.b16 {%0,%1,%2,%3}, [%4];" \
                 : "=r"(r0), "=r"(r1), "=r"(r2), "=r"(r3) : "r"(addr))
#define MMA16816(c, a, b) \
    asm volatile("mma.sync.aligned.m16n8k16.row.col.f32.bf16.bf16.f32 " \
                 "{%0,%1,%2,%3}, {%4,%5,%6,%7}, {%8,%9}, {%0,%1,%2,%3};" \
                 : "+f"(c[0]), "+f"(c[1]), "+f"(c[2]), "+f"(c[3]) \
                 : "r"(a[0]), "r"(a[1]), "r"(a[2]), "r"(a[3]), "r"(b[0]), "r"(b[1]))

__device__ __forceinline__ void mbar_init(uint32_t a, uint32_t cnt) {
    asm volatile("mbarrier.init.shared.b64 [%0], %1;" :: "r"(a), "r"(cnt) : "memory");
}
__device__ __forceinline__ void mbar_expect(uint32_t a, uint32_t bytes) {
    asm volatile("mbarrier.arrive.expect_tx.shared.b64 _, [%0], %1;"
                 :: "r"(a), "r"(bytes) : "memory");
}
__device__ __forceinline__ void mbar_wait(uint32_t a, uint32_t parity) {
    asm volatile(
        "{\n\t.reg .pred P;\n\t"
        "W%=:\n\t"
        "mbarrier.try_wait.parity.acquire.cta.shared::cta.b64 P, [%0], %1, 0x989680;\n\t"
        "@!P bra W%=;\n\t}"
        :: "r"(a), "r"(parity) : "memory");
}
__device__ __forceinline__ void bulk_g2s(uint32_t dst, const void* src,
                                         uint32_t bytes, uint32_t mbar) {
    asm volatile(
        "cp.async.bulk.shared::cta.global.mbarrier::complete_tx::bytes [%0], [%1], %2, [%3];"
        :: "r"(dst), "l"(src), "r"(bytes), "r"(mbar) : "memory");
}

// ================= fused prep: 8 weight splits + activation split + bcat ====
// grid (96, 24, 9), block (32, 8).
__global__ __launch_bounds__(256) void prep_kernel(
    const float* __restrict__ w0, const float* __restrict__ w1,
    const float* __restrict__ w2, const float* __restrict__ w3,
    const float* __restrict__ w4, const float* __restrict__ w5,
    const float* __restrict__ w6, const float* __restrict__ w7,
    bf16* __restrict__ hiB, bf16* __restrict__ loB,
    const float* __restrict__ X, bf16* __restrict__ xhi, bf16* __restrict__ xlo,
    const float* __restrict__ bq, const float* __restrict__ bk,
    const float* __restrict__ bv, float* __restrict__ bqkv)
{
    const int z = blockIdx.z;
    const int tid = threadIdx.y * 32 + threadIdx.x;

    if (z == 8) {
        // bias concat + activation split (grid-stride)
        int gid = (blockIdx.y * 96 + blockIdx.x) * 256 + tid;
        if (gid < 768) bqkv[gid] = bq[gid];
        else if (gid < 1536) bqkv[gid] = bk[gid - 768];
        else if (gid < 2304) bqkv[gid] = bv[gid - 1536];
        const int n4 = MROWS * DD / 4;
        for (int i = gid; i < n4; i += 96 * 24 * 256) {
            float4 v = ((const float4*)X)[i];
            int r = (i * 4) / 768, c = (i * 4) % 768;
            size_t off = ((size_t)(r >> 6) * 24 + (c >> 5)) * 2048 + sw_elem(r & 63, c & 31);
            bf16 h0 = __float2bfloat16(v.x), h1 = __float2bfloat16(v.y);
            bf16 h2 = __float2bfloat16(v.z), h3 = __float2bfloat16(v.w);
            *(__nv_bfloat162*)&xhi[off]     = {h0, h1};
            *(__nv_bfloat162*)&xhi[off + 2] = {h2, h3};
            *(__nv_bfloat162*)&xlo[off]     = {__float2bfloat16(v.x - __bfloat162float(h0)),
                                               __float2bfloat16(v.y - __bfloat162float(h1))};
            *(__nv_bfloat162*)&xlo[off + 2] = {__float2bfloat16(v.z - __bfloat162float(h2)),
                                               __float2bfloat16(v.w - __bfloat162float(h3))};
        }
        return;
    }

    __shared__ float tile[32][33];
    const float* W;
    int K, N, n0, k0;
    size_t ofs;
    if (z < 6) {
        if (blockIdx.x >= 24) return;
        K = 768; N = 768;
        k0 = blockIdx.x * 32; n0 = blockIdx.y * 32;
        const float* ws[6] = {w0, w1, w2, w3, w4, w5};
        W = ws[z];
        ofs = (size_t)z * DxD;
    } else if (z == 6) {
        K = 768; N = 3072;
        n0 = blockIdx.x * 32; k0 = blockIdx.y * 32;
        W = w6;
        ofs = 6 * (size_t)DxD;
    } else {
        K = 3072; N = 768;
        k0 = blockIdx.x * 32; n0 = blockIdx.y * 32;
        W = w7;
        ofs = 6 * (size_t)DxD + (size_t)768 * 3072;
    }
    bf16* hiT = hiB + ofs;
    bf16* loT = loB + ofs;

    const int tx = threadIdx.x, ty = threadIdx.y;
    #pragma unroll
    for (int i = 0; i < 4; i++)
        tile[ty + 8*i][tx] = W[(size_t)(k0 + ty + 8*i) * N + n0 + tx];
    __syncthreads();
    #pragma unroll
    for (int i = 0; i < 4; i++) {
        float v = tile[tx][ty + 8*i];
        int n = n0 + ty + 8*i, k = k0 + tx;
        bf16 h = __float2bfloat16(v);
        size_t o = ((size_t)(n >> 7) * (K >> 5) + (k >> 5)) * 4096 + sw_elem(n & 127, k & 31);
        hiT[o] = h;
        loT[o] = __float2bfloat16(v - __bfloat162float(h));
    }
}

// ================= bf16-split tensor-core GEMM (3-stage, 3 CTA/SM) =========
#define GBM 64
#define GBN 128
#define STAGE_BYTES 24576
#define OFF_AHI 0
#define OFF_ALO 4096
#define OFF_BHI 8192
#define OFF_BLO 16384
#define GEMM_SMEM (1024 + 3*STAGE_BYTES)

// MODE: 0 bias, 1 bias+res, 2 bias+gelu
// OSPLIT: 0 fp32 C | 1 attention-QK packed | 2 GEMM-A packed | 3 fused QKV route
template<int MODE, int OSPLIT>
__global__ __launch_bounds__(256, 3) void mma_gemm(
    const bf16* __restrict__ Apk_hi, const bf16* __restrict__ Apk_lo,
    const bf16* __restrict__ Bpk_hi, const bf16* __restrict__ Bpk_lo,
    const float* __restrict__ bias, const float* __restrict__ Rz,
    float* __restrict__ C, bf16* __restrict__ Chi, bf16* __restrict__ Clo,
    bf16* __restrict__ C2hi, bf16* __restrict__ C2lo,
    bf16* __restrict__ C3hi, bf16* __restrict__ C3lo,
    int N, int K)
{
    extern __shared__ __align__(16) char smem[];
    const uint32_t sb = smem_u32(smem);
    const uint32_t mb0 = sb, mb1 = sb + 8, mb2 = sb + 16;
    const uint32_t data = sb + 1024;

    const int tid = threadIdx.x;
    const int wid = tid >> 5, lane = tid & 31;
    const int warp_m = wid & 1, warp_n = wid >> 1;
    const int m0 = blockIdx.y * GBM, n0 = blockIdx.x * GBN;
    const int KT = K >> 5;

    const bf16* Ahi_t = Apk_hi + (size_t)(m0 >> 6) * KT * 2048;
    const bf16* Alo_t = Apk_lo + (size_t)(m0 >> 6) * KT * 2048;
    const bf16* Bhi_t = Bpk_hi + (size_t)(n0 >> 7) * KT * 4096;
    const bf16* Blo_t = Bpk_lo + (size_t)(n0 >> 7) * KT * 4096;

    if (tid == 0) { mbar_init(mb0, 1); mbar_init(mb1, 1); mbar_init(mb2, 1); }
    __syncthreads();

    auto issue = [&](int s, int kt) {
        const uint32_t mb = sb + s * 8;
        mbar_expect(mb, (uint32_t)STAGE_BYTES);
        const uint32_t b = data + s * STAGE_BYTES;
        bulk_g2s(b + OFF_AHI, Ahi_t + (size_t)kt * 2048, 4096, mb);
        bulk_g2s(b + OFF_ALO, Alo_t + (size_t)kt * 2048, 4096, mb);
        bulk_g2s(b + OFF_BHI, Bhi_t + (size_t)kt * 4096, 8192, mb);
        bulk_g2s(b + OFF_BLO, Blo_t + (size_t)kt * 4096, 8192, mb);
    };
    if (tid == 0) {
        issue(0, 0);
        if (KT > 1) issue(1, 1);
    }

    float acc[2][4][4];
    #pragma unroll
    for (int i = 0; i < 2; i++)
        #pragma unroll
        for (int j = 0; j < 4; j++)
            #pragma unroll
            for (int p = 0; p < 4; p++) acc[i][j][p] = 0.f;

    const int lr16 = lane & 15;
    const int lk8  = (lane >> 4) * 8;
    int p0 = 0, p1 = 0, p2 = 0;
    int s = 0;

    for (int kt = 0; kt < KT; kt++) {
        if (s == 0) { mbar_wait(mb0, p0); p0 ^= 1; }
        else if (s == 1) { mbar_wait(mb1, p1); p1 ^= 1; }
        else { mbar_wait(mb2, p2); p2 ^= 1; }

        const uint32_t base = data + s * STAGE_BYTES;
        #pragma unroll
        for (int k16 = 0; k16 < 32; k16 += 16) {
            uint32_t ah[2][4], al[2][4];
            #pragma unroll
            for (int mt = 0; mt < 2; mt++) {
                int row = warp_m * 32 + mt * 16 + lr16;
                uint32_t off = sw_elem(row, k16 + lk8) * 2;
                LDSM4(ah[mt][0], ah[mt][1], ah[mt][2], ah[mt][3], base + OFF_AHI + off);
                LDSM4(al[mt][0], al[mt][1], al[mt][2], al[mt][3], base + OFF_ALO + off);
            }
            uint32_t bh[4][2], bl[4][2];
            #pragma unroll
            for (int p = 0; p < 2; p++) {
                int row = warp_n * 32 + p * 16 + lr16;
                uint32_t off = sw_elem(row, k16 + lk8) * 2;
                uint32_t q0, q1, q2, q3;
                LDSM4(q0, q1, q2, q3, base + OFF_BHI + off);
                bh[2*p][0] = q0; bh[2*p][1] = q2; bh[2*p+1][0] = q1; bh[2*p+1][1] = q3;
                LDSM4(q0, q1, q2, q3, base + OFF_BLO + off);
                bl[2*p][0] = q0; bl[2*p][1] = q2; bl[2*p+1][0] = q1; bl[2*p+1][1] = q3;
            }
            #pragma unroll
            for (int mt = 0; mt < 2; mt++)
                #pragma unroll
                for (int nt = 0; nt < 4; nt++) {
                    MMA16816(acc[mt][nt], ah[mt], bh[nt]);
                    MMA16816(acc[mt][nt], ah[mt], bl[nt]);
                    MMA16816(acc[mt][nt], al[mt], bh[nt]);
                }
        }
        __syncthreads();
        if (tid == 0 && kt + 2 < KT) issue((kt + 2) % 3, kt + 2);
        s = (s + 1 == 3) ? 0 : s + 1;
    }

    #pragma unroll
    for (int mt = 0; mt < 2; mt++) {
        #pragma unroll
        for (int nt = 0; nt < 4; nt++) {
            int r0 = m0 + warp_m * 32 + mt * 16 + (lane >> 2);
            int cc = n0 + warp_n * 32 + nt * 8 + 2 * (lane & 3);
            float b0 = bias[cc], b1 = bias[cc + 1];
            #pragma unroll
            for (int hh = 0; hh < 2; hh++) {
                int r = r0 + 8 * hh;
                float v0 = acc[mt][nt][2*hh]     + b0;
                float v1 = acc[mt][nt][2*hh + 1] + b1;
                if (MODE == 1) {
                    const float* rp = Rz + (size_t)r * N + cc;
                    v0 += rp[0]; v1 += rp[1];
                }
                if (MODE == 2) {
                    v0 = 0.5f * v0 * (1.0f + erff(v0 * 0.70710678118654752f));
                    v1 = 0.5f * v1 * (1.0f + erff(v1 * 0.70710678118654752f));
                }
                if (OSPLIT == 0) {
                    *(float2*)&C[(size_t)r * N + cc] = make_float2(v0, v1);
                } else {
                    bf16 h0 = __float2bfloat16(v0), h1 = __float2bfloat16(v1);
                    __nv_bfloat162 hv = {h0, h1};
                    bf16 l0b = __float2bfloat16(v0 - __bfloat162float(h0));
                    bf16 l1b = __float2bfloat16(v1 - __bfloat162float(h1));
                    __nv_bfloat162 lv = {l0b, l1b};
                    if (OSPLIT == 1) {
                        int bb = r >> 11, s2 = r & 2047;
                        int h2 = cc >> 6, d = cc & 63;
                        size_t off = ((size_t)(bb * HH + h2) * 32 + (s2 >> 6)) * 4096
                                     + sw64(s2 & 63, d);
                        *(__nv_bfloat162*)&Chi[off] = hv;
                        *(__nv_bfloat162*)&Clo[off] = lv;
                    } else if (OSPLIT == 2) {
                        size_t off = ((size_t)(r >> 6) * (N >> 5) + (cc >> 5)) * 2048
                                     + sw_elem(r & 63, cc & 31);
                        *(__nv_bfloat162*)&Chi[off] = hv;
                        *(__nv_bfloat162*)&Clo[off] = lv;
                    } else {
                        int j = (cc >= 1536) ? 2 : ((cc >= 768) ? 1 : 0);
                        int local = cc - j * 768;
                        int bb = r >> 11, s2 = r & 2047;
                        int h2 = local >> 6, d = local & 63;
                        size_t blk = ((size_t)(bb * HH + h2) * 32 + (s2 >> 6)) * 4096;
                        if (j == 0) {
                            size_t off = blk + sw64(s2 & 63, d);
                            *(__nv_bfloat162*)&Chi[off] = hv;
                            *(__nv_bfloat162*)&Clo[off] = lv;
                        } else if (j == 1) {
                            size_t off = blk + sw64(s2 & 63, d);
                            *(__nv_bfloat162*)&C2hi[off] = hv;
                            *(__nv_bfloat162*)&C2lo[off] = lv;
                        } else {
                            size_t off0 = blk + sw64(d,     s2 & 63);
                            size_t off1 = blk + sw64(d + 1, s2 & 63);
                            C3hi[off0] = h0; C3lo[off0] = l0b;
                            C3hi[off1] = h1; C3lo[off1] = l1b;
                        }
                    }
                }
            }
        }
    }
}

// ---------------- fp32 SIMT tag GEMM with fused attention-pack epilogue -----
// C = tag_emb @ W + b; TRANS=0 -> K layout sw64(s,d), TRANS=1 -> V layout sw64(d,s)
#define BM 64
#define BN 64
#define BK 16
template<int TRANS>
__global__ __launch_bounds__(256) void tag_gemm(
    const float* __restrict__ A, const float* __restrict__ W,
    const float* __restrict__ bias, bf16* __restrict__ Phi, bf16* __restrict__ Plo,
    int M, int N, int K)
{
    __shared__ float As[BK][68];
    __shared__ float Bs[BK][BN];
    const int tid = threadIdx.x;
    const int tx = tid & 15, ty = tid >> 4;
    const int m0 = blockIdx.y * BM, n0 = blockIdx.x * BN;
    float acc[4][4] = {};
    for (int k0 = 0; k0 < K; k0 += BK) {
        {
            const int r = tid >> 4, c = tid & 15;
            #pragma unroll
            for (int i = 0; i < 4; i++)
                As[c][r + 16*i] = A[(size_t)(m0 + r + 16*i) * K + k0 + c];
        }
        {
            const int r = tid >> 6, c = tid & 63;
            #pragma unroll
            for (int i = 0; i < 4; i++)
                Bs[r + 4*i][c] = W[(size_t)(k0 + r + 4*i) * N + n0 + c];
        }
        __syncthreads();
        #pragma unroll
        for (int kk = 0; kk < BK; kk++) {
            float4 a4 = *(const float4*)&As[kk][ty*4];
            float4 b4 = *(const float4*)&Bs[kk][tx*4];
            float a[4] = {a4.x, a4.y, a4.z, a4.w};
            float b[4] = {b4.x, b4.y, b4.z, b4.w};
            #pragma unroll
            for (int i = 0; i < 4; i++)
                #pragma unroll
                for (int j = 0; j < 4; j++)
                    acc[i][j] += a[i] * b[j];
        }
        __syncthreads();
    }
    #pragma unroll
    for (int i = 0; i < 4; i++) {
        const int m = m0 + ty*4 + i;      // sequence position s (0..63)
        #pragma unroll
        for (int j = 0; j < 4; j++) {
            const int n = n0 + tx*4 + j;
            float vv = acc[i][j] + bias[n];
            int h = n >> 6, d = n & 63;
            bf16 hb = __float2bfloat16(vv);
            size_t off = (size_t)h * 4096 + (TRANS ? sw64(d, m) : sw64(m, d));
            Phi[off] = hb;
            Plo[off] = __float2bfloat16(vv - __bfloat162float(hb));
        }
    }
}

// ================= tensor-core flash attention (128 queries / block) ========
#define AQHI 0
#define AQLO 16384
#define ASTG 32768
#define AKHI 0
#define AKLO 8192
#define AVHI 16384
#define AVLO 24576
#define ATT_SMEM (1024 + 32768 + 2*32768)

__global__ __launch_bounds__(256) void mha_kernel(
    const bf16* __restrict__ Qhi, const bf16* __restrict__ Qlo,
    const bf16* __restrict__ Khi, const bf16* __restrict__ Klo,
    const bf16* __restrict__ Vhi, const bf16* __restrict__ Vlo,
    bf16* __restrict__ Ohi, bf16* __restrict__ Olo,
    int ntiles, int kb, int kh, int banded)
{
    extern __shared__ __align__(16) char smem[];
    const uint32_t sb = smem_u32(smem);
    const uint32_t mbq = sb, mb0 = sb + 8, mb1 = sb + 16;
    const uint32_t data = sb + 1024;

    const int tid = threadIdx.x;
    const int wid = tid >> 5, lane = tid & 31;
    const int b = blockIdx.z, h = blockIdx.y;
    const int q0 = blockIdx.x * 128;

    const int lr16 = lane & 15;
    const int lk8  = (lane >> 4) * 8;

    if (tid == 0) { mbar_init(mbq, 1); mbar_init(mb0, 1); mbar_init(mb1, 1); }
    __syncthreads();

    const size_t qblk  = (size_t)(b * HH + h) * 32 + (q0 >> 6);
    const size_t kvbase = (size_t)b * kb + (size_t)h * kh;

    auto issue_kv = [&](int s, int kt) {
        const uint32_t mb = s ? mb1 : mb0;
        mbar_expect(mb, 32768u);
        const uint32_t st = data + ASTG + s * 32768;
        bulk_g2s(st + AKHI, Khi + (kvbase + kt) * 4096, 8192, mb);
        bulk_g2s(st + AKLO, Klo + (kvbase + kt) * 4096, 8192, mb);
        bulk_g2s(st + AVHI, Vhi + (kvbase + kt) * 4096, 8192, mb);
        bulk_g2s(st + AVLO, Vlo + (kvbase + kt) * 4096, 8192, mb);
    };

    if (tid == 0) {
        mbar_expect(mbq, 32768u);
        bulk_g2s(data + AQHI, Qhi + qblk * 4096, 16384, mbq);
        bulk_g2s(data + AQLO, Qlo + qblk * 4096, 16384, mbq);
        issue_kv(0, 0);
    }

    mbar_wait(mbq, 0);
    const uint32_t qtile = (uint32_t)(wid >> 2) * 8192;
    uint32_t qh[4][4], ql[4][4];
    #pragma unroll
    for (int ks = 0; ks < 4; ks++) {
        int lrow = (wid * 16 + lr16) & 63;
        uint32_t off = qtile + sw64(lrow, ks * 16 + lk8) * 2;
        LDSM4(qh[ks][0], qh[ks][1], qh[ks][2], qh[ks][3], data + AQHI + off);
        LDSM4(ql[ks][0], ql[ks][1], ql[ks][2], ql[ks][3], data + AQLO + off);
    }

    float m0r = -1e30f, m1r = -1e30f, l0 = 0.f, l1 = 0.f;
    float oa[8][4];
    #pragma unroll
    for (int nt = 0; nt < 8; nt++)
        #pragma unroll
        for (int e = 0; e < 4; e++) oa[nt][e] = 0.f;

    const int gr = lane >> 2;
    const int gc2 = (lane & 3) * 2;
    const int qrow0 = q0 + wid * 16 + gr;
    const int qrow1 = qrow0 + 8;

    int ph0 = 0, ph1 = 0;
    for (int kt = 0; kt < ntiles; kt++) {
        const int s = kt & 1;
        if (kt + 1 < ntiles && tid == 0) issue_kv(s ^ 1, kt + 1);
        if (s == 0) { mbar_wait(mb0, ph0); ph0 ^= 1; }
        else        { mbar_wait(mb1, ph1); ph1 ^= 1; }

        const uint32_t base = data + ASTG + s * 32768;

        float sa[8][4];
        #pragma unroll
        for (int nt = 0; nt < 8; nt++)
            #pragma unroll
            for (int e = 0; e < 4; e++) sa[nt][e] = 0.f;

        #pragma unroll
        for (int p = 0; p < 4; p++) {
            #pragma unroll
            for (int ks = 0; ks < 4; ks++) {
                int row = p * 16 + lr16;
                uint32_t off = sw64(row, ks * 16 + lk8) * 2;
                uint32_t h0, h1, h2, h3, l0r, l1r, l2r, l3r;
                LDSM4(h0, h1, h2, h3, base + AKHI + off);
                LDSM4(l0r, l1r, l2r, l3r, base + AKLO + off);
                uint32_t bh0[2] = {h0, h2}, bh1[2] = {h1, h3};
                uint32_t bl0[2] = {l0r, l2r}, bl1[2] = {l1r, l3r};
                MMA16816(sa[2*p],   qh[ks], bh0);
                MMA16816(sa[2*p],   qh[ks], bl0);
                MMA16816(sa[2*p],   ql[ks], bh0);
                MMA16816(sa[2*p+1], qh[ks], bh1);
                MMA16816(sa[2*p+1], qh[ks], bl1);
                MMA16816(sa[2*p+1], ql[ks], bh1);
            }
        }

        #pragma unroll
        for (int nt = 0; nt < 8; nt++) {
            int col = kt * 64 + nt * 8 + gc2;
            #pragma unroll
            for (int e = 0; e < 4; e++) {
                float s2 = sa[nt][e] * 0.125f;
                if (banded) {
                    int r = (e < 2) ? qrow0 : qrow1;
                    int c = col + (e & 1);
                    int d = r - c;
                    if (d <= RR && d >= -RR) s2 += 1.0f;
                }
                sa[nt][e] = s2;
            }
        }

        float mx0 = -1e30f, mx1 = -1e30f;
        #pragma unroll
        for (int nt = 0; nt < 8; nt++) {
            mx0 = fmaxf(mx0, fmaxf(sa[nt][0], sa[nt][1]));
            mx1 = fmaxf(mx1, fmaxf(sa[nt][2], sa[nt][3]));
        }
        mx0 = fmaxf(mx0, __shfl_xor_sync(0xffffffffu, mx0, 1));
        mx0 = fmaxf(mx0, __shfl_xor_sync(0xffffffffu, mx0, 2));
        mx1 = fmaxf(mx1, __shfl_xor_sync(0xffffffffu, mx1, 1));
        mx1 = fmaxf(mx1, __shfl_xor_sync(0xffffffffu, mx1, 2));

        float nm0 = fmaxf(m0r, mx0), nm1 = fmaxf(m1r, mx1);
        float al0 = __expf(m0r - nm0), al1 = __expf(m1r - nm1);
        m0r = nm0; m1r = nm1;
        l0 *= al0; l1 *= al1;
        #pragma unroll
        for (int nt = 0; nt < 8; nt++) {
            oa[nt][0] *= al0; oa[nt][1] *= al0;
            oa[nt][2] *= al1; oa[nt][3] *= al1;
        }

        float ph_f[8][4], pl_f[8][4];
        #pragma unroll
        for (int nt = 0; nt < 8; nt++) {
            #pragma unroll
            for (int e = 0; e < 4; e++) {
                float p = __expf(sa[nt][e] - ((e < 2) ? nm0 : nm1));
                if (e < 2) l0 += p; else l1 += p;
                float hf = __bfloat162float(__float2bfloat16(p));
                ph_f[nt][e] = hf;
                pl_f[nt][e] = p - hf;
            }
        }

        uint32_t ph[4][4], pl[4][4];
        #pragma unroll
        for (int ks = 0; ks < 4; ks++) {
            int t0 = 2*ks, t1 = 2*ks + 1;
            ph[ks][0] = pack_bf16(ph_f[t0][0], ph_f[t0][1]);
            ph[ks][1] = pack_bf16(ph_f[t0][2], ph_f[t0][3]);
            ph[ks][2] = pack_bf16(ph_f[t1][0], ph_f[t1][1]);
            ph[ks][3] = pack_bf16(ph_f[t1][2], ph_f[t1][3]);
            pl[ks][0] = pack_bf16(pl_f[t0][0], pl_f[t0][1]);
            pl[ks][1] = pack_bf16(pl_f[t0][2], pl_f[t0][3]);
            pl[ks][2] = pack_bf16(pl_f[t1][0], pl_f[t1][1]);
            pl[ks][3] = pack_bf16(pl_f[t1][2], pl_f[t1][3]);
        }

        #pragma unroll
        for (int p = 0; p < 4; p++) {
            #pragma unroll
            for (int ks = 0; ks < 4; ks++) {
                int row = p * 16 + lr16;
                uint32_t off = sw64(row, ks * 16 + lk8) * 2;
                uint32_t h0, h1, h2, h3, v0, v1, v2, v3;
                LDSM4(h0, h1, h2, h3, base + AVHI + off);
                LDSM4(v0, v1, v2, v3, base + AVLO + off);
                uint32_t bh0[2] = {h0, h2}, bh1[2] = {h1, h3};
                uint32_t bl0[2] = {v0, v2}, bl1[2] = {v1, v3};
                MMA16816(oa[2*p],   ph[ks], bh0);
                MMA16816(oa[2*p],   pl[ks], bh0);
                MMA16816(oa[2*p],   ph[ks], bl0);
                MMA16816(oa[2*p+1], ph[ks], bh1);
                MMA16816(oa[2*p+1], pl[ks], bh1);
                MMA16816(oa[2*p+1], ph[ks], bl1);
            }
        }
        __syncthreads();
    }

    l0 += __shfl_xor_sync(0xffffffffu, l0, 1);
    l0 += __shfl_xor_sync(0xffffffffu, l0, 2);
    l1 += __shfl_xor_sync(0xffffffffu, l1, 1);
    l1 += __shfl_xor_sync(0xffffffffu, l1, 2);
    const float inv0 = 1.0f / l0, inv1 = 1.0f / l1;

    #pragma unroll
    for (int nt = 0; nt < 8; nt++) {
        int d = nt * 8 + gc2;
        int col = h * DHH + d;
        int R0 = b * SS + qrow0, R1 = b * SS + qrow1;
        size_t off0 = ((size_t)(R0 >> 6) * 24 + (col >> 5)) * 2048 + sw_elem(R0 & 63, col & 31);
        size_t off1 = ((size_t)(R1 >> 6) * 24 + (col >> 5)) * 2048 + sw_elem(R1 & 63, col & 31);
        float v0 = oa[nt][0] * inv0, v1 = oa[nt][1] * inv0;
        float v2 = oa[nt][2] * inv1, v3 = oa[nt][3] * inv1;
        bf16 h0 = __float2bfloat16(v0), h1 = __float2bfloat16(v1);
        bf16 h2 = __float2bfloat16(v2), h3 = __float2bfloat16(v3);
        *(__nv_bfloat162*)&Ohi[off0] = {h0, h1};
        *(__nv_bfloat162*)&Olo[off0] = {__float2bfloat16(v0 - __bfloat162float(h0)),
                                        __float2bfloat16(v1 - __bfloat162float(h1))};
        *(__nv_bfloat162*)&Ohi[off1] = {h2, h3};
        *(__nv_bfloat162*)&Olo[off1] = {__float2bfloat16(v2 - __bfloat162float(h2)),
                                        __float2bfloat16(v3 - __bfloat162float(h3))};
    }
}

// ---------------- layernorm (fp32 + optional packed split out) --------------
__global__ __launch_bounds__(256) void ln_kernel(
    const float* __restrict__ X, const float* __restrict__ g,
    const float* __restrict__ bta, float* __restrict__ Y,
    bf16* __restrict__ Yhi, bf16* __restrict__ Ylo)
{
    __shared__ float red[8];
    const int row = blockIdx.x, t = threadIdx.x;
    const float* x = X + (size_t)row * DD;

    float v0 = x[t], v1 = x[t + 256], v2 = x[t + 512];
    float s = v0 + v1 + v2;
    #pragma unroll
    for (int o = 16; o; o >>= 1) s += __shfl_xor_sync(0xffffffffu, s, o);
    if ((t & 31) == 0) red[t >> 5] = s;
    __syncthreads();
    float tot = 0.f;
    #pragma unroll
    for (int i = 0; i < 8; i++) tot += red[i];
    const float mean = tot * (1.0f / 768.0f);

    float d0 = v0 - mean, d1 = v1 - mean, d2 = v2 - mean;
    float s2 = d0*d0 + d1*d1 + d2*d2;
    __syncthreads();
    #pragma unroll
    for (int o = 16; o; o >>= 1) s2 += __shfl_xor_sync(0xffffffffu, s2, o);
    if ((t & 31) == 0) red[t >> 5] = s2;
    __syncthreads();
    float tot2 = 0.f;
    #pragma unroll
    for (int i = 0; i < 8; i++) tot2 += red[i];
    const float rstd = rsqrtf(tot2 * (1.0f / 768.0f) + 1e-12f);

    float* y = Y + (size_t)row * DD;
    #pragma unroll
    for (int c = 0; c < 3; c++) {
        int idx = t + 256 * c;
        float dv = (c == 0) ? d0 : (c == 1) ? d1 : d2;
        float r = dv * rstd * g[idx] + bta[idx];
        y[idx] = r;
        if (Yhi) {
            size_t off = ((size_t)(row >> 6) * 24 + (idx >> 5)) * 2048
                         + sw_elem(row & 63, idx & 31);
            bf16 hh = __float2bfloat16(r);
            Yhi[off] = hh;
            Ylo[off] = __float2bfloat16(r - __bfloat162float(hh));
        }
    }
}

// ---------------- launch ----------------------------------------------------
extern "C" void kernel_launch(void* const* d_in, const int* in_sizes, int n_in,
                              void* d_out, int out_size)
{
    const float* hidden  = (const float*)d_in[0];
    const float* tag_emb = (const float*)d_in[1];
    const float* sa_wq = (const float*)d_in[2],  *sa_bq = (const float*)d_in[3];
    const float* sa_wk = (const float*)d_in[4],  *sa_bk = (const float*)d_in[5];
    const float* sa_wv = (const float*)d_in[6],  *sa_bv = (const float*)d_in[7];
    const float* sa_wo = (const float*)d_in[8],  *sa_bo = (const float*)d_in[9];
    const float* sa_lg = (const float*)d_in[10], *sa_lb = (const float*)d_in[11];
    const float* ca_wq = (const float*)d_in[12], *ca_bq = (const float*)d_in[13];
    const float* ca_wk = (const float*)d_in[14], *ca_bk = (const float*)d_in[15];
    const float* ca_wv = (const float*)d_in[16], *ca_bv = (const float*)d_in[17];
    const float* ca_wo = (const float*)d_in[18], *ca_bo = (const float*)d_in[19];
    const float* ca_lg = (const float*)d_in[20], *ca_lb = (const float*)d_in[21];
    const float* ff_w1 = (const float*)d_in[22], *ff_b1 = (const float*)d_in[23];
    const float* ff_w2 = (const float*)d_in[24], *ff_b2 = (const float*)d_in[25];
    const float* ff_lg = (const float*)d_in[26], *ff_lb = (const float*)d_in[27];
    float* out = (float*)d_out;

    float *tmp, *x1, *x2, *bqkv;
    bf16 *whi, *wlo, *qhi, *qlo, *khi, *klo, *vthi, *vtlo, *ctxhi, *ctxlo;
    bf16 *x1hi, *x1lo, *x2hi, *x2lo, *hhi, *hlo, *ihi, *ilo;
    bf16 *ckhi, *cklo, *cvthi, *cvtlo;
    cudaGetSymbolAddress((void**)&tmp,  g_tmp);
    cudaGetSymbolAddress((void**)&x1,   g_x1);
    cudaGetSymbolAddress((void**)&x2,   g_x2);
    cudaGetSymbolAddress((void**)&bqkv, g_bqkv);
    cudaGetSymbolAddress((void**)&whi,  g_whi);
    cudaGetSymbolAddress((void**)&wlo,  g_wlo);
    cudaGetSymbolAddress((void**)&qhi,  g_qhi);
    cudaGetSymbolAddress((void**)&qlo,  g_qlo);
    cudaGetSymbolAddress((void**)&khi,  g_khi);
    cudaGetSymbolAddress((void**)&klo,  g_klo);
    cudaGetSymbolAddress((void**)&vthi, g_vthi);
    cudaGetSymbolAddress((void**)&vtlo, g_vtlo);
    cudaGetSymbolAddress((void**)&ctxhi, g_ctxhi);
    cudaGetSymbolAddress((void**)&ctxlo, g_ctxlo);
    cudaGetSymbolAddress((void**)&x1hi, g_x1hi);
    cudaGetSymbolAddress((void**)&x1lo, g_x1lo);
    cudaGetSymbolAddress((void**)&x2hi, g_x2hi);
    cudaGetSymbolAddress((void**)&x2lo, g_x2lo);
    cudaGetSymbolAddress((void**)&hhi,  g_hhi);
    cudaGetSymbolAddress((void**)&hlo,  g_hlo);
    cudaGetSymbolAddress((void**)&ihi,  g_ihi);
    cudaGetSymbolAddress((void**)&ilo,  g_ilo);
    cudaGetSymbolAddress((void**)&ckhi, g_ckhi);
    cudaGetSymbolAddress((void**)&cklo, g_cklo);
    cudaGetSymbolAddress((void**)&cvthi, g_cvthi);
    cudaGetSymbolAddress((void**)&cvtlo, g_cvtlo);

    // raise smem limits + max carveout so 3 CTAs/SM can co-reside
    cudaFuncSetAttribute(mma_gemm<0,3>, cudaFuncAttributeMaxDynamicSharedMemorySize, GEMM_SMEM);
    cudaFuncSetAttribute(mma_gemm<0,1>, cudaFuncAttributeMaxDynamicSharedMemorySize, GEMM_SMEM);
    cudaFuncSetAttribute(mma_gemm<1,0>, cudaFuncAttributeMaxDynamicSharedMemorySize, GEMM_SMEM);
    cudaFuncSetAttribute(mma_gemm<2,2>, cudaFuncAttributeMaxDynamicSharedMemorySize, GEMM_SMEM);
    cudaFuncSetAttribute(mha_kernel,    cudaFuncAttributeMaxDynamicSharedMemorySize, ATT_SMEM);
    cudaFuncSetAttribute(mma_gemm<0,3>, cudaFuncAttributePreferredSharedMemoryCarveout, 100);
    cudaFuncSetAttribute(mma_gemm<0,1>, cudaFuncAttributePreferredSharedMemoryCarveout, 100);
    cudaFuncSetAttribute(mma_gemm<1,0>, cudaFuncAttributePreferredSharedMemoryCarveout, 100);
    cudaFuncSetAttribute(mma_gemm<2,2>, cudaFuncAttributePreferredSharedMemoryCarveout, 100);
    cudaFuncSetAttribute(mha_kernel,    cudaFuncAttributePreferredSharedMemoryCarveout, 100);

    const size_t o_sawo = 3*(size_t)DxD, o_cawq = 4*(size_t)DxD, o_cawo = 5*(size_t)DxD;
    const size_t o_ff1  = 6*(size_t)DxD;
    const size_t o_ff2  = 6*(size_t)DxD + (size_t)768*3072;

    const dim3 wsB(32, 8);
    // all prep (8 weight splits + hidden split + bias concat) in one launch
    prep_kernel<<<dim3(96, 24, 9), wsB>>>(sa_wq, sa_wk, sa_wv, sa_wo, ca_wq, ca_wo,
                                          ff_w1, ff_w2, whi, wlo,
                                          hidden, hhi, hlo, sa_bq, sa_bk, sa_bv, bqkv);

    const dim3 thr(256);
    const dim3 gQKV(2304 / GBN, MROWS / GBM);   // (18, 64)
    const dim3 gMMA_D (DD / GBN, MROWS / GBM);  // (6, 64)
    const dim3 gMMA_F1(FF / GBN, MROWS / GBM);  // (24, 64)
    const dim3 gCK(DD / BN, TT / BM);           // (12, 1)
    const dim3 attn_grid(SS / 128, HH, BB);
    const size_t smb = GEMM_SMEM;

    // ---- self attention ----
    mma_gemm<0,3><<<gQKV, thr, smb>>>(hhi, hlo, whi, wlo, bqkv, nullptr,
                                      nullptr, qhi, qlo, khi, klo, vthi, vtlo, 2304, DD);
    mha_kernel<<<attn_grid, 256, ATT_SMEM>>>(qhi, qlo, khi, klo, vthi, vtlo, ctxhi, ctxlo,
                                             SS/64, HH*32, 32, 1);
    mma_gemm<1,0><<<gMMA_D, thr, smb>>>(ctxhi, ctxlo, whi+o_sawo, wlo+o_sawo, sa_bo, hidden,
                                        tmp, nullptr, nullptr, nullptr, nullptr, nullptr, nullptr, DD, DD);
    ln_kernel<<<MROWS, thr>>>(tmp, sa_lg, sa_lb, x1, x1hi, x1lo);

    // ---- cross attention ----
    mma_gemm<0,1><<<gMMA_D, thr, smb>>>(x1hi, x1lo, whi+o_cawq, wlo+o_cawq, ca_bq, nullptr,
                                        nullptr, qhi, qlo, nullptr, nullptr, nullptr, nullptr, DD, DD);
    tag_gemm<0><<<gCK, thr>>>(tag_emb, ca_wk, ca_bk, ckhi, cklo, TT, DD, DD);
    tag_gemm<1><<<gCK, thr>>>(tag_emb, ca_wv, ca_bv, cvthi, cvtlo, TT, DD, DD);
    mha_kernel<<<attn_grid, 256, ATT_SMEM>>>(qhi, qlo, ckhi, cklo, cvthi, cvtlo, ctxhi, ctxlo,
                                             1, 0, 1, 0);
    mma_gemm<1,0><<<gMMA_D, thr, smb>>>(ctxhi, ctxlo, whi+o_cawo, wlo+o_cawo, ca_bo, x1,
                                        tmp, nullptr, nullptr, nullptr, nullptr, nullptr, nullptr, DD, DD);
    ln_kernel<<<MROWS, thr>>>(tmp, ca_lg, ca_lb, x2, x2hi, x2lo);

    // ---- FFN ----
    mma_gemm<2,2><<<gMMA_F1, thr, smb>>>(x2hi, x2lo, whi+o_ff1, wlo+o_ff1, ff_b1, nullptr,
                                         nullptr, ihi, ilo, nullptr, nullptr, nullptr, nullptr, FF, DD);
    mma_gemm<1,0><<<gMMA_D, thr, smb>>>(ihi, ilo, whi+o_ff2, wlo+o_ff2, ff_b2, x2,
                                        tmp, nullptr, nullptr, nullptr, nullptr, nullptr, nullptr, DD, FF);
    ln_kernel<<<MROWS, thr>>>(tmp, ff_lg, ff_lb, out, nullptr, nullptr);
}

// round 16
// speedup vs baseline: 1.1878x; 1.0005x over previous
#include <cuda_runtime.h>
#include <cuda_bf16.h>
#include <math.h>
#include <stdint.h>

#define BB 2
#define SS 2048
#define DD 768
#define HH 12
#define DHH 64
#define TT 64
#define RR 50
#define FF 3072
#define MROWS (BB*SS)   // 4096

typedef __nv_bfloat16 bf16;

// ---------------- scratch ---------------------------------------------------
__device__ float g_tmp [MROWS*DD];
__device__ float g_x1  [MROWS*DD];
__device__ float g_x2  [MROWS*DD];
__device__ float g_bqkv[3*DD];

// attention-packed buffers (64x64 sw64 blocks)
__device__ __align__(128) bf16 g_qhi[MROWS*DD];
__device__ __align__(128) bf16 g_qlo[MROWS*DD];
__device__ __align__(128) bf16 g_khi[MROWS*DD];
__device__ __align__(128) bf16 g_klo[MROWS*DD];
__device__ __align__(128) bf16 g_vthi[BB*HH*DHH*SS];
__device__ __align__(128) bf16 g_vtlo[BB*HH*DHH*SS];
__device__ __align__(128) bf16 g_ckhi[HH*TT*DHH];
__device__ __align__(128) bf16 g_cklo[HH*TT*DHH];
__device__ __align__(128) bf16 g_cvthi[HH*DHH*TT];
__device__ __align__(128) bf16 g_cvtlo[HH*DHH*TT];

// GEMM operand buffers (A: 64x32 sw_elem blocks; B: 192x32 sw_elem blocks)
__device__ __align__(128) bf16 g_ctxhi[MROWS*DD];
__device__ __align__(128) bf16 g_ctxlo[MROWS*DD];
__device__ __align__(128) bf16 g_x1hi[MROWS*DD];
__device__ __align__(128) bf16 g_x1lo[MROWS*DD];
__device__ __align__(128) bf16 g_x2hi[MROWS*DD];
__device__ __align__(128) bf16 g_x2lo[MROWS*DD];
__device__ __align__(128) bf16 g_hhi[MROWS*DD];
__device__ __align__(128) bf16 g_hlo[MROWS*DD];
__device__ __align__(128) bf16 g_ihi[MROWS*FF];
__device__ __align__(128) bf16 g_ilo[MROWS*FF];

#define DxD (768*768)
#define WSPLIT_TOTAL (6*DxD + 2*768*3072)
__device__ __align__(128) bf16 g_whi[WSPLIT_TOTAL];
__device__ __align__(128) bf16 g_wlo[WSPLIT_TOTAL];

// ================= helpers ==================================================
__device__ __forceinline__ uint32_t smem_u32(const void* p) {
    return (uint32_t)__cvta_generic_to_shared(p);
}
__device__ __forceinline__ uint32_t pack_bf16(float a, float b) {
    __nv_bfloat162 t = __floats2bfloat162_rn(a, b);
    return *(uint32_t*)&t;
}
// swizzled element offset inside a [rows][32] bf16 tile
__device__ __forceinline__ uint32_t sw_elem(int row, int k) {
    return (uint32_t)(row * 32 + ((((k >> 3) ^ ((row >> 1) & 3))) << 3) + (k & 7));
}
// attention 64x64 tile swizzled element offset
__device__ __forceinline__ uint32_t sw64(int row, int k) {
    return (uint32_t)(row * 64 + ((((k >> 3) ^ (row & 7))) << 3) + (k & 7));
}

#define LDSM4(r0, r1, r2, r3, addr) \
    asm volatile("ldmatrix.sync.aligned.m8n8.x4.shared.b16 {%0,%1,%2,%3}, [%4];" \
                 : "=r"(r0), "=r"(r1), "=r"(r2), "=r"(r3) : "r"(addr))
#define MMA16816(c, a, b) \
    asm volatile("mma.sync.aligned.m16n8k16.row.col.f32.bf16.bf16.f32 " \
                 "{%0,%1,%2,%3}, {%4,%5,%6,%7}, {%8,%9}, {%0,%1,%2,%3};" \
                 : "+f"(c[0]), "+f"(c[1]), "+f"(c[2]), "+f"(c[3]) \
                 : "r"(a[0]), "r"(a[1]), "r"(a[2]), "r"(a[3]), "r"(b[0]), "r"(b[1]))

__device__ __forceinline__ void mbar_init(uint32_t a, uint32_t cnt) {
    asm volatile("mbarrier.init.shared.b64 [%0], %1;" :: "r"(a), "r"(cnt) : "memory");
}
__device__ __forceinline__ void mbar_expect(uint32_t a, uint32_t bytes) {
    asm volatile("mbarrier.arrive.expect_tx.shared.b64 _, [%0], %1;"
                 :: "r"(a), "r"(bytes) : "memory");
}
__device__ __forceinline__ void mbar_wait(uint32_t a, uint32_t parity) {
    asm volatile(
        "{\n\t.reg .pred P;\n\t"
        "W%=:\n\t"
        "mbarrier.try_wait.parity.acquire.cta.shared::cta.b64 P, [%0], %1, 0x989680;\n\t"
        "@!P bra W%=;\n\t}"
        :: "r"(a), "r"(parity) : "memory");
}
__device__ __forceinline__ void bulk_g2s(uint32_t dst, const void* src,
                                         uint32_t bytes, uint32_t mbar) {
    asm volatile(
        "cp.async.bulk.shared::cta.global.mbarrier::complete_tx::bytes [%0], [%1], %2, [%3];"
        :: "r"(dst), "l"(src), "r"(bytes), "r"(mbar) : "memory");
}

// ================= fused prep: 8 weight splits + activation split + bcat ====
// grid (96, 24, 9), block (32, 8). Weight B-packing: 192-row x 32-col blocks.
__global__ __launch_bounds__(256) void prep_kernel(
    const float* __restrict__ w0, const float* __restrict__ w1,
    const float* __restrict__ w2, const float* __restrict__ w3,
    const float* __restrict__ w4, const float* __restrict__ w5,
    const float* __restrict__ w6, const float* __restrict__ w7,
    bf16* __restrict__ hiB, bf16* __restrict__ loB,
    const float* __restrict__ X, bf16* __restrict__ xhi, bf16* __restrict__ xlo,
    const float* __restrict__ bq, const float* __restrict__ bk,
    const float* __restrict__ bv, float* __restrict__ bqkv)
{
    const int z = blockIdx.z;
    const int tid = threadIdx.y * 32 + threadIdx.x;

    if (z == 8) {
        int gid = (blockIdx.y * 96 + blockIdx.x) * 256 + tid;
        if (gid < 768) bqkv[gid] = bq[gid];
        else if (gid < 1536) bqkv[gid] = bk[gid - 768];
        else if (gid < 2304) bqkv[gid] = bv[gid - 1536];
        const int n4 = MROWS * DD / 4;
        for (int i = gid; i < n4; i += 96 * 24 * 256) {
            float4 v = ((const float4*)X)[i];
            int r = (i * 4) / 768, c = (i * 4) % 768;
            size_t off = ((size_t)(r >> 6) * 24 + (c >> 5)) * 2048 + sw_elem(r & 63, c & 31);
            bf16 h0 = __float2bfloat16(v.x), h1 = __float2bfloat16(v.y);
            bf16 h2 = __float2bfloat16(v.z), h3 = __float2bfloat16(v.w);
            *(__nv_bfloat162*)&xhi[off]     = {h0, h1};
            *(__nv_bfloat162*)&xhi[off + 2] = {h2, h3};
            *(__nv_bfloat162*)&xlo[off]     = {__float2bfloat16(v.x - __bfloat162float(h0)),
                                               __float2bfloat16(v.y - __bfloat162float(h1))};
            *(__nv_bfloat162*)&xlo[off + 2] = {__float2bfloat16(v.z - __bfloat162float(h2)),
                                               __float2bfloat16(v.w - __bfloat162float(h3))};
        }
        return;
    }

    __shared__ float tile[32][33];
    const float* W;
    int K, N, n0, k0;
    size_t ofs;
    if (z < 6) {
        if (blockIdx.x >= 24) return;
        K = 768; N = 768;
        k0 = blockIdx.x * 32; n0 = blockIdx.y * 32;
        const float* ws[6] = {w0, w1, w2, w3, w4, w5};
        W = ws[z];
        ofs = (size_t)z * DxD;
    } else if (z == 6) {
        K = 768; N = 3072;
        n0 = blockIdx.x * 32; k0 = blockIdx.y * 32;
        W = w6;
        ofs = 6 * (size_t)DxD;
    } else {
        K = 3072; N = 768;
        k0 = blockIdx.x * 32; n0 = blockIdx.y * 32;
        W = w7;
        ofs = 6 * (size_t)DxD + (size_t)768 * 3072;
    }
    bf16* hiT = hiB + ofs;
    bf16* loT = loB + ofs;

    const int tx = threadIdx.x, ty = threadIdx.y;
    #pragma unroll
    for (int i = 0; i < 4; i++)
        tile[ty + 8*i][tx] = W[(size_t)(k0 + ty + 8*i) * N + n0 + tx];
    __syncthreads();
    #pragma unroll
    for (int i = 0; i < 4; i++) {
        float v = tile[tx][ty + 8*i];
        int n = n0 + ty + 8*i, k = k0 + tx;
        bf16 h = __float2bfloat16(v);
        size_t o = ((size_t)(n / 192) * (K >> 5) + (k >> 5)) * 6144
                   + sw_elem(n % 192, k & 31);
        hiT[o] = h;
        loT[o] = __float2bfloat16(v - __bfloat162float(h));
    }
}

// ================= bf16-split tensor-core GEMM (64x192 tile) ===============
#define GBM 64
#define GBN 192
#define STAGE_BYTES 32768
#define OFF_AHI 0
#define OFF_ALO 4096
#define OFF_BHI 8192
#define OFF_BLO 20480
#define GEMM_SMEM (1024 + 3*STAGE_BYTES)

// MODE: 0 bias, 1 bias+res, 2 bias+gelu
// OSPLIT: 0 fp32 C | 1 attention-QK packed | 2 GEMM-A packed | 3 fused QKV route
template<int MODE, int OSPLIT>
__global__ __launch_bounds__(256, 2) void mma_gemm(
    const bf16* __restrict__ Apk_hi, const bf16* __restrict__ Apk_lo,
    const bf16* __restrict__ Bpk_hi, const bf16* __restrict__ Bpk_lo,
    const float* __restrict__ bias, const float* __restrict__ Rz,
    float* __restrict__ C, bf16* __restrict__ Chi, bf16* __restrict__ Clo,
    bf16* __restrict__ C2hi, bf16* __restrict__ C2lo,
    bf16* __restrict__ C3hi, bf16* __restrict__ C3lo,
    int N, int K)
{
    extern __shared__ __align__(16) char smem[];
    const uint32_t sb = smem_u32(smem);
    const uint32_t mb0 = sb, mb1 = sb + 8, mb2 = sb + 16;
    const uint32_t data = sb + 1024;

    const int tid = threadIdx.x;
    const int wid = tid >> 5, lane = tid & 31;
    const int warp_m = wid & 1, warp_n = wid >> 1;   // 2 x 4 warps, warp tile 32x48
    const int m0 = blockIdx.y * GBM, n0 = blockIdx.x * GBN;
    const int KT = K >> 5;

    const bf16* Ahi_t = Apk_hi + (size_t)(m0 >> 6) * KT * 2048;
    const bf16* Alo_t = Apk_lo + (size_t)(m0 >> 6) * KT * 2048;
    const bf16* Bhi_t = Bpk_hi + (size_t)(n0 / 192) * KT * 6144;
    const bf16* Blo_t = Bpk_lo + (size_t)(n0 / 192) * KT * 6144;

    if (tid == 0) { mbar_init(mb0, 1); mbar_init(mb1, 1); mbar_init(mb2, 1); }
    __syncthreads();

    auto issue = [&](int s, int kt) {
        const uint32_t mb = sb + s * 8;
        mbar_expect(mb, (uint32_t)STAGE_BYTES);
        const uint32_t b = data + s * STAGE_BYTES;
        bulk_g2s(b + OFF_AHI, Ahi_t + (size_t)kt * 2048, 4096, mb);
        bulk_g2s(b + OFF_ALO, Alo_t + (size_t)kt * 2048, 4096, mb);
        bulk_g2s(b + OFF_BHI, Bhi_t + (size_t)kt * 6144, 12288, mb);
        bulk_g2s(b + OFF_BLO, Blo_t + (size_t)kt * 6144, 12288, mb);
    };
    if (tid == 0) {
        issue(0, 0);
        if (KT > 1) issue(1, 1);
    }

    float acc[2][6][4];
    #pragma unroll
    for (int i = 0; i < 2; i++)
        #pragma unroll
        for (int j = 0; j < 6; j++)
            #pragma unroll
            for (int p = 0; p < 4; p++) acc[i][j][p] = 0.f;

    const int lr16 = lane & 15;
    const int lk8  = (lane >> 4) * 8;
    int p0 = 0, p1 = 0, p2 = 0;
    int s = 0;

    for (int kt = 0; kt < KT; kt++) {
        if (s == 0) { mbar_wait(mb0, p0); p0 ^= 1; }
        else if (s == 1) { mbar_wait(mb1, p1); p1 ^= 1; }
        else { mbar_wait(mb2, p2); p2 ^= 1; }

        const uint32_t base = data + s * STAGE_BYTES;
        #pragma unroll
        for (int k16 = 0; k16 < 32; k16 += 16) {
            uint32_t ah[2][4], al[2][4];
            #pragma unroll
            for (int mt = 0; mt < 2; mt++) {
                int row = warp_m * 32 + mt * 16 + lr16;
                uint32_t off = sw_elem(row, k16 + lk8) * 2;
                LDSM4(ah[mt][0], ah[mt][1], ah[mt][2], ah[mt][3], base + OFF_AHI + off);
                LDSM4(al[mt][0], al[mt][1], al[mt][2], al[mt][3], base + OFF_ALO + off);
            }
            uint32_t bh[6][2], bl[6][2];
            #pragma unroll
            for (int p = 0; p < 3; p++) {
                int row = warp_n * 48 + p * 16 + lr16;
                uint32_t off = sw_elem(row, k16 + lk8) * 2;
                uint32_t q0, q1, q2, q3;
                LDSM4(q0, q1, q2, q3, base + OFF_BHI + off);
                bh[2*p][0] = q0; bh[2*p][1] = q2; bh[2*p+1][0] = q1; bh[2*p+1][1] = q3;
                LDSM4(q0, q1, q2, q3, base + OFF_BLO + off);
                bl[2*p][0] = q0; bl[2*p][1] = q2; bl[2*p+1][0] = q1; bl[2*p+1][1] = q3;
            }
            #pragma unroll
            for (int mt = 0; mt < 2; mt++)
                #pragma unroll
                for (int nt = 0; nt < 6; nt++) {
                    MMA16816(acc[mt][nt], ah[mt], bh[nt]);
                    MMA16816(acc[mt][nt], ah[mt], bl[nt]);
                    MMA16816(acc[mt][nt], al[mt], bh[nt]);
                }
        }
        __syncthreads();
        if (tid == 0 && kt + 2 < KT) issue((kt + 2) % 3, kt + 2);
        s = (s + 1 == 3) ? 0 : s + 1;
    }

    #pragma unroll
    for (int mt = 0; mt < 2; mt++) {
        #pragma unroll
        for (int nt = 0; nt < 6; nt++) {
            int r0 = m0 + warp_m * 32 + mt * 16 + (lane >> 2);
            int cc = n0 + warp_n * 48 + nt * 8 + 2 * (lane & 3);
            float b0 = bias[cc], b1 = bias[cc + 1];
            #pragma unroll
            for (int hh = 0; hh < 2; hh++) {
                int r = r0 + 8 * hh;
                float v0 = acc[mt][nt][2*hh]     + b0;
                float v1 = acc[mt][nt][2*hh + 1] + b1;
                if (MODE == 1) {
                    const float* rp = Rz + (size_t)r * N + cc;
                    v0 += rp[0]; v1 += rp[1];
                }
                if (MODE == 2) {
                    v0 = 0.5f * v0 * (1.0f + erff(v0 * 0.70710678118654752f));
                    v1 = 0.5f * v1 * (1.0f + erff(v1 * 0.70710678118654752f));
                }
                if (OSPLIT == 0) {
                    *(float2*)&C[(size_t)r * N + cc] = make_float2(v0, v1);
                } else {
                    bf16 h0 = __float2bfloat16(v0), h1 = __float2bfloat16(v1);
                    __nv_bfloat162 hv = {h0, h1};
                    bf16 l0b = __float2bfloat16(v0 - __bfloat162float(h0));
                    bf16 l1b = __float2bfloat16(v1 - __bfloat162float(h1));
                    __nv_bfloat162 lv = {l0b, l1b};
                    if (OSPLIT == 1) {
                        int bb = r >> 11, s2 = r & 2047;
                        int h2 = cc >> 6, d = cc & 63;
                        size_t off = ((size_t)(bb * HH + h2) * 32 + (s2 >> 6)) * 4096
                                     + sw64(s2 & 63, d);
                        *(__nv_bfloat162*)&Chi[off] = hv;
                        *(__nv_bfloat162*)&Clo[off] = lv;
                    } else if (OSPLIT == 2) {
                        size_t off = ((size_t)(r >> 6) * (N >> 5) + (cc >> 5)) * 2048
                                     + sw_elem(r & 63, cc & 31);
                        *(__nv_bfloat162*)&Chi[off] = hv;
                        *(__nv_bfloat162*)&Clo[off] = lv;
                    } else {
                        int j = (cc >= 1536) ? 2 : ((cc >= 768) ? 1 : 0);
                        int local = cc - j * 768;
                        int bb = r >> 11, s2 = r & 2047;
                        int h2 = local >> 6, d = local & 63;
                        size_t blk = ((size_t)(bb * HH + h2) * 32 + (s2 >> 6)) * 4096;
                        if (j == 0) {
                            size_t off = blk + sw64(s2 & 63, d);
                            *(__nv_bfloat162*)&Chi[off] = hv;
                            *(__nv_bfloat162*)&Clo[off] = lv;
                        } else if (j == 1) {
                            size_t off = blk + sw64(s2 & 63, d);
                            *(__nv_bfloat162*)&C2hi[off] = hv;
                            *(__nv_bfloat162*)&C2lo[off] = lv;
                        } else {
                            size_t off0 = blk + sw64(d,     s2 & 63);
                            size_t off1 = blk + sw64(d + 1, s2 & 63);
                            C3hi[off0] = h0; C3lo[off0] = l0b;
                            C3hi[off1] = h1; C3lo[off1] = l1b;
                        }
                    }
                }
            }
        }
    }
}

// ---------------- fp32 SIMT tag GEMM with fused attention-pack epilogue -----
#define BM 64
#define BN 64
#define BK 16
template<int TRANS>
__global__ __launch_bounds__(256) void tag_gemm(
    const float* __restrict__ A, const float* __restrict__ W,
    const float* __restrict__ bias, bf16* __restrict__ Phi, bf16* __restrict__ Plo,
    int M, int N, int K)
{
    __shared__ float As[BK][68];
    __shared__ float Bs[BK][BN];
    const int tid = threadIdx.x;
    const int tx = tid & 15, ty = tid >> 4;
    const int m0 = blockIdx.y * BM, n0 = blockIdx.x * BN;
    float acc[4][4] = {};
    for (int k0 = 0; k0 < K; k0 += BK) {
        {
            const int r = tid >> 4, c = tid & 15;
            #pragma unroll
            for (int i = 0; i < 4; i++)
                As[c][r + 16*i] = A[(size_t)(m0 + r + 16*i) * K + k0 + c];
        }
        {
            const int r = tid >> 6, c = tid & 63;
            #pragma unroll
            for (int i = 0; i < 4; i++)
                Bs[r + 4*i][c] = W[(size_t)(k0 + r + 4*i) * N + n0 + c];
        }
        __syncthreads();
        #pragma unroll
        for (int kk = 0; kk < BK; kk++) {
            float4 a4 = *(const float4*)&As[kk][ty*4];
            float4 b4 = *(const float4*)&Bs[kk][tx*4];
            float a[4] = {a4.x, a4.y, a4.z, a4.w};
            float b[4] = {b4.x, b4.y, b4.z, b4.w};
            #pragma unroll
            for (int i = 0; i < 4; i++)
                #pragma unroll
                for (int j = 0; j < 4; j++)
                    acc[i][j] += a[i] * b[j];
        }
        __syncthreads();
    }
    #pragma unroll
    for (int i = 0; i < 4; i++) {
        const int m = m0 + ty*4 + i;
        #pragma unroll
        for (int j = 0; j < 4; j++) {
            const int n = n0 + tx*4 + j;
            float vv = acc[i][j] + bias[n];
            int h = n >> 6, d = n & 63;
            bf16 hb = __float2bfloat16(vv);
            size_t off = (size_t)h * 4096 + (TRANS ? sw64(d, m) : sw64(m, d));
            Phi[off] = hb;
            Plo[off] = __float2bfloat16(vv - __bfloat162float(hb));
        }
    }
}

// ================= tensor-core flash attention (128 queries / block) ========
#define AQHI 0
#define AQLO 16384
#define ASTG 32768
#define AKHI 0
#define AKLO 8192
#define AVHI 16384
#define AVLO 24576
#define ATT_SMEM (1024 + 32768 + 2*32768)

__global__ __launch_bounds__(256) void mha_kernel(
    const bf16* __restrict__ Qhi, const bf16* __restrict__ Qlo,
    const bf16* __restrict__ Khi, const bf16* __restrict__ Klo,
    const bf16* __restrict__ Vhi, const bf16* __restrict__ Vlo,
    bf16* __restrict__ Ohi, bf16* __restrict__ Olo,
    int ntiles, int kb, int kh, int banded)
{
    extern __shared__ __align__(16) char smem[];
    const uint32_t sb = smem_u32(smem);
    const uint32_t mbq = sb, mb0 = sb + 8, mb1 = sb + 16;
    const uint32_t data = sb + 1024;

    const int tid = threadIdx.x;
    const int wid = tid >> 5, lane = tid & 31;
    const int b = blockIdx.z, h = blockIdx.y;
    const int q0 = blockIdx.x * 128;

    const int lr16 = lane & 15;
    const int lk8  = (lane >> 4) * 8;

    if (tid == 0) { mbar_init(mbq, 1); mbar_init(mb0, 1); mbar_init(mb1, 1); }
    __syncthreads();

    const size_t qblk  = (size_t)(b * HH + h) * 32 + (q0 >> 6);
    const size_t kvbase = (size_t)b * kb + (size_t)h * kh;

    auto issue_kv = [&](int s, int kt) {
        const uint32_t mb = s ? mb1 : mb0;
        mbar_expect(mb, 32768u);
        const uint32_t st = data + ASTG + s * 32768;
        bulk_g2s(st + AKHI, Khi + (kvbase + kt) * 4096, 8192, mb);
        bulk_g2s(st + AKLO, Klo + (kvbase + kt) * 4096, 8192, mb);
        bulk_g2s(st + AVHI, Vhi + (kvbase + kt) * 4096, 8192, mb);
        bulk_g2s(st + AVLO, Vlo + (kvbase + kt) * 4096, 8192, mb);
    };

    if (tid == 0) {
        mbar_expect(mbq, 32768u);
        bulk_g2s(data + AQHI, Qhi + qblk * 4096, 16384, mbq);
        bulk_g2s(data + AQLO, Qlo + qblk * 4096, 16384, mbq);
        issue_kv(0, 0);
    }

    mbar_wait(mbq, 0);
    const uint32_t qtile = (uint32_t)(wid >> 2) * 8192;
    uint32_t qh[4][4], ql[4][4];
    #pragma unroll
    for (int ks = 0; ks < 4; ks++) {
        int lrow = (wid * 16 + lr16) & 63;
        uint32_t off = qtile + sw64(lrow, ks * 16 + lk8) * 2;
        LDSM4(qh[ks][0], qh[ks][1], qh[ks][2], qh[ks][3], data + AQHI + off);
        LDSM4(ql[ks][0], ql[ks][1], ql[ks][2], ql[ks][3], data + AQLO + off);
    }

    float m0r = -1e30f, m1r = -1e30f, l0 = 0.f, l1 = 0.f;
    float oa[8][4];
    #pragma unroll
    for (int nt = 0; nt < 8; nt++)
        #pragma unroll
        for (int e = 0; e < 4; e++) oa[nt][e] = 0.f;

    const int gr = lane >> 2;
    const int gc2 = (lane & 3) * 2;
    const int qrow0 = q0 + wid * 16 + gr;
    const int qrow1 = qrow0 + 8;

    int ph0 = 0, ph1 = 0;
    for (int kt = 0; kt < ntiles; kt++) {
        const int s = kt & 1;
        if (kt + 1 < ntiles && tid == 0) issue_kv(s ^ 1, kt + 1);
        if (s == 0) { mbar_wait(mb0, ph0); ph0 ^= 1; }
        else        { mbar_wait(mb1, ph1); ph1 ^= 1; }

        const uint32_t base = data + ASTG + s * 32768;

        float sa[8][4];
        #pragma unroll
        for (int nt = 0; nt < 8; nt++)
            #pragma unroll
            for (int e = 0; e < 4; e++) sa[nt][e] = 0.f;

        #pragma unroll
        for (int p = 0; p < 4; p++) {
            #pragma unroll
            for (int ks = 0; ks < 4; ks++) {
                int row = p * 16 + lr16;
                uint32_t off = sw64(row, ks * 16 + lk8) * 2;
                uint32_t h0, h1, h2, h3, l0r, l1r, l2r, l3r;
                LDSM4(h0, h1, h2, h3, base + AKHI + off);
                LDSM4(l0r, l1r, l2r, l3r, base + AKLO + off);
                uint32_t bh0[2] = {h0, h2}, bh1[2] = {h1, h3};
                uint32_t bl0[2] = {l0r, l2r}, bl1[2] = {l1r, l3r};
                MMA16816(sa[2*p],   qh[ks], bh0);
                MMA16816(sa[2*p],   qh[ks], bl0);
                MMA16816(sa[2*p],   ql[ks], bh0);
                MMA16816(sa[2*p+1], qh[ks], bh1);
                MMA16816(sa[2*p+1], qh[ks], bl1);
                MMA16816(sa[2*p+1], ql[ks], bh1);
            }
        }

        #pragma unroll
        for (int nt = 0; nt < 8; nt++) {
            int col = kt * 64 + nt * 8 + gc2;
            #pragma unroll
            for (int e = 0; e < 4; e++) {
                float s2 = sa[nt][e] * 0.125f;
                if (banded) {
                    int r = (e < 2) ? qrow0 : qrow1;
                    int c = col + (e & 1);
                    int d = r - c;
                    if (d <= RR && d >= -RR) s2 += 1.0f;
                }
                sa[nt][e] = s2;
            }
        }

        float mx0 = -1e30f, mx1 = -1e30f;
        #pragma unroll
        for (int nt = 0; nt < 8; nt++) {
            mx0 = fmaxf(mx0, fmaxf(sa[nt][0], sa[nt][1]));
            mx1 = fmaxf(mx1, fmaxf(sa[nt][2], sa[nt][3]));
        }
        mx0 = fmaxf(mx0, __shfl_xor_sync(0xffffffffu, mx0, 1));
        mx0 = fmaxf(mx0, __shfl_xor_sync(0xffffffffu, mx0, 2));
        mx1 = fmaxf(mx1, __shfl_xor_sync(0xffffffffu, mx1, 1));
        mx1 = fmaxf(mx1, __shfl_xor_sync(0xffffffffu, mx1, 2));

        float nm0 = fmaxf(m0r, mx0), nm1 = fmaxf(m1r, mx1);
        float al0 = __expf(m0r - nm0), al1 = __expf(m1r - nm1);
        m0r = nm0; m1r = nm1;
        l0 *= al0; l1 *= al1;
        #pragma unroll
        for (int nt = 0; nt < 8; nt++) {
            oa[nt][0] *= al0; oa[nt][1] *= al0;
            oa[nt][2] *= al1; oa[nt][3] *= al1;
        }

        float ph_f[8][4], pl_f[8][4];
        #pragma unroll
        for (int nt = 0; nt < 8; nt++) {
            #pragma unroll
            for (int e = 0; e < 4; e++) {
                float p = __expf(sa[nt][e] - ((e < 2) ? nm0 : nm1));
                if (e < 2) l0 += p; else l1 += p;
                float hf = __bfloat162float(__float2bfloat16(p));
                ph_f[nt][e] = hf;
                pl_f[nt][e] = p - hf;
            }
        }

        uint32_t ph[4][4], pl[4][4];
        #pragma unroll
        for (int ks = 0; ks < 4; ks++) {
            int t0 = 2*ks, t1 = 2*ks + 1;
            ph[ks][0] = pack_bf16(ph_f[t0][0], ph_f[t0][1]);
            ph[ks][1] = pack_bf16(ph_f[t0][2], ph_f[t0][3]);
            ph[ks][2] = pack_bf16(ph_f[t1][0], ph_f[t1][1]);
            ph[ks][3] = pack_bf16(ph_f[t1][2], ph_f[t1][3]);
            pl[ks][0] = pack_bf16(pl_f[t0][0], pl_f[t0][1]);
            pl[ks][1] = pack_bf16(pl_f[t0][2], pl_f[t0][3]);
            pl[ks][2] = pack_bf16(pl_f[t1][0], pl_f[t1][1]);
            pl[ks][3] = pack_bf16(pl_f[t1][2], pl_f[t1][3]);
        }

        #pragma unroll
        for (int p = 0; p < 4; p++) {
            #pragma unroll
            for (int ks = 0; ks < 4; ks++) {
                int row = p * 16 + lr16;
                uint32_t off = sw64(row, ks * 16 + lk8) * 2;
                uint32_t h0, h1, h2, h3, v0, v1, v2, v3;
                LDSM4(h0, h1, h2, h3, base + AVHI + off);
                LDSM4(v0, v1, v2, v3, base + AVLO + off);
                uint32_t bh0[2] = {h0, h2}, bh1[2] = {h1, h3};
                uint32_t bl0[2] = {v0, v2}, bl1[2] = {v1, v3};
                MMA16816(oa[2*p],   ph[ks], bh0);
                MMA16816(oa[2*p],   pl[ks], bh0);
                MMA16816(oa[2*p],   ph[ks], bl0);
                MMA16816(oa[2*p+1], ph[ks], bh1);
                MMA16816(oa[2*p+1], pl[ks], bh1);
                MMA16816(oa[2*p+1], ph[ks], bl1);
            }
        }
        __syncthreads();
    }

    l0 += __shfl_xor_sync(0xffffffffu, l0, 1);
    l0 += __shfl_xor_sync(0xffffffffu, l0, 2);
    l1 += __shfl_xor_sync(0xffffffffu, l1, 1);
    l1 += __shfl_xor_sync(0xffffffffu, l1, 2);
    const float inv0 = 1.0f / l0, inv1 = 1.0f / l1;

    #pragma unroll
    for (int nt = 0; nt < 8; nt++) {
        int d = nt * 8 + gc2;
        int col = h * DHH + d;
        int R0 = b * SS + qrow0, R1 = b * SS + qrow1;
        size_t off0 = ((size_t)(R0 >> 6) * 24 + (col >> 5)) * 2048 + sw_elem(R0 & 63, col & 31);
        size_t off1 = ((size_t)(R1 >> 6) * 24 + (col >> 5)) * 2048 + sw_elem(R1 & 63, col & 31);
        float v0 = oa[nt][0] * inv0, v1 = oa[nt][1] * inv0;
        float v2 = oa[nt][2] * inv1, v3 = oa[nt][3] * inv1;
        bf16 h0 = __float2bfloat16(v0), h1 = __float2bfloat16(v1);
        bf16 h2 = __float2bfloat16(v2), h3 = __float2bfloat16(v3);
        *(__nv_bfloat162*)&Ohi[off0] = {h0, h1};
        *(__nv_bfloat162*)&Olo[off0] = {__float2bfloat16(v0 - __bfloat162float(h0)),
                                        __float2bfloat16(v1 - __bfloat162float(h1))};
        *(__nv_bfloat162*)&Ohi[off1] = {h2, h3};
        *(__nv_bfloat162*)&Olo[off1] = {__float2bfloat16(v2 - __bfloat162float(h2)),
                                        __float2bfloat16(v3 - __bfloat162float(h3))};
    }
}

// ---------------- layernorm (fp32 + optional packed split out) --------------
__global__ __launch_bounds__(256) void ln_kernel(
    const float* __restrict__ X, const float* __restrict__ g,
    const float* __restrict__ bta, float* __restrict__ Y,
    bf16* __restrict__ Yhi, bf16* __restrict__ Ylo)
{
    __shared__ float red[8];
    const int row = blockIdx.x, t = threadIdx.x;
    const float* x = X + (size_t)row * DD;

    float v0 = x[t], v1 = x[t + 256], v2 = x[t + 512];
    float s = v0 + v1 + v2;
    #pragma unroll
    for (int o = 16; o; o >>= 1) s += __shfl_xor_sync(0xffffffffu, s, o);
    if ((t & 31) == 0) red[t >> 5] = s;
    __syncthreads();
    float tot = 0.f;
    #pragma unroll
    for (int i = 0; i < 8; i++) tot += red[i];
    const float mean = tot * (1.0f / 768.0f);

    float d0 = v0 - mean, d1 = v1 - mean, d2 = v2 - mean;
    float s2 = d0*d0 + d1*d1 + d2*d2;
    __syncthreads();
    #pragma unroll
    for (int o = 16; o; o >>= 1) s2 += __shfl_xor_sync(0xffffffffu, s2, o);
    if ((t & 31) == 0) red[t >> 5] = s2;
    __syncthreads();
    float tot2 = 0.f;
    #pragma unroll
    for (int i = 0; i < 8; i++) tot2 += red[i];
    const float rstd = rsqrtf(tot2 * (1.0f / 768.0f) + 1e-12f);

    float* y = Y + (size_t)row * DD;
    #pragma unroll
    for (int c = 0; c < 3; c++) {
        int idx = t + 256 * c;
        float dv = (c == 0) ? d0 : (c == 1) ? d1 : d2;
        float r = dv * rstd * g[idx] + bta[idx];
        y[idx] = r;
        if (Yhi) {
            size_t off = ((size_t)(row >> 6) * 24 + (idx >> 5)) * 2048
                         + sw_elem(row & 63, idx & 31);
            bf16 hh = __float2bfloat16(r);
            Yhi[off] = hh;
            Ylo[off] = __float2bfloat16(r - __bfloat162float(hh));
        }
    }
}

// ---------------- launch ----------------------------------------------------
extern "C" void kernel_launch(void* const* d_in, const int* in_sizes, int n_in,
                              void* d_out, int out_size)
{
    const float* hidden  = (const float*)d_in[0];
    const float* tag_emb = (const float*)d_in[1];
    const float* sa_wq = (const float*)d_in[2],  *sa_bq = (const float*)d_in[3];
    const float* sa_wk = (const float*)d_in[4],  *sa_bk = (const float*)d_in[5];
    const float* sa_wv = (const float*)d_in[6],  *sa_bv = (const float*)d_in[7];
    const float* sa_wo = (const float*)d_in[8],  *sa_bo = (const float*)d_in[9];
    const float* sa_lg = (const float*)d_in[10], *sa_lb = (const float*)d_in[11];
    const float* ca_wq = (const float*)d_in[12], *ca_bq = (const float*)d_in[13];
    const float* ca_wk = (const float*)d_in[14], *ca_bk = (const float*)d_in[15];
    const float* ca_wv = (const float*)d_in[16], *ca_bv = (const float*)d_in[17];
    const float* ca_wo = (const float*)d_in[18], *ca_bo = (const float*)d_in[19];
    const float* ca_lg = (const float*)d_in[20], *ca_lb = (const float*)d_in[21];
    const float* ff_w1 = (const float*)d_in[22], *ff_b1 = (const float*)d_in[23];
    const float* ff_w2 = (const float*)d_in[24], *ff_b2 = (const float*)d_in[25];
    const float* ff_lg = (const float*)d_in[26], *ff_lb = (const float*)d_in[27];
    float* out = (float*)d_out;

    float *tmp, *x1, *x2, *bqkv;
    bf16 *whi, *wlo, *qhi, *qlo, *khi, *klo, *vthi, *vtlo, *ctxhi, *ctxlo;
    bf16 *x1hi, *x1lo, *x2hi, *x2lo, *hhi, *hlo, *ihi, *ilo;
    bf16 *ckhi, *cklo, *cvthi, *cvtlo;
    cudaGetSymbolAddress((void**)&tmp,  g_tmp);
    cudaGetSymbolAddress((void**)&x1,   g_x1);
    cudaGetSymbolAddress((void**)&x2,   g_x2);
    cudaGetSymbolAddress((void**)&bqkv, g_bqkv);
    cudaGetSymbolAddress((void**)&whi,  g_whi);
    cudaGetSymbolAddress((void**)&wlo,  g_wlo);
    cudaGetSymbolAddress((void**)&qhi,  g_qhi);
    cudaGetSymbolAddress((void**)&qlo,  g_qlo);
    cudaGetSymbolAddress((void**)&khi,  g_khi);
    cudaGetSymbolAddress((void**)&klo,  g_klo);
    cudaGetSymbolAddress((void**)&vthi, g_vthi);
    cudaGetSymbolAddress((void**)&vtlo, g_vtlo);
    cudaGetSymbolAddress((void**)&ctxhi, g_ctxhi);
    cudaGetSymbolAddress((void**)&ctxlo, g_ctxlo);
    cudaGetSymbolAddress((void**)&x1hi, g_x1hi);
    cudaGetSymbolAddress((void**)&x1lo, g_x1lo);
    cudaGetSymbolAddress((void**)&x2hi, g_x2hi);
    cudaGetSymbolAddress((void**)&x2lo, g_x2lo);
    cudaGetSymbolAddress((void**)&hhi,  g_hhi);
    cudaGetSymbolAddress((void**)&hlo,  g_hlo);
    cudaGetSymbolAddress((void**)&ihi,  g_ihi);
    cudaGetSymbolAddress((void**)&ilo,  g_ilo);
    cudaGetSymbolAddress((void**)&ckhi, g_ckhi);
    cudaGetSymbolAddress((void**)&cklo, g_cklo);
    cudaGetSymbolAddress((void**)&cvthi, g_cvthi);
    cudaGetSymbolAddress((void**)&cvtlo, g_cvtlo);

    cudaFuncSetAttribute(mma_gemm<0,3>, cudaFuncAttributeMaxDynamicSharedMemorySize, GEMM_SMEM);
    cudaFuncSetAttribute(mma_gemm<0,1>, cudaFuncAttributeMaxDynamicSharedMemorySize, GEMM_SMEM);
    cudaFuncSetAttribute(mma_gemm<1,0>, cudaFuncAttributeMaxDynamicSharedMemorySize, GEMM_SMEM);
    cudaFuncSetAttribute(mma_gemm<2,2>, cudaFuncAttributeMaxDynamicSharedMemorySize, GEMM_SMEM);
    cudaFuncSetAttribute(mha_kernel,    cudaFuncAttributeMaxDynamicSharedMemorySize, ATT_SMEM);
    cudaFuncSetAttribute(mma_gemm<0,3>, cudaFuncAttributePreferredSharedMemoryCarveout, 100);
    cudaFuncSetAttribute(mma_gemm<0,1>, cudaFuncAttributePreferredSharedMemoryCarveout, 100);
    cudaFuncSetAttribute(mma_gemm<1,0>, cudaFuncAttributePreferredSharedMemoryCarveout, 100);
    cudaFuncSetAttribute(mma_gemm<2,2>, cudaFuncAttributePreferredSharedMemoryCarveout, 100);
    cudaFuncSetAttribute(mha_kernel,    cudaFuncAttributePreferredSharedMemoryCarveout, 100);

    const size_t o_sawo = 3*(size_t)DxD, o_cawq = 4*(size_t)DxD, o_cawo = 5*(size_t)DxD;
    const size_t o_ff1  = 6*(size_t)DxD;
    const size_t o_ff2  = 6*(size_t)DxD + (size_t)768*3072;

    const dim3 wsB(32, 8);
    prep_kernel<<<dim3(96, 24, 9), wsB>>>(sa_wq, sa_wk, sa_wv, sa_wo, ca_wq, ca_wo,
                                          ff_w1, ff_w2, whi, wlo,
                                          hidden, hhi, hlo, sa_bq, sa_bk, sa_bv, bqkv);

    const dim3 thr(256);
    const dim3 gQKV(2304 / GBN, MROWS / GBM);   // (12, 64)
    const dim3 gMMA_D (DD / GBN, MROWS / GBM);  // (4, 64) -> 256 blocks, single wave
    const dim3 gMMA_F1(FF / GBN, MROWS / GBM);  // (16, 64)
    const dim3 gCK(DD / BN, TT / BM);
    const dim3 attn_grid(SS / 128, HH, BB);
    const size_t smb = GEMM_SMEM;

    // ---- self attention ----
    mma_gemm<0,3><<<gQKV, thr, smb>>>(hhi, hlo, whi, wlo, bqkv, nullptr,
                                      nullptr, qhi, qlo, khi, klo, vthi, vtlo, 2304, DD);
    mha_kernel<<<attn_grid, 256, ATT_SMEM>>>(qhi, qlo, khi, klo, vthi, vtlo, ctxhi, ctxlo,
                                             SS/64, HH*32, 32, 1);
    mma_gemm<1,0><<<gMMA_D, thr, smb>>>(ctxhi, ctxlo, whi+o_sawo, wlo+o_sawo, sa_bo, hidden,
                                        tmp, nullptr, nullptr, nullptr, nullptr, nullptr, nullptr, DD, DD);
    ln_kernel<<<MROWS, thr>>>(tmp, sa_lg, sa_lb, x1, x1hi, x1lo);

    // ---- cross attention ----
    mma_gemm<0,1><<<gMMA_D, thr, smb>>>(x1hi, x1lo, whi+o_cawq, wlo+o_cawq, ca_bq, nullptr,
                                        nullptr, qhi, qlo, nullptr, nullptr, nullptr, nullptr, DD, DD);
    tag_gemm<0><<<gCK, thr>>>(tag_emb, ca_wk, ca_bk, ckhi, cklo, TT, DD, DD);
    tag_gemm<1><<<gCK, thr>>>(tag_emb, ca_wv, ca_bv, cvthi, cvtlo, TT, DD, DD);
    mha_kernel<<<attn_grid, 256, ATT_SMEM>>>(qhi, qlo, ckhi, cklo, cvthi, cvtlo, ctxhi, ctxlo,
                                             1, 0, 1, 0);
    mma_gemm<1,0><<<gMMA_D, thr, smb>>>(ctxhi, ctxlo, whi+o_cawo, wlo+o_cawo, ca_bo, x1,
                                        tmp, nullptr, nullptr, nullptr, nullptr, nullptr, nullptr, DD, DD);
    ln_kernel<<<MROWS, thr>>>(tmp, ca_lg, ca_lb, x2, x2hi, x2lo);

    // ---- FFN ----
    mma_gemm<2,2><<<gMMA_F1, thr, smb>>>(x2hi, x2lo, whi+o_ff1, wlo+o_ff1, ff_b1, nullptr,
                                         nullptr, ihi, ilo, nullptr, nullptr, nullptr, nullptr, FF, DD);
    mma_gemm<1,0><<<gMMA_D, thr, smb>>>(ihi, ilo, whi+o_ff2, wlo+o_ff2, ff_b2, x2,
                                        tmp, nullptr, nullptr, nullptr, nullptr, nullptr, nullptr, DD, FF);
    ln_kernel<<<MROWS, thr>>>(tmp, ff_lg, ff_lb, out, nullptr, nullptr);
}